// round 1
// baseline (speedup 1.0000x reference)
#include <cuda_runtime.h>

#define NTOK 2048
#define HD   512
#define NH   8
#define DH   64
#define MB   4096      // compression blocks (16^3)
#define SBN  512       // selection blocks (8^3)
#define NWID 729       // shifted windows (9^3)

// ---------------- scratch (device globals; no allocations) ----------------
__device__ float g_q[NTOK*HD], g_kf[NTOK*HD], g_vf[NTOK*HD];
__device__ float g_kavg[MB*HD], g_vavg[MB*HD], g_ck[MB*HD], g_cv[MB*HD];
__device__ float g_S[(size_t)NH*NTOK*MB];     // scores, then exp(s-max) in place
__device__ float g_P8[(size_t)NTOK*MB];       // head-pooled probs per compact block
__device__ float g_invl[NH*NTOK];
__device__ float g_outc[NTOK*HD], g_outs[NTOK*HD], g_outw[NTOK*HD], g_fused[NTOK*HD];
__device__ float g_gate[NTOK*3];
__device__ int g_cnt[MB], g_boff[MB+1], g_bperm[NTOK], g_bid[NTOK];
__device__ int g_sbcnt[SBN], g_sboff[SBN+1], g_sbperm[NTOK], g_sbid[NTOK];
__device__ int g_wcnt[NWID], g_woff[NWID+1], g_wperm[NTOK], g_wid[NTOK];
__device__ int g_scount[SBN], g_soff[SBN+1], g_slist[MB], g_sidc[MB];
__device__ int g_vlist[MB], g_nvalid;
__device__ int g_pei[NTOK];
__device__ int g_top8[NTOK*8];

// ---------------- fast exp on the FMA pipe (rel err ~1e-7) ----------------
__device__ __forceinline__ float fexp(float x){
    x = fminf(fmaxf(x, -87.0f), 88.0f);
    float y = x * 1.4426950408889634f;
    float z = y + 12582912.0f;                 // round-to-nearest int via magic
    int   ki = __float_as_int(z) - 0x4B400000;
    float kf = z - 12582912.0f;
    float f  = y - kf;                         // f in [-0.5, 0.5], 2^f below
    float p  = 1.5403530393381609e-4f;
    p = fmaf(p, f, 1.3333558146428443e-3f);
    p = fmaf(p, f, 9.6181291076284772e-3f);
    p = fmaf(p, f, 5.5504108664821580e-2f);
    p = fmaf(p, f, 2.4022650695910071e-1f);
    p = fmaf(p, f, 6.9314718055994531e-1f);
    p = fmaf(p, f, 1.0f);
    return __int_as_float((ki + 127) << 23) * p;
}

// ---------------- setup kernels ----------------
__global__ void zero_k(){
    int i = blockIdx.x*256 + threadIdx.x;
    if (i < MB)   g_cnt[i]   = 0;
    if (i < SBN){ g_sbcnt[i] = 0; g_scount[i] = 0; }
    if (i < NWID) g_wcnt[i]  = 0;
}

__global__ void prep_k(const int* __restrict__ coords){
    int t = blockIdx.x*256 + threadIdx.x;
    if (t >= NTOK) return;
    int cf = coords[t];
    int x = cf >> 12, y = (cf >> 6) & 63, z = cf & 63;
    int bid = ((x>>2)<<8) | ((y>>2)<<4) | (z>>2);
    g_bid[t] = bid; atomicAdd(&g_cnt[bid], 1);
    int sb = ((x>>3)<<6) | ((y>>3)<<3) | (z>>3);
    g_sbid[t] = sb; atomicAdd(&g_sbcnt[sb], 1);
    int wd = (((x+4)>>3)*9 + ((y+4)>>3))*9 + ((z+4)>>3);
    g_wid[t] = wd; atomicAdd(&g_wcnt[wd], 1);
    g_pei[t] = (((x&3)*4 + (y&3))*4 + (z&3)) * HD;
}

__global__ void gate_k(const float* __restrict__ feats, const float* __restrict__ Wg){
    int n = blockIdx.x;
    int w = threadIdx.x >> 5, lane = threadIdx.x & 31;
    if (w >= 3) return;
    float s = 0.f;
    for (int i = lane; i < HD; i += 32) s += feats[n*HD + i] * Wg[i*3 + w];
    #pragma unroll
    for (int o = 16; o; o >>= 1) s += __shfl_xor_sync(0xffffffffu, s, o);
    if (lane == 0) g_gate[n*3 + w] = 1.0f / (1.0f + fexp(-s));
}

// warp-chunked exclusive scans + deterministic valid-block compaction
__device__ __forceinline__ void warp_exscan(const int* cnt, int* off, int len){
    int lane = threadIdx.x & 31;
    int run = 0;
    for (int base = 0; base < len; base += 32){
        int raw = (base+lane < len) ? cnt[base+lane] : 0;
        int v = raw;
        #pragma unroll
        for (int o = 1; o < 32; o <<= 1){ int t = __shfl_up_sync(0xffffffffu, v, o); if (lane >= o) v += t; }
        if (base+lane < len) off[base+lane] = run + v - raw;
        run += __shfl_sync(0xffffffffu, v, 31);
    }
    if (lane == 0) off[len] = run;
}

__global__ void scan1_k(){
    int w = threadIdx.x >> 5;
    if (w == 0) warp_exscan(g_cnt,   g_boff,  MB);
    else if (w == 1) warp_exscan(g_sbcnt, g_sboff, SBN);
    else if (w == 2) warp_exscan(g_wcnt,  g_woff,  NWID);
    else { // compact valid blocks (deterministic order)
        int lane = threadIdx.x & 31;
        int run = 0;
        for (int base = 0; base < MB; base += 32){
            int valid = g_cnt[base+lane] > 0 ? 1 : 0;
            int v = valid;
            #pragma unroll
            for (int o = 1; o < 32; o <<= 1){ int t = __shfl_up_sync(0xffffffffu, v, o); if (lane >= o) v += t; }
            if (valid) g_vlist[run + v - 1] = base + lane;
            run += __shfl_sync(0xffffffffu, v, 31);
        }
        if (lane == 0) g_nvalid = run;
    }
}

__global__ void scan2_k(){ warp_exscan(g_scount, g_soff, SBN); }

// deterministic rank-based bucket fills
__global__ void permfill_k(){
    int t = blockIdx.x*256 + threadIdx.x;
    if (t >= NTOK) return;
    int sb = g_sbid[t], wd = g_wid[t], bd = g_bid[t];
    int r1 = 0, r2 = 0, r3 = 0;
    for (int u = 0; u < t; u++){
        r1 += (g_sbid[u] == sb);
        r2 += (g_wid[u]  == wd);
        r3 += (g_bid[u]  == bd);
    }
    g_sbperm[g_sboff[sb] + r1] = t;
    g_wperm [g_woff[wd]  + r2] = t;
    g_bperm [g_boff[bd]  + r3] = t;
}

__global__ void slist_k(){
    int j = blockIdx.x*256 + threadIdx.x;
    if (j >= g_nvalid) return;
    int s = g_sidc[j];
    int r = 0;
    for (int u = 0; u < j; u++) r += (g_sidc[u] == s);
    g_slist[g_soff[s] + r] = j;
}

// per-compact-block averaging (ordered sums, no float atomics) + sid counts
__global__ void avg_k(const float* __restrict__ pe){
    int j = blockIdx.x;
    int nv = g_nvalid;
    if (j >= nv){
        for (int c = threadIdx.x; c < HD; c += 256){
            g_kavg[j*HD + c] = 0.f; g_vavg[j*HD + c] = 0.f;
        }
        return;
    }
    int m = g_vlist[j];
    int c0 = g_boff[m], c1 = g_boff[m+1];
    float dn = 1.0f / (float)max(c1 - c0, 1);
    for (int c = threadIdx.x; c < HD; c += 256){
        float sk = 0.f, sv = 0.f;
        for (int i = c0; i < c1; i++){
            int t = g_bperm[i];
            sk += g_kf[t*HD + c] + pe[g_pei[t] + c];
            sv += g_vf[t*HD + c];
        }
        g_kavg[j*HD + c] = sk * dn;
        g_vavg[j*HD + c] = sv * dn;
    }
    if (threadIdx.x == 0){
        int mx = m >> 8, my = (m >> 4) & 15, mz = m & 15;
        int sid = ((mx>>1)<<6) | ((my>>1)<<3) | (mz>>1);
        g_sidc[j] = sid;
        atomicAdd(&g_scount[sid], 1);
    }
}

// ---------------- generic fp32 SGEMM: C[M,N] = A[M,K] x B[K,N] ----------------
__global__ __launch_bounds__(256) void sgemm_k(
    const float* __restrict__ A, const float* __restrict__ B, float* __restrict__ C,
    int K, int Nc, int guard)
{
    int tbm = blockIdx.y*64, tbn = blockIdx.x*64;
    if (guard && tbm >= g_nvalid) return;
    __shared__ float As[16][68];
    __shared__ float Bs[16][68];
    int tid = threadIdx.x, ty = tid >> 4, tx = tid & 15;
    float acc[4][4] = {};
    for (int k0 = 0; k0 < K; k0 += 16){
        {
            int r = tid >> 2, c4 = tid & 3;
            float4 a = *(const float4*)&A[(tbm+r)*K + k0 + c4*4];
            As[c4*4+0][r] = a.x; As[c4*4+1][r] = a.y; As[c4*4+2][r] = a.z; As[c4*4+3][r] = a.w;
            int rb = tid >> 4, cb = tid & 15;
            *(float4*)&Bs[rb][cb*4] = *(const float4*)&B[(k0+rb)*Nc + tbn + cb*4];
        }
        __syncthreads();
        #pragma unroll
        for (int k = 0; k < 16; k++){
            float4 av = *(const float4*)&As[k][ty*4];
            float4 bv = *(const float4*)&Bs[k][tx*4];
            float a[4] = {av.x, av.y, av.z, av.w};
            float b[4] = {bv.x, bv.y, bv.z, bv.w};
            #pragma unroll
            for (int i = 0; i < 4; i++)
                #pragma unroll
                for (int j = 0; j < 4; j++)
                    acc[i][j] = fmaf(a[i], b[j], acc[i][j]);
        }
        __syncthreads();
    }
    #pragma unroll
    for (int i = 0; i < 4; i++){
        float4 o = {acc[i][0], acc[i][1], acc[i][2], acc[i][3]};
        *(float4*)&C[(tbm+ty*4+i)*Nc + tbn + tx*4] = o;
    }
}

// ---------------- compressed attention: QK^T scores ----------------
__global__ __launch_bounds__(256) void qk_k(){
    int h = blockIdx.z, nt = blockIdx.y*64, jt = blockIdx.x*64;
    if (jt >= g_nvalid) return;
    __shared__ float Qs[64][68];
    __shared__ float Ks[64][68];
    int tid = threadIdx.x;
    #pragma unroll
    for (int i = 0; i < 4; i++){
        int id = tid + 256*i;
        int r = id >> 4, c4 = id & 15;
        float4 a = *(const float4*)&g_q [(nt+r)*HD + h*DH + c4*4];
        Qs[c4*4+0][r] = a.x; Qs[c4*4+1][r] = a.y; Qs[c4*4+2][r] = a.z; Qs[c4*4+3][r] = a.w;
        float4 b = *(const float4*)&g_ck[(jt+r)*HD + h*DH + c4*4];
        Ks[c4*4+0][r] = b.x; Ks[c4*4+1][r] = b.y; Ks[c4*4+2][r] = b.z; Ks[c4*4+3][r] = b.w;
    }
    __syncthreads();
    int ty = tid >> 4, tx = tid & 15;
    float acc[4][4] = {};
    #pragma unroll
    for (int d = 0; d < 64; d++){
        float4 av = *(const float4*)&Qs[d][ty*4];
        float4 bv = *(const float4*)&Ks[d][tx*4];
        float a[4] = {av.x, av.y, av.z, av.w};
        float b[4] = {bv.x, bv.y, bv.z, bv.w};
        #pragma unroll
        for (int i = 0; i < 4; i++)
            #pragma unroll
            for (int j = 0; j < 4; j++)
                acc[i][j] = fmaf(a[i], b[j], acc[i][j]);
    }
    #pragma unroll
    for (int i = 0; i < 4; i++){
        float4 o = {acc[i][0]*0.125f, acc[i][1]*0.125f, acc[i][2]*0.125f, acc[i][3]*0.125f};
        *(float4*)&g_S[((size_t)(h*NTOK + nt + ty*4 + i))*MB + jt + tx*4] = o;
    }
}

// ---------------- per-row softmax: write exp(s-max) in place, store 1/sum ----------------
__global__ void smrow_k(){
    int n = blockIdx.x, h = blockIdx.y, tid = threadIdx.x;
    int nv = g_nvalid;
    float* row = g_S + ((size_t)(h*NTOK + n))*MB;
    float m = -1e30f;
    for (int j = tid; j < nv; j += 256) m = fmaxf(m, row[j]);
    __shared__ float sm[8], sl[8], bcast[2];
    #pragma unroll
    for (int o = 16; o; o >>= 1) m = fmaxf(m, __shfl_xor_sync(0xffffffffu, m, o));
    if ((tid & 31) == 0) sm[tid >> 5] = m;
    __syncthreads();
    if (tid < 32){
        float v = (tid < 8) ? sm[tid] : -1e30f;
        #pragma unroll
        for (int o = 4; o; o >>= 1) v = fmaxf(v, __shfl_xor_sync(0xffffffffu, v, o));
        if (tid == 0) bcast[0] = v;
    }
    __syncthreads();
    float bm = bcast[0];
    float l = 0.f;
    for (int j = tid; j < nv; j += 256){
        float e = fexp(row[j] - bm);
        row[j] = e;
        l += e;
    }
    #pragma unroll
    for (int o = 16; o; o >>= 1) l += __shfl_xor_sync(0xffffffffu, l, o);
    if ((tid & 31) == 0) sl[tid >> 5] = l;
    __syncthreads();
    if (tid < 32){
        float v = (tid < 8) ? sl[tid] : 0.f;
        #pragma unroll
        for (int o = 4; o; o >>= 1) v += __shfl_xor_sync(0xffffffffu, v, o);
        if (tid == 0) g_invl[h*NTOK + n] = 1.0f / v;
    }
}

// ---------------- compressed attention: P @ V ----------------
__global__ __launch_bounds__(256) void pv_k(){
    int h = blockIdx.y, nt = blockIdx.x*64;
    int nv = g_nvalid;
    __shared__ float Ps[64][68];   // [j][n]
    __shared__ float Vs[64][68];   // [j][d]
    int tid = threadIdx.x, ty = tid >> 4, tx = tid & 15;
    float acc[4][4] = {};
    for (int jt = 0; jt < nv; jt += 64){
        #pragma unroll
        for (int i = 0; i < 4; i++){
            int id = tid + 256*i;
            int r = id >> 4, c4 = id & 15;
            float4 s = *(const float4*)&g_S[((size_t)(h*NTOK + nt + r))*MB + jt + c4*4];
            float il = g_invl[h*NTOK + nt + r];
            int j0 = jt + c4*4;
            Ps[c4*4+0][r] = (j0+0 < nv) ? s.x*il : 0.f;
            Ps[c4*4+1][r] = (j0+1 < nv) ? s.y*il : 0.f;
            Ps[c4*4+2][r] = (j0+2 < nv) ? s.z*il : 0.f;
            Ps[c4*4+3][r] = (j0+3 < nv) ? s.w*il : 0.f;
            float4 v = {0.f,0.f,0.f,0.f};
            if (jt + r < nv) v = *(const float4*)&g_cv[(jt+r)*HD + h*DH + c4*4];
            *(float4*)&Vs[r][c4*4] = v;
        }
        __syncthreads();
        #pragma unroll
        for (int j = 0; j < 64; j++){
            float4 av = *(const float4*)&Ps[j][ty*4];
            float4 bv = *(const float4*)&Vs[j][tx*4];
            float a[4] = {av.x, av.y, av.z, av.w};
            float b[4] = {bv.x, bv.y, bv.z, bv.w};
            #pragma unroll
            for (int i = 0; i < 4; i++)
                #pragma unroll
                for (int jj = 0; jj < 4; jj++)
                    acc[i][jj] = fmaf(a[i], b[jj], acc[i][jj]);
        }
        __syncthreads();
    }
    #pragma unroll
    for (int i = 0; i < 4; i++){
        float4 o = {acc[i][0], acc[i][1], acc[i][2], acc[i][3]};
        *(float4*)&g_outc[(nt+ty*4+i)*HD + h*DH + tx*4] = o;
    }
}

// ---------------- head-pooled probs per compact block ----------------
__global__ void p8_k(){
    int n = blockIdx.x;
    int nv = g_nvalid;
    float il[NH];
    #pragma unroll
    for (int h = 0; h < NH; h++) il[h] = g_invl[h*NTOK + n];
    for (int j = threadIdx.x; j < nv; j += 256){
        float p = 0.f;
        #pragma unroll
        for (int h = 0; h < NH; h++)
            p += g_S[((size_t)(h*NTOK + n))*MB + j] * il[h];
        g_P8[(size_t)n*MB + j] = p;
    }
}

// ---------------- sel_score (deterministic via sid CSR) + top-8 ----------------
__global__ void topk_k(){
    int n = blockIdx.x, tid = threadIdx.x;   // 512 threads
    __shared__ float ss[SBN];
    __shared__ float rv[SBN];
    __shared__ int   ri[SBN];
    float v = 0.f;
    int o0 = g_soff[tid], o1 = g_soff[tid+1];
    for (int i = o0; i < o1; i++) v += g_P8[(size_t)n*MB + g_slist[i]];
    ss[tid] = v;
    __syncthreads();
    for (int r = 0; r < 8; r++){
        rv[tid] = ss[tid]; ri[tid] = tid;
        __syncthreads();
        for (int st = 256; st > 0; st >>= 1){
            if (tid < st){
                float v2 = rv[tid+st]; int i2 = ri[tid+st];
                if (v2 > rv[tid] || (v2 == rv[tid] && i2 < ri[tid])){ rv[tid] = v2; ri[tid] = i2; }
            }
            __syncthreads();
        }
        if (tid == 0){ g_top8[n*8 + r] = ri[0]; ss[ri[0]] = -1e30f; }
        __syncthreads();
    }
}

// ---------------- selection / window attention (bucketed, online softmax) ----------------
__global__ void spattn_k(int mode){
    int n = blockIdx.x;
    int h = threadIdx.x >> 5, lane = threadIdx.x & 31;
    const float* qr = &g_q[n*HD + h*DH];
    float q0 = qr[lane], q1 = qr[lane + 32];
    float m = -1e30f, l = 0.f, a0 = 0.f, a1 = 0.f;
    int nb = (mode == 0) ? 8 : 1;
    for (int kk = 0; kk < nb; kk++){
        int b, o, e;
        if (mode == 0){ b = g_top8[n*8 + kk]; o = g_sboff[b]; e = g_sboff[b+1]; }
        else          { b = g_wid[n];         o = g_woff[b];  e = g_woff[b+1]; }
        for (int i = o; i < e; i++){
            int t = (mode == 0) ? g_sbperm[i] : g_wperm[i];
            const float* kr = &g_kf[t*HD + h*DH];
            float s = q0*kr[lane] + q1*kr[lane + 32];
            #pragma unroll
            for (int of = 16; of; of >>= 1) s += __shfl_xor_sync(0xffffffffu, s, of);
            s *= 0.125f;
            float mn = fmaxf(m, s);
            float c = fexp(m - mn), w = fexp(s - mn);
            const float* vr = &g_vf[t*HD + h*DH];
            l  = l*c  + w;
            a0 = a0*c + w*vr[lane];
            a1 = a1*c + w*vr[lane + 32];
            m = mn;
        }
    }
    float* outp = mode ? g_outw : g_outs;
    outp[n*HD + h*DH + lane]      = a0 / l;
    outp[n*HD + h*DH + lane + 32] = a1 / l;
}

// ---------------- gated fuse ----------------
__global__ void fuse_k(){
    int i = blockIdx.x*256 + threadIdx.x;
    int n = i >> 9;
    float g0 = g_gate[n*3+0], g1 = g_gate[n*3+1], g2 = g_gate[n*3+2];
    g_fused[i] = g0*g_outc[i] + g1*g_outs[i] + g2*g_outw[i];
}

// ---------------- launch ----------------
extern "C" void kernel_launch(void* const* d_in, const int* in_sizes, int n_in,
                              void* d_out, int out_size){
    const float* feats  = (const float*)d_in[0];
    const int*   coords = (const int*)  d_in[1];
    const float* Wq  = (const float*)d_in[2];
    const float* Wk  = (const float*)d_in[3];
    const float* Wv  = (const float*)d_in[4];
    const float* Wo  = (const float*)d_in[5];
    const float* Wck = (const float*)d_in[6];
    const float* Wcv = (const float*)d_in[7];
    const float* pe  = (const float*)d_in[8];
    const float* Wg  = (const float*)d_in[9];
    float* out = (float*)d_out;

    float *gq, *gkf, *gvf, *gkavg, *gvavg, *gck, *gcv, *gfused;
    cudaGetSymbolAddress((void**)&gq,    g_q);
    cudaGetSymbolAddress((void**)&gkf,   g_kf);
    cudaGetSymbolAddress((void**)&gvf,   g_vf);
    cudaGetSymbolAddress((void**)&gkavg, g_kavg);
    cudaGetSymbolAddress((void**)&gvavg, g_vavg);
    cudaGetSymbolAddress((void**)&gck,   g_ck);
    cudaGetSymbolAddress((void**)&gcv,   g_cv);
    cudaGetSymbolAddress((void**)&gfused,g_fused);

    zero_k<<<16, 256>>>();
    prep_k<<<8, 256>>>(coords);
    gate_k<<<NTOK, 128>>>(feats, Wg);

    dim3 gproj(HD/64, NTOK/64);
    sgemm_k<<<gproj, 256>>>(feats, Wq, gq,  HD, HD, 0);
    sgemm_k<<<gproj, 256>>>(feats, Wk, gkf, HD, HD, 0);
    sgemm_k<<<gproj, 256>>>(feats, Wv, gvf, HD, HD, 0);

    scan1_k<<<1, 128>>>();
    permfill_k<<<8, 256>>>();
    avg_k<<<MB, 256>>>(pe);

    dim3 gcomp(HD/64, MB/64);
    sgemm_k<<<gcomp, 256>>>(gkavg, Wck, gck, HD, HD, 1);
    sgemm_k<<<gcomp, 256>>>(gvavg, Wcv, gcv, HD, HD, 1);

    scan2_k<<<1, 32>>>();
    slist_k<<<16, 256>>>();

    qk_k<<<dim3(MB/64, NTOK/64, NH), 256>>>();
    smrow_k<<<dim3(NTOK, NH), 256>>>();
    pv_k<<<dim3(NTOK/64, NH), 256>>>();
    p8_k<<<NTOK, 256>>>();
    topk_k<<<NTOK, 512>>>();

    spattn_k<<<NTOK, 256>>>(0);
    spattn_k<<<NTOK, 256>>>(1);

    fuse_k<<<NTOK*HD/256, 256>>>();
    sgemm_k<<<gproj, 256>>>(gfused, Wo, out, HD, HD, 0);
}

// round 2
// speedup vs baseline: 1.2679x; 1.2679x over previous
#include <cuda_runtime.h>

#define NTOK 2048
#define HD   512
#define NH   8
#define DH   64
#define MB   4096      // compression blocks (16^3)
#define SBN  512       // selection blocks (8^3)
#define NWID 729       // shifted windows (9^3)

// ---------------- scratch (device globals; no allocations) ----------------
__device__ float g_q[NTOK*HD], g_kf[NTOK*HD], g_vf[NTOK*HD];
__device__ float g_kavg[MB*HD], g_vavg[MB*HD], g_ck[MB*HD], g_cv[MB*HD];
__device__ float g_S[(size_t)NH*NTOK*MB];     // scores, then exp(s-max) in place
__device__ float g_P8[(size_t)NTOK*MB];       // head-pooled probs per compact block
__device__ float g_invl[NH*NTOK];
__device__ unsigned g_rowmaxk[NH*NTOK];       // encoded row max (ordered-uint)
__device__ float g_outc[NTOK*HD], g_outs[NTOK*HD], g_outw[NTOK*HD], g_fused[NTOK*HD];
__device__ float g_gate[NTOK*3];
__device__ int g_cnt[MB], g_boff[MB+1], g_bperm[NTOK], g_bid[NTOK];
__device__ int g_sbcnt[SBN], g_sboff[SBN+1], g_sbperm[NTOK], g_sbid[NTOK];
__device__ int g_wcnt[NWID], g_woff[NWID+1], g_wperm[NTOK], g_wid[NTOK];
__device__ int g_scount[SBN], g_soff[SBN+1], g_slist[MB], g_sidc[MB];
__device__ int g_vlist[MB], g_nvalid;
__device__ int g_pei[NTOK];
__device__ int g_packed[NTOK];
__device__ int g_top8[NTOK*8];

// ---------------- packed fp32x2 FMA (FFMA2) ----------------
__device__ __forceinline__ void ffma2(float2& d, float2 a, float2 b){
    asm("fma.rn.f32x2 %0, %1, %2, %0;"
        : "+l"(reinterpret_cast<unsigned long long&>(d))
        : "l"(reinterpret_cast<unsigned long long&>(a)),
          "l"(reinterpret_cast<unsigned long long&>(b)));
}

// ---------------- fast exp on the FMA pipe (rel err ~1e-7) ----------------
__device__ __forceinline__ float fexp(float x){
    x = fminf(fmaxf(x, -87.0f), 88.0f);
    float y = x * 1.4426950408889634f;
    float z = y + 12582912.0f;
    int   ki = __float_as_int(z) - 0x4B400000;
    float kf = z - 12582912.0f;
    float f  = y - kf;
    float p  = 1.5403530393381609e-4f;
    p = fmaf(p, f, 1.3333558146428443e-3f);
    p = fmaf(p, f, 9.6181291076284772e-3f);
    p = fmaf(p, f, 5.5504108664821580e-2f);
    p = fmaf(p, f, 2.4022650695910071e-1f);
    p = fmaf(p, f, 6.9314718055994531e-1f);
    p = fmaf(p, f, 1.0f);
    return __int_as_float((ki + 127) << 23) * p;
}

// ordered-uint encode/decode for float atomicMax
__device__ __forceinline__ unsigned fenc(float f){
    unsigned u = __float_as_uint(f);
    return (u & 0x80000000u) ? ~u : (u | 0x80000000u);
}
__device__ __forceinline__ float fdec(unsigned k){
    return (k & 0x80000000u) ? __uint_as_float(k ^ 0x80000000u) : __uint_as_float(~k);
}

// ---------------- setup kernels ----------------
__global__ void zero_k(){
    int i = blockIdx.x*256 + threadIdx.x;
    if (i < MB)   g_cnt[i]   = 0;
    if (i < SBN){ g_sbcnt[i] = 0; g_scount[i] = 0; }
    if (i < NWID) g_wcnt[i]  = 0;
    if (i < NH*NTOK) g_rowmaxk[i] = 0u;
}

__global__ void prep_k(const int* __restrict__ coords){
    int t = blockIdx.x*256 + threadIdx.x;
    if (t >= NTOK) return;
    int cf = coords[t];
    int x = cf >> 12, y = (cf >> 6) & 63, z = cf & 63;
    int bid = ((x>>2)<<8) | ((y>>2)<<4) | (z>>2);
    g_bid[t] = bid; atomicAdd(&g_cnt[bid], 1);
    int sb = ((x>>3)<<6) | ((y>>3)<<3) | (z>>3);
    g_sbid[t] = sb; atomicAdd(&g_sbcnt[sb], 1);
    int wd = (((x+4)>>3)*9 + ((y+4)>>3))*9 + ((z+4)>>3);
    g_wid[t] = wd; atomicAdd(&g_wcnt[wd], 1);
    g_pei[t] = (((x&3)*4 + (y&3))*4 + (z&3)) * HD;
    g_packed[t] = bid | (sb << 12) | (wd << 21);
}

__global__ void gate_k(const float* __restrict__ feats, const float* __restrict__ Wg){
    int n = blockIdx.x;
    int w = threadIdx.x >> 5, lane = threadIdx.x & 31;
    if (w >= 3) return;
    float s = 0.f;
    for (int i = lane; i < HD; i += 32) s += feats[n*HD + i] * Wg[i*3 + w];
    #pragma unroll
    for (int o = 16; o; o >>= 1) s += __shfl_xor_sync(0xffffffffu, s, o);
    if (lane == 0) g_gate[n*3 + w] = 1.0f / (1.0f + fexp(-s));
}

// warp-chunked exclusive scans + deterministic valid-block compaction
__device__ __forceinline__ void warp_exscan(const int* cnt, int* off, int len){
    int lane = threadIdx.x & 31;
    int run = 0;
    for (int base = 0; base < len; base += 32){
        int raw = (base+lane < len) ? cnt[base+lane] : 0;
        int v = raw;
        #pragma unroll
        for (int o = 1; o < 32; o <<= 1){ int t = __shfl_up_sync(0xffffffffu, v, o); if (lane >= o) v += t; }
        if (base+lane < len) off[base+lane] = run + v - raw;
        run += __shfl_sync(0xffffffffu, v, 31);
    }
    if (lane == 0) off[len] = run;
}

__global__ void scan1_k(){
    int w = threadIdx.x >> 5;
    if (w == 0) warp_exscan(g_cnt,   g_boff,  MB);
    else if (w == 1) warp_exscan(g_sbcnt, g_sboff, SBN);
    else if (w == 2) warp_exscan(g_wcnt,  g_woff,  NWID);
    else {
        int lane = threadIdx.x & 31;
        int run = 0;
        for (int base = 0; base < MB; base += 32){
            int valid = g_cnt[base+lane] > 0 ? 1 : 0;
            int v = valid;
            #pragma unroll
            for (int o = 1; o < 32; o <<= 1){ int t = __shfl_up_sync(0xffffffffu, v, o); if (lane >= o) v += t; }
            if (valid) g_vlist[run + v - 1] = base + lane;
            run += __shfl_sync(0xffffffffu, v, 31);
        }
        if (lane == 0) g_nvalid = run;
    }
}

__global__ void scan2_k(){ warp_exscan(g_scount, g_soff, SBN); }

// deterministic rank-based bucket fills (packed ids, smem-chunked scan)
__global__ void permfill_k(){
    __shared__ int sp[256];
    int t = blockIdx.x*256 + threadIdx.x;
    int my = g_packed[t];
    int r1 = 0, r2 = 0, r3 = 0;
    for (int base = 0; base < NTOK; base += 256){
        sp[threadIdx.x] = g_packed[base + threadIdx.x];
        __syncthreads();
        int lim = t - base; if (lim > 256) lim = 256;
        for (int u = 0; u < lim; u++){
            int p = sp[u] ^ my;
            r3 += ((p & 0x00000FFF) == 0);
            r1 += ((p & 0x001FF000) == 0);
            r2 += ((p & 0x7FE00000) == 0);
        }
        __syncthreads();
    }
    int bd = my & 0xFFF, sb = (my >> 12) & 0x1FF, wd = (my >> 21) & 0x3FF;
    g_sbperm[g_sboff[sb] + r1] = t;
    g_wperm [g_woff[wd]  + r2] = t;
    g_bperm [g_boff[bd]  + r3] = t;
}

__global__ void slist_k(){
    int j = blockIdx.x*256 + threadIdx.x;
    if (j >= g_nvalid) return;
    int s = g_sidc[j];
    int r = 0;
    for (int u = 0; u < j; u++) r += (g_sidc[u] == s);
    g_slist[g_soff[s] + r] = j;
}

// per-compact-block averaging (ordered sums) + sid counts
__global__ void avg_k(const float* __restrict__ pe){
    int j = blockIdx.x;
    int nv = g_nvalid;
    if (j >= nv){
        for (int c = threadIdx.x; c < HD; c += 256){
            g_kavg[j*HD + c] = 0.f; g_vavg[j*HD + c] = 0.f;
        }
        return;
    }
    int m = g_vlist[j];
    int c0 = g_boff[m], c1 = g_boff[m+1];
    float dn = 1.0f / (float)max(c1 - c0, 1);
    for (int c = threadIdx.x; c < HD; c += 256){
        float sk = 0.f, sv = 0.f;
        for (int i = c0; i < c1; i++){
            int t = g_bperm[i];
            sk += g_kf[t*HD + c] + pe[g_pei[t] + c];
            sv += g_vf[t*HD + c];
        }
        g_kavg[j*HD + c] = sk * dn;
        g_vavg[j*HD + c] = sv * dn;
    }
    if (threadIdx.x == 0){
        int mx = m >> 8, my = (m >> 4) & 15, mz = m & 15;
        int sid = ((mx>>1)<<6) | ((my>>1)<<3) | (mz>>1);
        g_sidc[j] = sid;
        atomicAdd(&g_scount[sid], 1);
    }
}

// ---------------- 128x128 GEMM, 256 thr, 8x8/thread, FFMA2: QKV projection ----------------
__global__ __launch_bounds__(256) void proj_k(
    const float* __restrict__ A,
    const float* __restrict__ B0, const float* __restrict__ B1, const float* __restrict__ B2,
    float* __restrict__ C0, float* __restrict__ C1, float* __restrict__ C2)
{
    const float* B = blockIdx.z == 0 ? B0 : (blockIdx.z == 1 ? B1 : B2);
    float*       C = blockIdx.z == 0 ? C0 : (blockIdx.z == 1 ? C1 : C2);
    int tbm = blockIdx.y*128, tbn = blockIdx.x*128;
    __shared__ float As[16][132];
    __shared__ float Bs[16][132];
    int tid = threadIdx.x, ty = tid >> 4, tx = tid & 15;
    float2 acc[8][4];
    #pragma unroll
    for (int i = 0; i < 8; i++)
        #pragma unroll
        for (int j = 0; j < 4; j++) acc[i][j] = make_float2(0.f, 0.f);

    for (int k0 = 0; k0 < HD; k0 += 16){
        #pragma unroll
        for (int q = 0; q < 2; q++){
            int f = tid + 256*q, r = f >> 2, c4 = f & 3;
            float4 a = *(const float4*)&A[(tbm+r)*HD + k0 + c4*4];
            As[c4*4+0][r] = a.x; As[c4*4+1][r] = a.y; As[c4*4+2][r] = a.z; As[c4*4+3][r] = a.w;
            int rb = f >> 5, cb = f & 31;
            *(float4*)&Bs[rb][cb*4] = *(const float4*)&B[(k0+rb)*HD + tbn + cb*4];
        }
        __syncthreads();
        #pragma unroll
        for (int k = 0; k < 16; k++){
            float4 a0 = *(const float4*)&As[k][ty*8];
            float4 a1 = *(const float4*)&As[k][ty*8+4];
            float4 b0 = *(const float4*)&Bs[k][tx*4];
            float4 b1 = *(const float4*)&Bs[k][64 + tx*4];
            float2 bb[4] = {{b0.x,b0.y},{b0.z,b0.w},{b1.x,b1.y},{b1.z,b1.w}};
            float av[8] = {a0.x,a0.y,a0.z,a0.w,a1.x,a1.y,a1.z,a1.w};
            #pragma unroll
            for (int i = 0; i < 8; i++){
                float2 ap = make_float2(av[i], av[i]);
                ffma2(acc[i][0], ap, bb[0]);
                ffma2(acc[i][1], ap, bb[1]);
                ffma2(acc[i][2], ap, bb[2]);
                ffma2(acc[i][3], ap, bb[3]);
            }
        }
        __syncthreads();
    }
    #pragma unroll
    for (int i = 0; i < 8; i++){
        int row = tbm + ty*8 + i;
        *(float4*)&C[row*HD + tbn + tx*4]      = make_float4(acc[i][0].x, acc[i][0].y, acc[i][1].x, acc[i][1].y);
        *(float4*)&C[row*HD + tbn + 64 + tx*4] = make_float4(acc[i][2].x, acc[i][2].y, acc[i][3].x, acc[i][3].y);
    }
}

// ---------------- 128x64 GEMM (N=512 matrices), 128 thr, 8x8/thread ----------------
__global__ __launch_bounds__(128) void gemm64_k(
    const float* __restrict__ A0, const float* __restrict__ A1,
    const float* __restrict__ B0, const float* __restrict__ B1,
    float* __restrict__ C0, float* __restrict__ C1, int guard)
{
    const float* A = blockIdx.z ? A1 : A0;
    const float* B = blockIdx.z ? B1 : B0;
    float*       C = blockIdx.z ? C1 : C0;
    int tbm = blockIdx.y*128, tbn = blockIdx.x*64;
    if (guard && tbm >= g_nvalid) return;
    __shared__ float As[16][132];
    __shared__ float Bs[16][68];
    int tid = threadIdx.x, ty = tid >> 3, tx = tid & 7;
    float2 acc[8][4];
    #pragma unroll
    for (int i = 0; i < 8; i++)
        #pragma unroll
        for (int j = 0; j < 4; j++) acc[i][j] = make_float2(0.f, 0.f);

    for (int k0 = 0; k0 < HD; k0 += 16){
        #pragma unroll
        for (int q = 0; q < 4; q++){
            int f = tid + 128*q, r = f >> 2, c4 = f & 3;
            float4 a = *(const float4*)&A[(tbm+r)*HD + k0 + c4*4];
            As[c4*4+0][r] = a.x; As[c4*4+1][r] = a.y; As[c4*4+2][r] = a.z; As[c4*4+3][r] = a.w;
        }
        #pragma unroll
        for (int q = 0; q < 2; q++){
            int f = tid + 128*q, rb = f >> 4, cb = f & 15;
            *(float4*)&Bs[rb][cb*4] = *(const float4*)&B[(k0+rb)*HD + tbn + cb*4];
        }
        __syncthreads();
        #pragma unroll
        for (int k = 0; k < 16; k++){
            float4 a0 = *(const float4*)&As[k][ty*8];
            float4 a1 = *(const float4*)&As[k][ty*8+4];
            float4 b0 = *(const float4*)&Bs[k][tx*4];
            float4 b1 = *(const float4*)&Bs[k][32 + tx*4];
            float2 bb[4] = {{b0.x,b0.y},{b0.z,b0.w},{b1.x,b1.y},{b1.z,b1.w}};
            float av[8] = {a0.x,a0.y,a0.z,a0.w,a1.x,a1.y,a1.z,a1.w};
            #pragma unroll
            for (int i = 0; i < 8; i++){
                float2 ap = make_float2(av[i], av[i]);
                ffma2(acc[i][0], ap, bb[0]);
                ffma2(acc[i][1], ap, bb[1]);
                ffma2(acc[i][2], ap, bb[2]);
                ffma2(acc[i][3], ap, bb[3]);
            }
        }
        __syncthreads();
    }
    #pragma unroll
    for (int i = 0; i < 8; i++){
        int row = tbm + ty*8 + i;
        *(float4*)&C[row*HD + tbn + tx*4]      = make_float4(acc[i][0].x, acc[i][0].y, acc[i][1].x, acc[i][1].y);
        *(float4*)&C[row*HD + tbn + 32 + tx*4] = make_float4(acc[i][2].x, acc[i][2].y, acc[i][3].x, acc[i][3].y);
    }
}

// ---------------- compressed attention QK^T (128x128 tiles) + row-max atomics ----------------
__global__ __launch_bounds__(256) void qk_k(){
    int h = blockIdx.z, nt = blockIdx.y*128, jt = blockIdx.x*128;
    int nv = g_nvalid;
    if (jt >= nv) return;
    __shared__ float Qs[16][132];
    __shared__ float Ks[16][132];
    int tid = threadIdx.x, ty = tid >> 4, tx = tid & 15;
    float2 acc[8][4];
    #pragma unroll
    for (int i = 0; i < 8; i++)
        #pragma unroll
        for (int j = 0; j < 4; j++) acc[i][j] = make_float2(0.f, 0.f);

    for (int k0 = 0; k0 < DH; k0 += 16){
        #pragma unroll
        for (int q = 0; q < 2; q++){
            int f = tid + 256*q, r = f >> 2, c4 = f & 3;
            float4 a = *(const float4*)&g_q [(nt+r)*HD + h*DH + k0 + c4*4];
            Qs[c4*4+0][r] = a.x; Qs[c4*4+1][r] = a.y; Qs[c4*4+2][r] = a.z; Qs[c4*4+3][r] = a.w;
            float4 b = *(const float4*)&g_ck[(jt+r)*HD + h*DH + k0 + c4*4];
            Ks[c4*4+0][r] = b.x; Ks[c4*4+1][r] = b.y; Ks[c4*4+2][r] = b.z; Ks[c4*4+3][r] = b.w;
        }
        __syncthreads();
        #pragma unroll
        for (int k = 0; k < 16; k++){
            float4 a0 = *(const float4*)&Qs[k][ty*8];
            float4 a1 = *(const float4*)&Qs[k][ty*8+4];
            float4 b0 = *(const float4*)&Ks[k][tx*4];
            float4 b1 = *(const float4*)&Ks[k][64 + tx*4];
            float2 bb[4] = {{b0.x,b0.y},{b0.z,b0.w},{b1.x,b1.y},{b1.z,b1.w}};
            float av[8] = {a0.x,a0.y,a0.z,a0.w,a1.x,a1.y,a1.z,a1.w};
            #pragma unroll
            for (int i = 0; i < 8; i++){
                float2 ap = make_float2(av[i], av[i]);
                ffma2(acc[i][0], ap, bb[0]);
                ffma2(acc[i][1], ap, bb[1]);
                ffma2(acc[i][2], ap, bb[2]);
                ffma2(acc[i][3], ap, bb[3]);
            }
        }
        __syncthreads();
    }
    int j0 = jt + tx*4, j1 = jt + 64 + tx*4;
    #pragma unroll
    for (int i = 0; i < 8; i++){
        int row = nt + ty*8 + i;
        float s[8] = {acc[i][0].x*0.125f, acc[i][0].y*0.125f, acc[i][1].x*0.125f, acc[i][1].y*0.125f,
                      acc[i][2].x*0.125f, acc[i][2].y*0.125f, acc[i][3].x*0.125f, acc[i][3].y*0.125f};
        float* dst = &g_S[((size_t)(h*NTOK + row))*MB];
        *(float4*)&dst[j0] = make_float4(s[0], s[1], s[2], s[3]);
        *(float4*)&dst[j1] = make_float4(s[4], s[5], s[6], s[7]);
        float m = -3.0e38f;
        #pragma unroll
        for (int c = 0; c < 4; c++){ if (j0 + c < nv) m = fmaxf(m, s[c]); }
        #pragma unroll
        for (int c = 0; c < 4; c++){ if (j1 + c < nv) m = fmaxf(m, s[4+c]); }
        #pragma unroll
        for (int o = 1; o < 16; o <<= 1) m = fmaxf(m, __shfl_xor_sync(0xffffffffu, m, o));
        if (tx == 0) atomicMax(&g_rowmaxk[h*NTOK + row], fenc(m));
    }
}

// ---------------- fused softmax + head-pooled probs (single pass over S) ----------------
__global__ __launch_bounds__(256) void smrow_k(){
    int n = blockIdx.x, tid = threadIdx.x;
    int nv = g_nvalid;
    __shared__ float red[8];
    __shared__ float binv;
    float p8a[16];
    #pragma unroll
    for (int q = 0; q < 16; q++) p8a[q] = 0.f;

    for (int h = 0; h < NH; h++){
        float* row = g_S + ((size_t)(h*NTOK + n))*MB;
        float bm = fdec(g_rowmaxk[h*NTOK + n]);
        float ec[16];
        float l = 0.f;
        #pragma unroll
        for (int q = 0; q < 16; q++){
            int j = tid + q*256;
            float e = 0.f;
            if (j < nv){ e = fexp(row[j] - bm); row[j] = e; l += e; }
            ec[q] = e;
        }
        #pragma unroll
        for (int o = 16; o; o >>= 1) l += __shfl_xor_sync(0xffffffffu, l, o);
        if ((tid & 31) == 0) red[tid >> 5] = l;
        __syncthreads();
        if (tid == 0){
            float s = 0.f;
            #pragma unroll
            for (int w = 0; w < 8; w++) s += red[w];
            float iv = 1.0f / s;
            binv = iv;
            g_invl[h*NTOK + n] = iv;
        }
        __syncthreads();
        float il = binv;
        #pragma unroll
        for (int q = 0; q < 16; q++) p8a[q] += ec[q] * il;
        __syncthreads();
    }
    #pragma unroll
    for (int q = 0; q < 16; q++){
        int j = tid + q*256;
        if (j < nv) g_P8[(size_t)n*MB + j] = p8a[q];
    }
}

// ---------------- compressed attention P @ V (128x64 tiles) ----------------
__global__ __launch_bounds__(128) void pv_k(){
    int nt = blockIdx.x*128, h = blockIdx.y;
    int nv = g_nvalid;
    int nv16 = (nv + 15) & ~15;
    __shared__ float Ps[16][132];
    __shared__ float Vs[16][68];
    int tid = threadIdx.x, ty = tid >> 3, tx = tid & 7;
    float2 acc[8][4];
    #pragma unroll
    for (int i = 0; i < 8; i++)
        #pragma unroll
        for (int j = 0; j < 4; j++) acc[i][j] = make_float2(0.f, 0.f);

    for (int j0 = 0; j0 < nv16; j0 += 16){
        #pragma unroll
        for (int q = 0; q < 4; q++){
            int f = tid + 128*q, r = f >> 2, c4 = f & 3;
            float4 s = *(const float4*)&g_S[((size_t)(h*NTOK + nt + r))*MB + j0 + c4*4];
            float il = g_invl[h*NTOK + nt + r];
            Ps[c4*4+0][r] = s.x*il; Ps[c4*4+1][r] = s.y*il;
            Ps[c4*4+2][r] = s.z*il; Ps[c4*4+3][r] = s.w*il;
        }
        #pragma unroll
        for (int q = 0; q < 2; q++){
            int f = tid + 128*q, rb = f >> 4, cb = f & 15;
            *(float4*)&Vs[rb][cb*4] = *(const float4*)&g_cv[(j0+rb)*HD + h*DH + cb*4];
        }
        __syncthreads();
        #pragma unroll
        for (int k = 0; k < 16; k++){
            float4 a0 = *(const float4*)&Ps[k][ty*8];
            float4 a1 = *(const float4*)&Ps[k][ty*8+4];
            float4 b0 = *(const float4*)&Vs[k][tx*4];
            float4 b1 = *(const float4*)&Vs[k][32 + tx*4];
            float2 bb[4] = {{b0.x,b0.y},{b0.z,b0.w},{b1.x,b1.y},{b1.z,b1.w}};
            float av[8] = {a0.x,a0.y,a0.z,a0.w,a1.x,a1.y,a1.z,a1.w};
            #pragma unroll
            for (int i = 0; i < 8; i++){
                float2 ap = make_float2(av[i], av[i]);
                ffma2(acc[i][0], ap, bb[0]);
                ffma2(acc[i][1], ap, bb[1]);
                ffma2(acc[i][2], ap, bb[2]);
                ffma2(acc[i][3], ap, bb[3]);
            }
        }
        __syncthreads();
    }
    #pragma unroll
    for (int i = 0; i < 8; i++){
        int row = nt + ty*8 + i;
        *(float4*)&g_outc[row*HD + h*DH + tx*4]      = make_float4(acc[i][0].x, acc[i][0].y, acc[i][1].x, acc[i][1].y);
        *(float4*)&g_outc[row*HD + h*DH + 32 + tx*4] = make_float4(acc[i][2].x, acc[i][2].y, acc[i][3].x, acc[i][3].y);
    }
}

// ---------------- sel_score + top-8 (warp-shuffle argmax) ----------------
__global__ void topk_k(){
    int n = blockIdx.x, tid = threadIdx.x;   // 512 threads
    int lane = tid & 31, w = tid >> 5;
    __shared__ float ss[SBN];
    __shared__ float wv[16];
    __shared__ int   wi[16];
    float v = 0.f;
    int o0 = g_soff[tid], o1 = g_soff[tid+1];
    for (int i = o0; i < o1; i++) v += g_P8[(size_t)n*MB + g_slist[i]];
    ss[tid] = v;
    __syncthreads();
    for (int r = 0; r < 8; r++){
        float mv = ss[tid]; int mi = tid;
        #pragma unroll
        for (int o = 16; o; o >>= 1){
            float ov = __shfl_xor_sync(0xffffffffu, mv, o);
            int   oi = __shfl_xor_sync(0xffffffffu, mi, o);
            if (ov > mv || (ov == mv && oi < mi)){ mv = ov; mi = oi; }
        }
        if (lane == 0){ wv[w] = mv; wi[w] = mi; }
        __syncthreads();
        if (tid < 16){
            float m2 = wv[tid]; int i2 = wi[tid];
            #pragma unroll
            for (int o = 8; o; o >>= 1){
                float ov = __shfl_xor_sync(0x0000ffffu, m2, o);
                int   oi = __shfl_xor_sync(0x0000ffffu, i2, o);
                if (ov > m2 || (ov == m2 && oi < i2)){ m2 = ov; i2 = oi; }
            }
            if (tid == 0){ g_top8[n*8 + r] = i2; ss[i2] = -1e30f; }
        }
        __syncthreads();
    }
}

// ---------------- selection / window attention (bucketed, online softmax) ----------------
__global__ void spattn_k(int mode){
    int n = blockIdx.x;
    int h = threadIdx.x >> 5, lane = threadIdx.x & 31;
    const float* qr = &g_q[n*HD + h*DH];
    float q0 = qr[lane], q1 = qr[lane + 32];
    float m = -1e30f, l = 0.f, a0 = 0.f, a1 = 0.f;
    int nb = (mode == 0) ? 8 : 1;
    for (int kk = 0; kk < nb; kk++){
        int b, o, e;
        if (mode == 0){ b = g_top8[n*8 + kk]; o = g_sboff[b]; e = g_sboff[b+1]; }
        else          { b = g_wid[n];         o = g_woff[b];  e = g_woff[b+1]; }
        for (int i = o; i < e; i++){
            int t = (mode == 0) ? g_sbperm[i] : g_wperm[i];
            const float* kr = &g_kf[t*HD + h*DH];
            float s = q0*kr[lane] + q1*kr[lane + 32];
            #pragma unroll
            for (int of = 16; of; of >>= 1) s += __shfl_xor_sync(0xffffffffu, s, of);
            s *= 0.125f;
            float mn = fmaxf(m, s);
            float c = fexp(m - mn), ww = fexp(s - mn);
            const float* vr = &g_vf[t*HD + h*DH];
            l  = l*c  + ww;
            a0 = a0*c + ww*vr[lane];
            a1 = a1*c + ww*vr[lane + 32];
            m = mn;
        }
    }
    float* outp = mode ? g_outw : g_outs;
    outp[n*HD + h*DH + lane]      = a0 / l;
    outp[n*HD + h*DH + lane + 32] = a1 / l;
}

// ---------------- gated fuse ----------------
__global__ void fuse_k(){
    int i = blockIdx.x*256 + threadIdx.x;
    int n = i >> 9;
    float g0 = g_gate[n*3+0], g1 = g_gate[n*3+1], g2 = g_gate[n*3+2];
    g_fused[i] = g0*g_outc[i] + g1*g_outs[i] + g2*g_outw[i];
}

// ---------------- launch ----------------
extern "C" void kernel_launch(void* const* d_in, const int* in_sizes, int n_in,
                              void* d_out, int out_size){
    const float* feats  = (const float*)d_in[0];
    const int*   coords = (const int*)  d_in[1];
    const float* Wq  = (const float*)d_in[2];
    const float* Wk  = (const float*)d_in[3];
    const float* Wv  = (const float*)d_in[4];
    const float* Wo  = (const float*)d_in[5];
    const float* Wck = (const float*)d_in[6];
    const float* Wcv = (const float*)d_in[7];
    const float* pe  = (const float*)d_in[8];
    const float* Wg  = (const float*)d_in[9];
    float* out = (float*)d_out;

    float *gq, *gkf, *gvf, *gkavg, *gvavg, *gck, *gcv, *gfused;
    cudaGetSymbolAddress((void**)&gq,    g_q);
    cudaGetSymbolAddress((void**)&gkf,   g_kf);
    cudaGetSymbolAddress((void**)&gvf,   g_vf);
    cudaGetSymbolAddress((void**)&gkavg, g_kavg);
    cudaGetSymbolAddress((void**)&gvavg, g_vavg);
    cudaGetSymbolAddress((void**)&gck,   g_ck);
    cudaGetSymbolAddress((void**)&gcv,   g_cv);
    cudaGetSymbolAddress((void**)&gfused,g_fused);

    zero_k<<<64, 256>>>();
    prep_k<<<8, 256>>>(coords);
    gate_k<<<NTOK, 128>>>(feats, Wg);

    proj_k<<<dim3(HD/128, NTOK/128, 3), 256>>>(feats, Wq, Wk, Wv, gq, gkf, gvf);

    scan1_k<<<1, 128>>>();
    permfill_k<<<8, 256>>>();
    avg_k<<<MB, 256>>>(pe);

    gemm64_k<<<dim3(HD/64, MB/128, 2), 128>>>(gkavg, gvavg, Wck, Wcv, gck, gcv, 1);

    scan2_k<<<1, 32>>>();
    slist_k<<<16, 256>>>();

    qk_k<<<dim3(MB/128, NTOK/128, NH), 256>>>();
    smrow_k<<<NTOK, 256>>>();
    pv_k<<<dim3(NTOK/128, NH), 128>>>();
    topk_k<<<NTOK, 512>>>();

    spattn_k<<<NTOK, 256>>>(0);
    spattn_k<<<NTOK, 256>>>(1);

    fuse_k<<<NTOK*HD/256, 256>>>();
    gemm64_k<<<dim3(HD/64, NTOK/128, 1), 128>>>(gfused, gfused, Wo, Wo, out, out, 0);
}

// round 3
// speedup vs baseline: 1.3862x; 1.0933x over previous
#include <cuda_runtime.h>

#define NTOK 2048
#define HD   512
#define NH   8
#define DH   64
#define MB   4096      // compression blocks (16^3)
#define SBN  512       // selection blocks (8^3)
#define NWID 729       // shifted windows (9^3)

// ---------------- scratch (device globals; no allocations) ----------------
__device__ float g_q[NTOK*HD], g_kf[NTOK*HD], g_vf[NTOK*HD];
__device__ float g_kavg[MB*HD], g_vavg[MB*HD], g_ck[MB*HD], g_cv[MB*HD];
__device__ float g_S[(size_t)NH*NTOK*MB];     // scores, then exp(s-max) in place
__device__ float g_P8[(size_t)NTOK*MB];       // head-pooled probs per compact block
__device__ float g_invl[NH*NTOK];
__device__ unsigned g_rowmaxk[NH*NTOK];       // encoded row max (ordered-uint)
__device__ float g_outc[NTOK*HD], g_outs[NTOK*HD], g_outw[NTOK*HD], g_fused[NTOK*HD];
__device__ float g_gate[NTOK*3];
__device__ int g_cnt[MB], g_boff[MB+1], g_bperm[NTOK], g_bid[NTOK];
__device__ int g_sbcnt[SBN], g_sboff[SBN+1], g_sbperm[NTOK], g_sbid[NTOK];
__device__ int g_wcnt[NWID], g_woff[NWID+1], g_wperm[NTOK], g_wid[NTOK];
__device__ int g_scount[SBN], g_soff[SBN+1], g_slist[MB], g_sidc[MB];
__device__ int g_vlist[MB], g_nvalid;
__device__ int g_pei[NTOK];
__device__ int g_packed[NTOK];
__device__ int g_top8[NTOK*8];

// ---------------- packed fp32x2 FMA (FFMA2) ----------------
__device__ __forceinline__ void ffma2(float2& d, float2 a, float2 b){
    asm("fma.rn.f32x2 %0, %1, %2, %0;"
        : "+l"(reinterpret_cast<unsigned long long&>(d))
        : "l"(reinterpret_cast<unsigned long long&>(a)),
          "l"(reinterpret_cast<unsigned long long&>(b)));
}

// ---------------- fast exp on the FMA pipe (rel err ~1e-7) ----------------
__device__ __forceinline__ float fexp(float x){
    x = fminf(fmaxf(x, -87.0f), 88.0f);
    float y = x * 1.4426950408889634f;
    float z = y + 12582912.0f;
    int   ki = __float_as_int(z) - 0x4B400000;
    float kf = z - 12582912.0f;
    float f  = y - kf;
    float p  = 1.5403530393381609e-4f;
    p = fmaf(p, f, 1.3333558146428443e-3f);
    p = fmaf(p, f, 9.6181291076284772e-3f);
    p = fmaf(p, f, 5.5504108664821580e-2f);
    p = fmaf(p, f, 2.4022650695910071e-1f);
    p = fmaf(p, f, 6.9314718055994531e-1f);
    p = fmaf(p, f, 1.0f);
    return __int_as_float((ki + 127) << 23) * p;
}

__device__ __forceinline__ unsigned fenc(float f){
    unsigned u = __float_as_uint(f);
    return (u & 0x80000000u) ? ~u : (u | 0x80000000u);
}
__device__ __forceinline__ float fdec(unsigned k){
    return (k & 0x80000000u) ? __uint_as_float(k ^ 0x80000000u) : __uint_as_float(~k);
}

// ---------------- setup kernels ----------------
__global__ void zero_k(){
    int i = blockIdx.x*256 + threadIdx.x;
    if (i < MB)   g_cnt[i]   = 0;
    if (i < SBN){ g_sbcnt[i] = 0; g_scount[i] = 0; }
    if (i < NWID) g_wcnt[i]  = 0;
    if (i < NH*NTOK) g_rowmaxk[i] = 0u;
}

__global__ void prep_k(const int* __restrict__ coords){
    int t = blockIdx.x*256 + threadIdx.x;
    if (t >= NTOK) return;
    int cf = coords[t];
    int x = cf >> 12, y = (cf >> 6) & 63, z = cf & 63;
    int bid = ((x>>2)<<8) | ((y>>2)<<4) | (z>>2);
    g_bid[t] = bid; atomicAdd(&g_cnt[bid], 1);
    int sb = ((x>>3)<<6) | ((y>>3)<<3) | (z>>3);
    g_sbid[t] = sb; atomicAdd(&g_sbcnt[sb], 1);
    int wd = (((x+4)>>3)*9 + ((y+4)>>3))*9 + ((z+4)>>3);
    g_wid[t] = wd; atomicAdd(&g_wcnt[wd], 1);
    g_pei[t] = (((x&3)*4 + (y&3))*4 + (z&3)) * HD;
    g_packed[t] = bid | (sb << 12) | (wd << 21);
}

__global__ void gate_k(const float* __restrict__ feats, const float* __restrict__ Wg){
    int n = blockIdx.x;
    int w = threadIdx.x >> 5, lane = threadIdx.x & 31;
    if (w >= 3) return;
    float s = 0.f;
    for (int i = lane; i < HD; i += 32) s += feats[n*HD + i] * Wg[i*3 + w];
    #pragma unroll
    for (int o = 16; o; o >>= 1) s += __shfl_xor_sync(0xffffffffu, s, o);
    if (lane == 0) g_gate[n*3 + w] = 1.0f / (1.0f + fexp(-s));
}

__device__ __forceinline__ void warp_exscan(const int* cnt, int* off, int len){
    int lane = threadIdx.x & 31;
    int run = 0;
    for (int base = 0; base < len; base += 32){
        int raw = (base+lane < len) ? cnt[base+lane] : 0;
        int v = raw;
        #pragma unroll
        for (int o = 1; o < 32; o <<= 1){ int t = __shfl_up_sync(0xffffffffu, v, o); if (lane >= o) v += t; }
        if (base+lane < len) off[base+lane] = run + v - raw;
        run += __shfl_sync(0xffffffffu, v, 31);
    }
    if (lane == 0) off[len] = run;
}

__global__ void scan1_k(){
    int w = threadIdx.x >> 5;
    if (w == 0) warp_exscan(g_cnt,   g_boff,  MB);
    else if (w == 1) warp_exscan(g_sbcnt, g_sboff, SBN);
    else if (w == 2) warp_exscan(g_wcnt,  g_woff,  NWID);
    else {
        int lane = threadIdx.x & 31;
        int run = 0;
        for (int base = 0; base < MB; base += 32){
            int valid = g_cnt[base+lane] > 0 ? 1 : 0;
            int v = valid;
            #pragma unroll
            for (int o = 1; o < 32; o <<= 1){ int t = __shfl_up_sync(0xffffffffu, v, o); if (lane >= o) v += t; }
            if (valid) g_vlist[run + v - 1] = base + lane;
            run += __shfl_sync(0xffffffffu, v, 31);
        }
        if (lane == 0) g_nvalid = run;
    }
}

__global__ void scan2_k(){ warp_exscan(g_scount, g_soff, SBN); }

__global__ void permfill_k(){
    __shared__ int sp[256];
    int t = blockIdx.x*256 + threadIdx.x;
    int my = g_packed[t];
    int r1 = 0, r2 = 0, r3 = 0;
    for (int base = 0; base < NTOK; base += 256){
        sp[threadIdx.x] = g_packed[base + threadIdx.x];
        __syncthreads();
        int lim = t - base; if (lim > 256) lim = 256;
        for (int u = 0; u < lim; u++){
            int p = sp[u] ^ my;
            r3 += ((p & 0x00000FFF) == 0);
            r1 += ((p & 0x001FF000) == 0);
            r2 += ((p & 0x7FE00000) == 0);
        }
        __syncthreads();
    }
    int bd = my & 0xFFF, sb = (my >> 12) & 0x1FF, wd = (my >> 21) & 0x3FF;
    g_sbperm[g_sboff[sb] + r1] = t;
    g_wperm [g_woff[wd]  + r2] = t;
    g_bperm [g_boff[bd]  + r3] = t;
}

__global__ void slist_k(){
    int j = blockIdx.x*256 + threadIdx.x;
    if (j >= g_nvalid) return;
    int s = g_sidc[j];
    int r = 0;
    for (int u = 0; u < j; u++) r += (g_sidc[u] == s);
    g_slist[g_soff[s] + r] = j;
}

__global__ void avg_k(const float* __restrict__ pe){
    int j = blockIdx.x;
    int nv = g_nvalid;
    if (j >= nv){
        for (int c = threadIdx.x; c < HD; c += 256){
            g_kavg[j*HD + c] = 0.f; g_vavg[j*HD + c] = 0.f;
        }
        return;
    }
    int m = g_vlist[j];
    int c0 = g_boff[m], c1 = g_boff[m+1];
    float dn = 1.0f / (float)max(c1 - c0, 1);
    for (int c = threadIdx.x; c < HD; c += 256){
        float sk = 0.f, sv = 0.f;
        for (int i = c0; i < c1; i++){
            int t = g_bperm[i];
            sk += g_kf[t*HD + c] + pe[g_pei[t] + c];
            sv += g_vf[t*HD + c];
        }
        g_kavg[j*HD + c] = sk * dn;
        g_vavg[j*HD + c] = sv * dn;
    }
    if (threadIdx.x == 0){
        int mx = m >> 8, my = (m >> 4) & 15, mz = m & 15;
        int sid = ((mx>>1)<<6) | ((my>>1)<<3) | (mz>>1);
        g_sidc[j] = sid;
        atomicAdd(&g_scount[sid], 1);
    }
}

// ---------------- shared 128x64 tile compute (8 rows x 8 cols / thread) ----------------
__device__ __forceinline__ void tc128(const float (*As)[132], const float (*Bs)[68],
                                      int ty, int tx, float2 acc[8][4]){
    #pragma unroll
    for (int k = 0; k < 16; k++){
        float4 a0 = *(const float4*)&As[k][ty*8];
        float4 a1 = *(const float4*)&As[k][ty*8+4];
        float4 b0 = *(const float4*)&Bs[k][tx*4];
        float4 b1 = *(const float4*)&Bs[k][32+tx*4];
        float2 bb0 = {b0.x,b0.y}, bb1 = {b0.z,b0.w}, bb2 = {b1.x,b1.y}, bb3 = {b1.z,b1.w};
        float av[8] = {a0.x,a0.y,a0.z,a0.w,a1.x,a1.y,a1.z,a1.w};
        #pragma unroll
        for (int i = 0; i < 8; i++){
            float2 ap = {av[i], av[i]};
            ffma2(acc[i][0], ap, bb0);
            ffma2(acc[i][1], ap, bb1);
            ffma2(acc[i][2], ap, bb2);
            ffma2(acc[i][3], ap, bb3);
        }
    }
}

// ---------------- pipelined 128x64 GEMM over K=512 (proj + Wo) ----------------
__global__ __launch_bounds__(128) void proj_k(
    const float* __restrict__ A,
    const float* __restrict__ B0, const float* __restrict__ B1, const float* __restrict__ B2,
    float* __restrict__ C0, float* __restrict__ C1, float* __restrict__ C2)
{
    const float* B = blockIdx.z == 0 ? B0 : (blockIdx.z == 1 ? B1 : B2);
    float*       C = blockIdx.z == 0 ? C0 : (blockIdx.z == 1 ? C1 : C2);
    int tbm = blockIdx.y*128, tbn = blockIdx.x*64;
    __shared__ float As[2][16][132];
    __shared__ float Bs[2][16][68];
    int tid = threadIdx.x, ty = tid >> 3, tx = tid & 7;
    float2 acc[8][4];
    #pragma unroll
    for (int i = 0; i < 8; i++){ acc[i][0]={0,0}; acc[i][1]={0,0}; acc[i][2]={0,0}; acc[i][3]={0,0}; }
    float4 ar[4], br[2];
    #pragma unroll
    for (int q = 0; q < 4; q++){ int f = tid+128*q; ar[q] = *(const float4*)&A[(size_t)(tbm+(f>>2))*HD + (f&3)*4]; }
    #pragma unroll
    for (int q = 0; q < 2; q++){ int f = tid+128*q; br[q] = *(const float4*)&B[(size_t)(f>>4)*HD + tbn + (f&15)*4]; }
    #pragma unroll
    for (int q = 0; q < 4; q++){ int f = tid+128*q; int r=f>>2, c4=f&3;
        As[0][c4*4+0][r]=ar[q].x; As[0][c4*4+1][r]=ar[q].y; As[0][c4*4+2][r]=ar[q].z; As[0][c4*4+3][r]=ar[q].w; }
    #pragma unroll
    for (int q = 0; q < 2; q++){ int f = tid+128*q; *(float4*)&Bs[0][f>>4][(f&15)*4] = br[q]; }
    __syncthreads();
    for (int it = 1; it < HD/16; it++){
        int k0 = it*16;
        #pragma unroll
        for (int q = 0; q < 4; q++){ int f = tid+128*q; ar[q] = *(const float4*)&A[(size_t)(tbm+(f>>2))*HD + k0 + (f&3)*4]; }
        #pragma unroll
        for (int q = 0; q < 2; q++){ int f = tid+128*q; br[q] = *(const float4*)&B[(size_t)(k0+(f>>4))*HD + tbn + (f&15)*4]; }
        tc128(As[(it-1)&1], Bs[(it-1)&1], ty, tx, acc);
        int nb = it & 1;
        #pragma unroll
        for (int q = 0; q < 4; q++){ int f = tid+128*q; int r=f>>2, c4=f&3;
            As[nb][c4*4+0][r]=ar[q].x; As[nb][c4*4+1][r]=ar[q].y; As[nb][c4*4+2][r]=ar[q].z; As[nb][c4*4+3][r]=ar[q].w; }
        #pragma unroll
        for (int q = 0; q < 2; q++){ int f = tid+128*q; *(float4*)&Bs[nb][f>>4][(f&15)*4] = br[q]; }
        __syncthreads();
    }
    tc128(As[(HD/16-1)&1], Bs[(HD/16-1)&1], ty, tx, acc);
    #pragma unroll
    for (int i = 0; i < 8; i++){
        int row = tbm + ty*8 + i;
        *(float4*)&C[(size_t)row*HD + tbn + tx*4]      = make_float4(acc[i][0].x, acc[i][0].y, acc[i][1].x, acc[i][1].y);
        *(float4*)&C[(size_t)row*HD + tbn + 32 + tx*4] = make_float4(acc[i][2].x, acc[i][2].y, acc[i][3].x, acc[i][3].y);
    }
}

// ---------------- pipelined 128x64 GEMM, guarded rows (Wck/Wcv) ----------------
__global__ __launch_bounds__(128) void cmp_k(
    const float* __restrict__ A0, const float* __restrict__ A1,
    const float* __restrict__ B0, const float* __restrict__ B1,
    float* __restrict__ C0, float* __restrict__ C1)
{
    const float* A = blockIdx.z ? A1 : A0;
    const float* B = blockIdx.z ? B1 : B0;
    float*       C = blockIdx.z ? C1 : C0;
    int tbm = blockIdx.y*128, tbn = blockIdx.x*64;
    if (tbm >= g_nvalid) return;
    __shared__ float As[2][16][132];
    __shared__ float Bs[2][16][68];
    int tid = threadIdx.x, ty = tid >> 3, tx = tid & 7;
    float2 acc[8][4];
    #pragma unroll
    for (int i = 0; i < 8; i++){ acc[i][0]={0,0}; acc[i][1]={0,0}; acc[i][2]={0,0}; acc[i][3]={0,0}; }
    float4 ar[4], br[2];
    #pragma unroll
    for (int q = 0; q < 4; q++){ int f = tid+128*q; ar[q] = *(const float4*)&A[(size_t)(tbm+(f>>2))*HD + (f&3)*4]; }
    #pragma unroll
    for (int q = 0; q < 2; q++){ int f = tid+128*q; br[q] = *(const float4*)&B[(size_t)(f>>4)*HD + tbn + (f&15)*4]; }
    #pragma unroll
    for (int q = 0; q < 4; q++){ int f = tid+128*q; int r=f>>2, c4=f&3;
        As[0][c4*4+0][r]=ar[q].x; As[0][c4*4+1][r]=ar[q].y; As[0][c4*4+2][r]=ar[q].z; As[0][c4*4+3][r]=ar[q].w; }
    #pragma unroll
    for (int q = 0; q < 2; q++){ int f = tid+128*q; *(float4*)&Bs[0][f>>4][(f&15)*4] = br[q]; }
    __syncthreads();
    for (int it = 1; it < HD/16; it++){
        int k0 = it*16;
        #pragma unroll
        for (int q = 0; q < 4; q++){ int f = tid+128*q; ar[q] = *(const float4*)&A[(size_t)(tbm+(f>>2))*HD + k0 + (f&3)*4]; }
        #pragma unroll
        for (int q = 0; q < 2; q++){ int f = tid+128*q; br[q] = *(const float4*)&B[(size_t)(k0+(f>>4))*HD + tbn + (f&15)*4]; }
        tc128(As[(it-1)&1], Bs[(it-1)&1], ty, tx, acc);
        int nb = it & 1;
        #pragma unroll
        for (int q = 0; q < 4; q++){ int f = tid+128*q; int r=f>>2, c4=f&3;
            As[nb][c4*4+0][r]=ar[q].x; As[nb][c4*4+1][r]=ar[q].y; As[nb][c4*4+2][r]=ar[q].z; As[nb][c4*4+3][r]=ar[q].w; }
        #pragma unroll
        for (int q = 0; q < 2; q++){ int f = tid+128*q; *(float4*)&Bs[nb][f>>4][(f&15)*4] = br[q]; }
        __syncthreads();
    }
    tc128(As[(HD/16-1)&1], Bs[(HD/16-1)&1], ty, tx, acc);
    #pragma unroll
    for (int i = 0; i < 8; i++){
        int row = tbm + ty*8 + i;
        *(float4*)&C[(size_t)row*HD + tbn + tx*4]      = make_float4(acc[i][0].x, acc[i][0].y, acc[i][1].x, acc[i][1].y);
        *(float4*)&C[(size_t)row*HD + tbn + 32 + tx*4] = make_float4(acc[i][2].x, acc[i][2].y, acc[i][3].x, acc[i][3].y);
    }
}

// ---------------- compressed attention QK^T (128x64 tiles, K=64) + row-max ----------------
__global__ __launch_bounds__(128) void qk_k(){
    int h = blockIdx.z, nt = blockIdx.y*128, jt = blockIdx.x*64;
    int nv = g_nvalid;
    if (jt >= nv) return;
    __shared__ float As[2][16][132];
    __shared__ float Bs[2][16][68];
    int tid = threadIdx.x, ty = tid >> 3, tx = tid & 7;
    const float* Abase = g_q  + h*DH;
    const float* Bbase = g_ck + h*DH;
    float2 acc[8][4];
    #pragma unroll
    for (int i = 0; i < 8; i++){ acc[i][0]={0,0}; acc[i][1]={0,0}; acc[i][2]={0,0}; acc[i][3]={0,0}; }
    float4 ar[4], br[2];
    #pragma unroll
    for (int q = 0; q < 4; q++){ int f = tid+128*q; ar[q] = *(const float4*)&Abase[(size_t)(nt+(f>>2))*HD + (f&3)*4]; }
    #pragma unroll
    for (int q = 0; q < 2; q++){ int f = tid+128*q; br[q] = *(const float4*)&Bbase[(size_t)(jt+(f>>2))*HD + (f&3)*4]; }
    #pragma unroll
    for (int q = 0; q < 4; q++){ int f = tid+128*q; int r=f>>2, c4=f&3;
        As[0][c4*4+0][r]=ar[q].x; As[0][c4*4+1][r]=ar[q].y; As[0][c4*4+2][r]=ar[q].z; As[0][c4*4+3][r]=ar[q].w; }
    #pragma unroll
    for (int q = 0; q < 2; q++){ int f = tid+128*q; int r=f>>2, c4=f&3;
        Bs[0][c4*4+0][r]=br[q].x; Bs[0][c4*4+1][r]=br[q].y; Bs[0][c4*4+2][r]=br[q].z; Bs[0][c4*4+3][r]=br[q].w; }
    __syncthreads();
    #pragma unroll
    for (int it = 1; it < 4; it++){
        int k0 = it*16;
        #pragma unroll
        for (int q = 0; q < 4; q++){ int f = tid+128*q; ar[q] = *(const float4*)&Abase[(size_t)(nt+(f>>2))*HD + k0 + (f&3)*4]; }
        #pragma unroll
        for (int q = 0; q < 2; q++){ int f = tid+128*q; br[q] = *(const float4*)&Bbase[(size_t)(jt+(f>>2))*HD + k0 + (f&3)*4]; }
        tc128(As[(it-1)&1], Bs[(it-1)&1], ty, tx, acc);
        int nb = it & 1;
        #pragma unroll
        for (int q = 0; q < 4; q++){ int f = tid+128*q; int r=f>>2, c4=f&3;
            As[nb][c4*4+0][r]=ar[q].x; As[nb][c4*4+1][r]=ar[q].y; As[nb][c4*4+2][r]=ar[q].z; As[nb][c4*4+3][r]=ar[q].w; }
        #pragma unroll
        for (int q = 0; q < 2; q++){ int f = tid+128*q; int r=f>>2, c4=f&3;
            Bs[nb][c4*4+0][r]=br[q].x; Bs[nb][c4*4+1][r]=br[q].y; Bs[nb][c4*4+2][r]=br[q].z; Bs[nb][c4*4+3][r]=br[q].w; }
        __syncthreads();
    }
    tc128(As[1], Bs[1], ty, tx, acc);

    int j0 = jt + tx*4, j1 = jt + 32 + tx*4;
    #pragma unroll
    for (int i = 0; i < 8; i++){
        int row = nt + ty*8 + i;
        float s[8] = {acc[i][0].x*0.125f, acc[i][0].y*0.125f, acc[i][1].x*0.125f, acc[i][1].y*0.125f,
                      acc[i][2].x*0.125f, acc[i][2].y*0.125f, acc[i][3].x*0.125f, acc[i][3].y*0.125f};
        float* dst = &g_S[((size_t)(h*NTOK + row))*MB];
        *(float4*)&dst[j0] = make_float4(s[0], s[1], s[2], s[3]);
        *(float4*)&dst[j1] = make_float4(s[4], s[5], s[6], s[7]);
        float m = -3.0e38f;
        #pragma unroll
        for (int c = 0; c < 4; c++){ if (j0 + c < nv) m = fmaxf(m, s[c]); }
        #pragma unroll
        for (int c = 0; c < 4; c++){ if (j1 + c < nv) m = fmaxf(m, s[4+c]); }
        #pragma unroll
        for (int o = 1; o < 8; o <<= 1) m = fmaxf(m, __shfl_xor_sync(0xffffffffu, m, o));
        if (tx == 0) atomicMax(&g_rowmaxk[h*NTOK + row], fenc(m));
    }
}

// ---------------- fused softmax + head-pooled probs (single pass over S) ----------------
__global__ __launch_bounds__(256) void smrow_k(){
    int n = blockIdx.x, tid = threadIdx.x;
    int nv = g_nvalid;
    __shared__ float red[8];
    __shared__ float binv;
    float p8a[16];
    #pragma unroll
    for (int q = 0; q < 16; q++) p8a[q] = 0.f;

    for (int h = 0; h < NH; h++){
        float* row = g_S + ((size_t)(h*NTOK + n))*MB;
        float bm = fdec(g_rowmaxk[h*NTOK + n]);
        float ec[16];
        float l = 0.f;
        #pragma unroll
        for (int q = 0; q < 16; q++){
            int j = tid + q*256;
            float e = 0.f;
            if (j < nv){ e = fexp(row[j] - bm); row[j] = e; l += e; }
            ec[q] = e;
        }
        #pragma unroll
        for (int o = 16; o; o >>= 1) l += __shfl_xor_sync(0xffffffffu, l, o);
        if ((tid & 31) == 0) red[tid >> 5] = l;
        __syncthreads();
        if (tid == 0){
            float s = 0.f;
            #pragma unroll
            for (int w = 0; w < 8; w++) s += red[w];
            float iv = 1.0f / s;
            binv = iv;
            g_invl[h*NTOK + n] = iv;
        }
        __syncthreads();
        float il = binv;
        #pragma unroll
        for (int q = 0; q < 16; q++) p8a[q] += ec[q] * il;
        __syncthreads();
    }
    #pragma unroll
    for (int q = 0; q < 16; q++){
        int j = tid + q*256;
        if (j < nv) g_P8[(size_t)n*MB + j] = p8a[q];
    }
}

// ---------------- compressed attention P @ V (64x64 tiles, pipelined) ----------------
__global__ __launch_bounds__(128) void pv_k(){
    int nt = blockIdx.x*64, h = blockIdx.y;
    int nv = g_nvalid;
    int nk = ((nv + 15) & ~15) / 16;
    __shared__ float Ps[2][16][68];
    __shared__ float Vs[2][16][68];
    int tid = threadIdx.x, ty = tid >> 3, tx = tid & 7;
    float2 acc[4][4];
    #pragma unroll
    for (int i = 0; i < 4; i++){ acc[i][0]={0,0}; acc[i][1]={0,0}; acc[i][2]={0,0}; acc[i][3]={0,0}; }
    const float* Sbase = g_S + (size_t)(h*NTOK + nt)*MB;
    const float* Vbase = g_cv + h*DH;
    float4 ar[2], br[2];
    #pragma unroll
    for (int q = 0; q < 2; q++){ int f = tid+128*q; ar[q] = *(const float4*)&Sbase[(size_t)(f>>2)*MB + (f&3)*4]; }
    #pragma unroll
    for (int q = 0; q < 2; q++){ int f = tid+128*q; br[q] = *(const float4*)&Vbase[(size_t)(f>>4)*HD + (f&15)*4]; }
    #pragma unroll
    for (int q = 0; q < 2; q++){ int f = tid+128*q; int r=f>>2, c4=f&3;
        Ps[0][c4*4+0][r]=ar[q].x; Ps[0][c4*4+1][r]=ar[q].y; Ps[0][c4*4+2][r]=ar[q].z; Ps[0][c4*4+3][r]=ar[q].w; }
    #pragma unroll
    for (int q = 0; q < 2; q++){ int f = tid+128*q; *(float4*)&Vs[0][f>>4][(f&15)*4] = br[q]; }
    __syncthreads();
    for (int it = 1; it < nk; it++){
        int k0 = it*16;
        #pragma unroll
        for (int q = 0; q < 2; q++){ int f = tid+128*q; ar[q] = *(const float4*)&Sbase[(size_t)(f>>2)*MB + k0 + (f&3)*4]; }
        #pragma unroll
        for (int q = 0; q < 2; q++){ int f = tid+128*q; br[q] = *(const float4*)&Vbase[(size_t)(k0+(f>>4))*HD + (f&15)*4]; }
        {
            const float (*Pb)[68] = Ps[(it-1)&1];
            const float (*Vb)[68] = Vs[(it-1)&1];
            #pragma unroll
            for (int k = 0; k < 16; k++){
                float4 a0 = *(const float4*)&Pb[k][ty*4];
                float4 b0 = *(const float4*)&Vb[k][tx*4];
                float4 b1 = *(const float4*)&Vb[k][32+tx*4];
                float2 bb0 = {b0.x,b0.y}, bb1 = {b0.z,b0.w}, bb2 = {b1.x,b1.y}, bb3 = {b1.z,b1.w};
                float av[4] = {a0.x,a0.y,a0.z,a0.w};
                #pragma unroll
                for (int i = 0; i < 4; i++){
                    float2 ap = {av[i], av[i]};
                    ffma2(acc[i][0], ap, bb0);
                    ffma2(acc[i][1], ap, bb1);
                    ffma2(acc[i][2], ap, bb2);
                    ffma2(acc[i][3], ap, bb3);
                }
            }
        }
        int nb = it & 1;
        #pragma unroll
        for (int q = 0; q < 2; q++){ int f = tid+128*q; int r=f>>2, c4=f&3;
            Ps[nb][c4*4+0][r]=ar[q].x; Ps[nb][c4*4+1][r]=ar[q].y; Ps[nb][c4*4+2][r]=ar[q].z; Ps[nb][c4*4+3][r]=ar[q].w; }
        #pragma unroll
        for (int q = 0; q < 2; q++){ int f = tid+128*q; *(float4*)&Vs[nb][f>>4][(f&15)*4] = br[q]; }
        __syncthreads();
    }
    {
        const float (*Pb)[68] = Ps[(nk-1)&1];
        const float (*Vb)[68] = Vs[(nk-1)&1];
        #pragma unroll
        for (int k = 0; k < 16; k++){
            float4 a0 = *(const float4*)&Pb[k][ty*4];
            float4 b0 = *(const float4*)&Vb[k][tx*4];
            float4 b1 = *(const float4*)&Vb[k][32+tx*4];
            float2 bb0 = {b0.x,b0.y}, bb1 = {b0.z,b0.w}, bb2 = {b1.x,b1.y}, bb3 = {b1.z,b1.w};
            float av[4] = {a0.x,a0.y,a0.z,a0.w};
            #pragma unroll
            for (int i = 0; i < 4; i++){
                float2 ap = {av[i], av[i]};
                ffma2(acc[i][0], ap, bb0);
                ffma2(acc[i][1], ap, bb1);
                ffma2(acc[i][2], ap, bb2);
                ffma2(acc[i][3], ap, bb3);
            }
        }
    }
    #pragma unroll
    for (int i = 0; i < 4; i++){
        int row = nt + ty*4 + i;
        float il = g_invl[h*NTOK + row];
        *(float4*)&g_outc[(size_t)row*HD + h*DH + tx*4]      = make_float4(acc[i][0].x*il, acc[i][0].y*il, acc[i][1].x*il, acc[i][1].y*il);
        *(float4*)&g_outc[(size_t)row*HD + h*DH + 32 + tx*4] = make_float4(acc[i][2].x*il, acc[i][2].y*il, acc[i][3].x*il, acc[i][3].y*il);
    }
}

// ---------------- sel_score + top-8 (warp-shuffle argmax) ----------------
__global__ void topk_k(){
    int n = blockIdx.x, tid = threadIdx.x;   // 512 threads
    int lane = tid & 31, w = tid >> 5;
    __shared__ float ss[SBN];
    __shared__ float wv[16];
    __shared__ int   wi[16];
    float v = 0.f;
    int o0 = g_soff[tid], o1 = g_soff[tid+1];
    for (int i = o0; i < o1; i++) v += g_P8[(size_t)n*MB + g_slist[i]];
    ss[tid] = v;
    __syncthreads();
    for (int r = 0; r < 8; r++){
        float mv = ss[tid]; int mi = tid;
        #pragma unroll
        for (int o = 16; o; o >>= 1){
            float ov = __shfl_xor_sync(0xffffffffu, mv, o);
            int   oi = __shfl_xor_sync(0xffffffffu, mi, o);
            if (ov > mv || (ov == mv && oi < mi)){ mv = ov; mi = oi; }
        }
        if (lane == 0){ wv[w] = mv; wi[w] = mi; }
        __syncthreads();
        if (tid < 16){
            float m2 = wv[tid]; int i2 = wi[tid];
            #pragma unroll
            for (int o = 8; o; o >>= 1){
                float ov = __shfl_xor_sync(0x0000ffffu, m2, o);
                int   oi = __shfl_xor_sync(0x0000ffffu, i2, o);
                if (ov > m2 || (ov == m2 && oi < i2)){ m2 = ov; i2 = oi; }
            }
            if (tid == 0){ g_top8[n*8 + r] = i2; ss[i2] = -1e30f; }
        }
        __syncthreads();
    }
}

// ---------------- selection / window attention (merged modes) ----------------
__global__ void spattn_k(){
    int n = blockIdx.x, mode = blockIdx.y;
    int h = threadIdx.x >> 5, lane = threadIdx.x & 31;
    const float* qr = &g_q[n*HD + h*DH];
    float q0 = qr[lane], q1 = qr[lane + 32];
    float m = -1e30f, l = 0.f, a0 = 0.f, a1 = 0.f;
    int nb = (mode == 0) ? 8 : 1;
    for (int kk = 0; kk < nb; kk++){
        int b, o, e;
        if (mode == 0){ b = g_top8[n*8 + kk]; o = g_sboff[b]; e = g_sboff[b+1]; }
        else          { b = g_wid[n];         o = g_woff[b];  e = g_woff[b+1]; }
        for (int i = o; i < e; i++){
            int t = (mode == 0) ? g_sbperm[i] : g_wperm[i];
            const float* kr = &g_kf[t*HD + h*DH];
            float s = q0*kr[lane] + q1*kr[lane + 32];
            #pragma unroll
            for (int of = 16; of; of >>= 1) s += __shfl_xor_sync(0xffffffffu, s, of);
            s *= 0.125f;
            float mn = fmaxf(m, s);
            float c = fexp(m - mn), ww = fexp(s - mn);
            const float* vr = &g_vf[t*HD + h*DH];
            l  = l*c  + ww;
            a0 = a0*c + ww*vr[lane];
            a1 = a1*c + ww*vr[lane + 32];
            m = mn;
        }
    }
    float* outp = mode ? g_outw : g_outs;
    outp[n*HD + h*DH + lane]      = a0 / l;
    outp[n*HD + h*DH + lane + 32] = a1 / l;
}

// ---------------- gated fuse ----------------
__global__ void fuse_k(){
    int i = blockIdx.x*256 + threadIdx.x;
    int n = i >> 9;
    float g0 = g_gate[n*3+0], g1 = g_gate[n*3+1], g2 = g_gate[n*3+2];
    g_fused[i] = g0*g_outc[i] + g1*g_outs[i] + g2*g_outw[i];
}

// ---------------- launch ----------------
extern "C" void kernel_launch(void* const* d_in, const int* in_sizes, int n_in,
                              void* d_out, int out_size){
    const float* feats  = (const float*)d_in[0];
    const int*   coords = (const int*)  d_in[1];
    const float* Wq  = (const float*)d_in[2];
    const float* Wk  = (const float*)d_in[3];
    const float* Wv  = (const float*)d_in[4];
    const float* Wo  = (const float*)d_in[5];
    const float* Wck = (const float*)d_in[6];
    const float* Wcv = (const float*)d_in[7];
    const float* pe  = (const float*)d_in[8];
    const float* Wg  = (const float*)d_in[9];
    float* out = (float*)d_out;

    float *gq, *gkf, *gvf, *gkavg, *gvavg, *gck, *gcv, *gfused;
    cudaGetSymbolAddress((void**)&gq,    g_q);
    cudaGetSymbolAddress((void**)&gkf,   g_kf);
    cudaGetSymbolAddress((void**)&gvf,   g_vf);
    cudaGetSymbolAddress((void**)&gkavg, g_kavg);
    cudaGetSymbolAddress((void**)&gvavg, g_vavg);
    cudaGetSymbolAddress((void**)&gck,   g_ck);
    cudaGetSymbolAddress((void**)&gcv,   g_cv);
    cudaGetSymbolAddress((void**)&gfused,g_fused);

    zero_k<<<64, 256>>>();
    prep_k<<<8, 256>>>(coords);
    gate_k<<<NTOK, 128>>>(feats, Wg);

    proj_k<<<dim3(HD/64, NTOK/128, 3), 128>>>(feats, Wq, Wk, Wv, gq, gkf, gvf);

    scan1_k<<<1, 128>>>();
    permfill_k<<<8, 256>>>();
    avg_k<<<MB, 256>>>(pe);

    cmp_k<<<dim3(HD/64, MB/128, 2), 128>>>(gkavg, gvavg, Wck, Wcv, gck, gcv);

    scan2_k<<<1, 32>>>();
    slist_k<<<16, 256>>>();

    qk_k<<<dim3(MB/64, NTOK/128, NH), 128>>>();
    smrow_k<<<NTOK, 256>>>();
    pv_k<<<dim3(NTOK/64, NH), 128>>>();
    topk_k<<<NTOK, 512>>>();

    spattn_k<<<dim3(NTOK, 2), 256>>>();

    fuse_k<<<NTOK*HD/256, 256>>>();
    proj_k<<<dim3(HD/64, NTOK/128, 1), 128>>>(gfused, Wo, Wo, Wo, out, out, out);
}

// round 6
// speedup vs baseline: 1.5930x; 1.1492x over previous
#include <cuda_runtime.h>
#include <cuda_bf16.h>

#define NTOK 2048
#define HD   512
#define NH   8
#define DH   64
#define MB   4096
#define SBN  512
#define NWID 729

// ---------------- scratch ----------------
__device__ float g_q[NTOK*HD], g_kf[NTOK*HD], g_vf[NTOK*HD];
__device__ float g_ck[MB*HD], g_cv[MB*HD];
__device__ float g_S[(size_t)NH*NTOK*MB];
__device__ float g_P8[(size_t)NTOK*MB];
__device__ float g_invl[NH*NTOK];
__device__ unsigned g_rowmaxk[NH*NTOK];
__device__ float g_outc[NTOK*HD], g_outs[NTOK*HD], g_outw[NTOK*HD];
__device__ float g_gate[NTOK*3];
__device__ int g_cnt[MB], g_boff[MB+1], g_bperm[NTOK], g_bid[NTOK];
__device__ int g_sbcnt[SBN], g_sboff[SBN+1], g_sbperm[NTOK], g_sbid[NTOK];
__device__ int g_wcnt[NWID], g_woff[NWID+1], g_wperm[NTOK], g_wid[NTOK];
__device__ int g_scount[SBN], g_soff[SBN+1], g_slist[MB], g_sidc[MB];
__device__ int g_vlist[MB], g_nvalid;
__device__ int g_pei[NTOK], g_packed[NTOK], g_top8[NTOK*8];
// split-bf16 operands
__device__ __nv_bfloat16 g_wth[6*HD*HD], g_wtl[6*HD*HD];
__device__ __nv_bfloat16 g_fh[NTOK*HD], g_fl[NTOK*HD];      // feats, later fused
__device__ __nv_bfloat16 g_qh[NTOK*HD], g_ql[NTOK*HD];
__device__ __nv_bfloat16 g_kah[MB*HD], g_kal[MB*HD], g_vah[MB*HD], g_val[MB*HD];
__device__ __nv_bfloat16 g_ckh[MB*HD], g_ckl[MB*HD];

// ---------------- helpers ----------------
__device__ __forceinline__ unsigned smem_u32(const void* p){
    unsigned a;
    asm("{ .reg .u64 t; cvta.to.shared.u64 t, %1; cvt.u32.u64 %0, t; }" : "=r"(a) : "l"(p));
    return a;
}
__device__ __forceinline__ void sts128(unsigned a, float4 v){
    asm volatile("st.shared.v4.b32 [%0], {%1,%2,%3,%4};" :: "r"(a),
        "r"(__float_as_uint(v.x)), "r"(__float_as_uint(v.y)),
        "r"(__float_as_uint(v.z)), "r"(__float_as_uint(v.w)) : "memory");
}
__device__ __forceinline__ void ldsm4(unsigned* r, unsigned addr){
    asm volatile("ldmatrix.sync.aligned.m8n8.x4.shared.b16 {%0,%1,%2,%3}, [%4];"
        : "=r"(r[0]), "=r"(r[1]), "=r"(r[2]), "=r"(r[3]) : "r"(addr));
}
__device__ __forceinline__ void mma16816(float* c, const unsigned* a, const unsigned* b){
    asm volatile("mma.sync.aligned.m16n8k16.row.col.f32.bf16.bf16.f32 "
        "{%0,%1,%2,%3}, {%4,%5,%6,%7}, {%8,%9}, {%0,%1,%2,%3};"
        : "+f"(c[0]), "+f"(c[1]), "+f"(c[2]), "+f"(c[3])
        : "r"(a[0]), "r"(a[1]), "r"(a[2]), "r"(a[3]), "r"(b[0]), "r"(b[1]));
}
__device__ __forceinline__ void ffma2(float2& d, float2 a, float2 b){
    asm("fma.rn.f32x2 %0, %1, %2, %0;"
        : "+l"(reinterpret_cast<unsigned long long&>(d))
        : "l"(reinterpret_cast<unsigned long long&>(a)),
          "l"(reinterpret_cast<unsigned long long&>(b)));
}
__device__ __forceinline__ float fexp(float x){
    x = fminf(fmaxf(x, -87.0f), 88.0f);
    float y = x * 1.4426950408889634f;
    float z = y + 12582912.0f;
    int ki = __float_as_int(z) - 0x4B400000;
    float f = y - (z - 12582912.0f);
    float p = 1.5403530393381609e-4f;
    p = fmaf(p, f, 1.3333558146428443e-3f);
    p = fmaf(p, f, 9.6181291076284772e-3f);
    p = fmaf(p, f, 5.5504108664821580e-2f);
    p = fmaf(p, f, 2.4022650695910071e-1f);
    p = fmaf(p, f, 6.9314718055994531e-1f);
    p = fmaf(p, f, 1.0f);
    return __int_as_float((ki + 127) << 23) * p;
}
__device__ __forceinline__ unsigned fenc(float f){
    unsigned u = __float_as_uint(f);
    return (u & 0x80000000u) ? ~u : (u | 0x80000000u);
}
__device__ __forceinline__ float fdec(unsigned k){
    return (k & 0x80000000u) ? __uint_as_float(k ^ 0x80000000u) : __uint_as_float(~k);
}

// ---------------- setup ----------------
__global__ void zero_k(){
    int i = blockIdx.x*256 + threadIdx.x;
    if (i < MB)   g_cnt[i] = 0;
    if (i < SBN){ g_sbcnt[i] = 0; g_scount[i] = 0; }
    if (i < NWID) g_wcnt[i] = 0;
    if (i < NH*NTOK) g_rowmaxk[i] = 0u;
}
__global__ void prep_k(const int* __restrict__ coords){
    int t = blockIdx.x*256 + threadIdx.x;
    if (t >= NTOK) return;
    int cf = coords[t];
    int x = cf >> 12, y = (cf >> 6) & 63, z = cf & 63;
    int bid = ((x>>2)<<8) | ((y>>2)<<4) | (z>>2);
    g_bid[t] = bid; atomicAdd(&g_cnt[bid], 1);
    int sb = ((x>>3)<<6) | ((y>>3)<<3) | (z>>3);
    g_sbid[t] = sb; atomicAdd(&g_sbcnt[sb], 1);
    int wd = (((x+4)>>3)*9 + ((y+4)>>3))*9 + ((z+4)>>3);
    g_wid[t] = wd; atomicAdd(&g_wcnt[wd], 1);
    g_pei[t] = (((x&3)*4 + (y&3))*4 + (z&3)) * HD;
    g_packed[t] = bid | (sb << 12) | (wd << 21);
}
__global__ void gate_k(const float* __restrict__ feats, const float* __restrict__ Wg){
    int n = blockIdx.x;
    int w = threadIdx.x >> 5, lane = threadIdx.x & 31;
    if (w >= 3) return;
    float s = 0.f;
    for (int i = lane; i < HD; i += 32) s += feats[n*HD + i] * Wg[i*3 + w];
    #pragma unroll
    for (int o = 16; o; o >>= 1) s += __shfl_xor_sync(0xffffffffu, s, o);
    if (lane == 0) g_gate[n*3 + w] = 1.0f / (1.0f + fexp(-s));
}
__device__ __forceinline__ void warp_exscan(const int* cnt, int* off, int len){
    int lane = threadIdx.x & 31;
    int run = 0;
    for (int base = 0; base < len; base += 32){
        int raw = (base+lane < len) ? cnt[base+lane] : 0;
        int v = raw;
        #pragma unroll
        for (int o = 1; o < 32; o <<= 1){ int t = __shfl_up_sync(0xffffffffu, v, o); if (lane >= o) v += t; }
        if (base+lane < len) off[base+lane] = run + v - raw;
        run += __shfl_sync(0xffffffffu, v, 31);
    }
    if (lane == 0) off[len] = run;
}
__global__ void scan1_k(){
    int w = threadIdx.x >> 5;
    if (w == 0) warp_exscan(g_cnt, g_boff, MB);
    else if (w == 1) warp_exscan(g_sbcnt, g_sboff, SBN);
    else if (w == 2) warp_exscan(g_wcnt, g_woff, NWID);
    else {
        int lane = threadIdx.x & 31;
        int run = 0;
        for (int base = 0; base < MB; base += 32){
            int valid = g_cnt[base+lane] > 0 ? 1 : 0;
            int v = valid;
            #pragma unroll
            for (int o = 1; o < 32; o <<= 1){ int t = __shfl_up_sync(0xffffffffu, v, o); if (lane >= o) v += t; }
            if (valid) g_vlist[run + v - 1] = base + lane;
            run += __shfl_sync(0xffffffffu, v, 31);
        }
        if (lane == 0) g_nvalid = run;
    }
}
__global__ void scan2_k(){ warp_exscan(g_scount, g_soff, SBN); }
__global__ void permfill_k(){
    __shared__ int sp[256];
    int t = blockIdx.x*256 + threadIdx.x;
    int my = g_packed[t];
    int r1 = 0, r2 = 0, r3 = 0;
    for (int base = 0; base < NTOK; base += 256){
        sp[threadIdx.x] = g_packed[base + threadIdx.x];
        __syncthreads();
        int lim = t - base; if (lim > 256) lim = 256;
        for (int u = 0; u < lim; u++){
            int p = sp[u] ^ my;
            r3 += ((p & 0x00000FFF) == 0);
            r1 += ((p & 0x001FF000) == 0);
            r2 += ((p & 0x7FE00000) == 0);
        }
        __syncthreads();
    }
    int bd = my & 0xFFF, sb = (my >> 12) & 0x1FF, wd = (my >> 21) & 0x3FF;
    g_sbperm[g_sboff[sb] + r1] = t;
    g_wperm [g_woff[wd]  + r2] = t;
    g_bperm [g_boff[bd]  + r3] = t;
}
__global__ void slist_k(){
    int j = blockIdx.x*256 + threadIdx.x;
    if (j >= g_nvalid) return;
    int s = g_sidc[j];
    int r = 0;
    for (int u = 0; u < j; u++) r += (g_sidc[u] == s);
    g_slist[g_soff[s] + r] = j;
}
__global__ void avg_k(const float* __restrict__ pe){
    int j = blockIdx.x;
    int nv = g_nvalid;
    if (j >= nv){
        __nv_bfloat16 zb = __float2bfloat16(0.f);
        for (int c = threadIdx.x; c < HD; c += 256){
            g_kah[j*HD+c]=zb; g_kal[j*HD+c]=zb; g_vah[j*HD+c]=zb; g_val[j*HD+c]=zb;
        }
        return;
    }
    int m = g_vlist[j];
    int c0 = g_boff[m], c1 = g_boff[m+1];
    float dn = 1.0f / (float)max(c1 - c0, 1);
    for (int c = threadIdx.x; c < HD; c += 256){
        float sk = 0.f, sv = 0.f;
        for (int i = c0; i < c1; i++){
            int t = g_bperm[i];
            sk += g_kf[t*HD + c] + pe[g_pei[t] + c];
            sv += g_vf[t*HD + c];
        }
        sk *= dn; sv *= dn;
        __nv_bfloat16 kh = __float2bfloat16(sk);
        __nv_bfloat16 vh = __float2bfloat16(sv);
        g_kah[j*HD+c] = kh; g_kal[j*HD+c] = __float2bfloat16(sk - __bfloat162float(kh));
        g_vah[j*HD+c] = vh; g_val[j*HD+c] = __float2bfloat16(sv - __bfloat162float(vh));
    }
    if (threadIdx.x == 0){
        int mx = m >> 8, my = (m >> 4) & 15, mz = m & 15;
        g_sidc[j] = ((mx>>1)<<6) | ((my>>1)<<3) | (mz>>1);
        atomicAdd(&g_scount[g_sidc[j]], 1);
    }
}
__global__ void convA_k(const float* __restrict__ in, __nv_bfloat16* __restrict__ h, __nv_bfloat16* __restrict__ l){
    int i = blockIdx.x*256 + threadIdx.x;
    float x = in[i];
    __nv_bfloat16 hb = __float2bfloat16(x);
    h[i] = hb; l[i] = __float2bfloat16(x - __bfloat162float(hb));
}
__global__ void convW_k(const float* W0, const float* W1, const float* W2,
                        const float* W3, const float* W4, const float* W5){
    int z = blockIdx.z;
    const float* W = z==0?W0 : z==1?W1 : z==2?W2 : z==3?W3 : z==4?W4 : W5;
    __nv_bfloat16* h = g_wth + (size_t)z*HD*HD;
    __nv_bfloat16* l = g_wtl + (size_t)z*HD*HD;
    __shared__ float t[32][33];
    int bn = blockIdx.x*32, bk = blockIdx.y*32;
    int tx = threadIdx.x & 31, ty = threadIdx.x >> 5;
    for (int r = ty; r < 32; r += 8) t[r][tx] = W[(size_t)(bk+r)*HD + bn + tx];
    __syncthreads();
    for (int r = ty; r < 32; r += 8){
        float x = t[tx][r];
        __nv_bfloat16 hb = __float2bfloat16(x);
        h[(size_t)(bn+r)*HD + bk + tx] = hb;
        l[(size_t)(bn+r)*HD + bk + tx] = __float2bfloat16(x - __bfloat162float(hb));
    }
}

// ---------------- mma.sync stage compute: 8 warps, CTA tile 128x128 ----------------
#define KSTR 24                 // smem row stride (bf16)
#define ARR  6144               // bytes per operand array (128*24*2)
#define STG  24576              // bytes per stage (4 arrays)

__device__ __forceinline__ void mma_stage(unsigned base, int wm, int wn, int lane, float acc[4][4][4]){
    unsigned ah[4][4], al[4][4], bh[4][2], bl[4][2];
    int t7 = lane & 7, t8 = lane >> 3;
    #pragma unroll
    for (int mt = 0; mt < 4; mt++){
        int m = wm*64 + mt*16 + (t8&1)*8 + t7;
        unsigned off = base + (m*KSTR + (t8>>1)*8)*2;
        ldsm4(ah[mt], off);
        ldsm4(al[mt], off + ARR);
    }
    #pragma unroll
    for (int p = 0; p < 2; p++){
        int n = wn*32 + p*16 + (t8>>1)*8 + t7;
        unsigned off = base + 2*ARR + (n*KSTR + (t8&1)*8)*2;
        unsigned r[4];
        ldsm4(r, off);
        bh[2*p][0]=r[0]; bh[2*p][1]=r[1]; bh[2*p+1][0]=r[2]; bh[2*p+1][1]=r[3];
        ldsm4(r, off + ARR);
        bl[2*p][0]=r[0]; bl[2*p][1]=r[1]; bl[2*p+1][0]=r[2]; bl[2*p+1][1]=r[3];
    }
    #pragma unroll
    for (int mt = 0; mt < 4; mt++)
        #pragma unroll
        for (int nt = 0; nt < 4; nt++){
            mma16816(acc[mt][nt], ah[mt], bh[nt]);
            mma16816(acc[mt][nt], ah[mt], bl[nt]);
            mma16816(acc[mt][nt], al[mt], bh[nt]);
        }
}

// ---------------- GEMM C[·,512] x W^T -> C[128,128] tiles ----------------
__global__ void __launch_bounds__(256) mm_k(
    const __nv_bfloat16* __restrict__ Ah0, const __nv_bfloat16* __restrict__ Al0,
    const __nv_bfloat16* __restrict__ Ah1, const __nv_bfloat16* __restrict__ Al1,
    int wbase, float* C0, float* C1, float* C2,
    __nv_bfloat16* Hh, __nv_bfloat16* Hl, int hz0, int guard)
{
    extern __shared__ char smem[];
    int z = blockIdx.z;
    const __nv_bfloat16* Ah = (z==1) ? Ah1 : Ah0;
    const __nv_bfloat16* Al = (z==1) ? Al1 : Al0;
    const __nv_bfloat16* Bh = g_wth + (size_t)(wbase+z)*HD*HD;
    const __nv_bfloat16* Bl = g_wtl + (size_t)(wbase+z)*HD*HD;
    float* C = (z==0) ? C0 : ((z==1) ? C1 : C2);
    int tbm = blockIdx.y*128, tbn = blockIdx.x*128;
    if (guard && tbm >= g_nvalid) return;
    unsigned s0 = smem_u32(smem);
    int tid = threadIdx.x, lane = tid & 31, warp = tid >> 5;
    int wm = warp & 1, wn = warp >> 1;
    int row = tid >> 1, half = tid & 1;
    size_t aoff = (size_t)(tbm+row)*HD + half*8;
    size_t boff = (size_t)(tbn+row)*HD + half*8;
    unsigned sdst = (row*KSTR + half*8)*2;

    float acc[4][4][4];
    #pragma unroll
    for (int i = 0; i < 4; i++)
        #pragma unroll
        for (int j2 = 0; j2 < 4; j2++){ acc[i][j2][0]=0.f; acc[i][j2][1]=0.f; acc[i][j2][2]=0.f; acc[i][j2][3]=0.f; }

    float4 pa = *(const float4*)&Ah[aoff];
    float4 pl = *(const float4*)&Al[aoff];
    float4 pb = *(const float4*)&Bh[boff];
    float4 pq = *(const float4*)&Bl[boff];
    { unsigned b = s0 + sdst; sts128(b, pa); sts128(b+ARR, pl); sts128(b+2*ARR, pb); sts128(b+3*ARR, pq); }
    __syncthreads();
    for (int it = 1; it <= 32; it++){
        if (it < 32){
            pa = *(const float4*)&Ah[aoff + it*16];
            pl = *(const float4*)&Al[aoff + it*16];
            pb = *(const float4*)&Bh[boff + it*16];
            pq = *(const float4*)&Bl[boff + it*16];
        }
        mma_stage(s0 + ((it-1)&1)*STG, wm, wn, lane, acc);
        if (it < 32){
            unsigned b = s0 + (it&1)*STG + sdst;
            sts128(b, pa); sts128(b+ARR, pl); sts128(b+2*ARR, pb); sts128(b+3*ARR, pq);
            __syncthreads();
        }
    }
    #pragma unroll
    for (int mt = 0; mt < 4; mt++){
        int m0 = tbm + wm*64 + mt*16 + (lane>>2);
        #pragma unroll
        for (int nt = 0; nt < 4; nt++){
            int n = tbn + wn*32 + nt*8 + (lane&3)*2;
            float* c = acc[mt][nt];
            size_t i0 = (size_t)m0*HD + n, i1 = (size_t)(m0+8)*HD + n;
            *(float2*)&C[i0] = make_float2(c[0], c[1]);
            *(float2*)&C[i1] = make_float2(c[2], c[3]);
            if (hz0 && z == 0){
                __nv_bfloat16 h0 = __float2bfloat16(c[0]), h1 = __float2bfloat16(c[1]);
                __nv_bfloat16 h2 = __float2bfloat16(c[2]), h3 = __float2bfloat16(c[3]);
                *(__nv_bfloat162*)&Hh[i0] = __nv_bfloat162(h0, h1);
                *(__nv_bfloat162*)&Hh[i1] = __nv_bfloat162(h2, h3);
                *(__nv_bfloat162*)&Hl[i0] = __nv_bfloat162(
                    __float2bfloat16(c[0]-__bfloat162float(h0)), __float2bfloat16(c[1]-__bfloat162float(h1)));
                *(__nv_bfloat162*)&Hl[i1] = __nv_bfloat162(
                    __float2bfloat16(c[2]-__bfloat162float(h2)), __float2bfloat16(c[3]-__bfloat162float(h3)));
            }
        }
    }
}

// ---------------- QK^T: S[128q x 128j] per head, K=64 ----------------
__global__ void __launch_bounds__(256) qkmm_k(){
    extern __shared__ char smem[];
    int h = blockIdx.z, nt0 = blockIdx.y*128, jt = blockIdx.x*128;
    int nv = g_nvalid;
    if (jt >= nv) return;
    unsigned s0 = smem_u32(smem);
    int tid = threadIdx.x, lane = tid & 31, warp = tid >> 5;
    int wm = warp & 1, wn = warp >> 1;
    int row = tid >> 1, half = tid & 1;
    size_t aoff = (size_t)(nt0+row)*HD + h*DH + half*8;
    size_t boff = (size_t)(jt+row)*HD + h*DH + half*8;
    unsigned sdst = (row*KSTR + half*8)*2;

    float acc[4][4][4];
    #pragma unroll
    for (int i = 0; i < 4; i++)
        #pragma unroll
        for (int j2 = 0; j2 < 4; j2++){ acc[i][j2][0]=0.f; acc[i][j2][1]=0.f; acc[i][j2][2]=0.f; acc[i][j2][3]=0.f; }

    float4 pa = *(const float4*)&g_qh [aoff];
    float4 pl = *(const float4*)&g_ql [aoff];
    float4 pb = *(const float4*)&g_ckh[boff];
    float4 pq = *(const float4*)&g_ckl[boff];
    { unsigned b = s0 + sdst; sts128(b, pa); sts128(b+ARR, pl); sts128(b+2*ARR, pb); sts128(b+3*ARR, pq); }
    __syncthreads();
    #pragma unroll
    for (int it = 1; it <= 4; it++){
        if (it < 4){
            pa = *(const float4*)&g_qh [aoff + it*16];
            pl = *(const float4*)&g_ql [aoff + it*16];
            pb = *(const float4*)&g_ckh[boff + it*16];
            pq = *(const float4*)&g_ckl[boff + it*16];
        }
        mma_stage(s0 + ((it-1)&1)*STG, wm, wn, lane, acc);
        if (it < 4){
            unsigned b = s0 + (it&1)*STG + sdst;
            sts128(b, pa); sts128(b+ARR, pl); sts128(b+2*ARR, pb); sts128(b+3*ARR, pq);
            __syncthreads();
        }
    }
    #pragma unroll
    for (int mt = 0; mt < 4; mt++){
        int m = nt0 + wm*64 + mt*16 + (lane>>2);
        float mx0 = -3.0e38f, mx1 = -3.0e38f;
        #pragma unroll
        for (int nt = 0; nt < 4; nt++){
            int j = jt + wn*32 + nt*8 + (lane&3)*2;
            float* c = acc[mt][nt];
            float v0 = c[0]*0.125f, v1 = c[1]*0.125f, v2 = c[2]*0.125f, v3 = c[3]*0.125f;
            *(float2*)&g_S[(size_t)(h*NTOK + m  )*MB + j] = make_float2(v0, v1);
            *(float2*)&g_S[(size_t)(h*NTOK + m+8)*MB + j] = make_float2(v2, v3);
            if (j   < nv){ mx0 = fmaxf(mx0, v0); mx1 = fmaxf(mx1, v2); }
            if (j+1 < nv){ mx0 = fmaxf(mx0, v1); mx1 = fmaxf(mx1, v3); }
        }
        mx0 = fmaxf(mx0, __shfl_xor_sync(0xffffffffu, mx0, 1));
        mx0 = fmaxf(mx0, __shfl_xor_sync(0xffffffffu, mx0, 2));
        mx1 = fmaxf(mx1, __shfl_xor_sync(0xffffffffu, mx1, 1));
        mx1 = fmaxf(mx1, __shfl_xor_sync(0xffffffffu, mx1, 2));
        if ((lane & 3) == 0){
            atomicMax(&g_rowmaxk[h*NTOK + m],     fenc(mx0));
            atomicMax(&g_rowmaxk[h*NTOK + m + 8], fenc(mx1));
        }
    }
}

// ---------------- fused softmax + head-pooled probs ----------------
__global__ __launch_bounds__(256) void smrow_k(){
    int n = blockIdx.x, tid = threadIdx.x;
    int nv = g_nvalid;
    __shared__ float red[8];
    __shared__ float binv;
    float p8a[16];
    #pragma unroll
    for (int q = 0; q < 16; q++) p8a[q] = 0.f;
    for (int h = 0; h < NH; h++){
        float* row = g_S + ((size_t)(h*NTOK + n))*MB;
        float bm = fdec(g_rowmaxk[h*NTOK + n]);
        float ec[16];
        float l = 0.f;
        #pragma unroll
        for (int q = 0; q < 16; q++){
            int j = tid + q*256;
            float e = 0.f;
            if (j < nv){ e = fexp(row[j] - bm); row[j] = e; l += e; }
            ec[q] = e;
        }
        #pragma unroll
        for (int o = 16; o; o >>= 1) l += __shfl_xor_sync(0xffffffffu, l, o);
        if ((tid & 31) == 0) red[tid >> 5] = l;
        __syncthreads();
        if (tid == 0){
            float s = 0.f;
            #pragma unroll
            for (int w = 0; w < 8; w++) s += red[w];
            float iv = 1.0f / s;
            binv = iv;
            g_invl[h*NTOK + n] = iv;
        }
        __syncthreads();
        float il = binv;
        #pragma unroll
        for (int q = 0; q < 16; q++) p8a[q] += ec[q] * il;
        __syncthreads();
    }
    #pragma unroll
    for (int q = 0; q < 16; q++){
        int j = tid + q*256;
        if (j < nv) g_P8[(size_t)n*MB + j] = p8a[q];
    }
}

// ---------------- P @ V (fp32 pipelined 64x64) ----------------
__global__ __launch_bounds__(128) void pv_k(){
    int nt = blockIdx.x*64, h = blockIdx.y;
    int nv = g_nvalid;
    int nk = ((nv + 15) & ~15) / 16;
    __shared__ float Ps[2][16][68];
    __shared__ float Vs[2][16][68];
    int tid = threadIdx.x, ty = tid >> 3, tx = tid & 7;
    float2 acc[4][4];
    #pragma unroll
    for (int i = 0; i < 4; i++){ acc[i][0]={0,0}; acc[i][1]={0,0}; acc[i][2]={0,0}; acc[i][3]={0,0}; }
    const float* Sb = g_S + (size_t)(h*NTOK + nt)*MB;
    const float* Vb = g_cv + h*DH;
    float4 ar[2], br[2];
    #pragma unroll
    for (int q = 0; q < 2; q++){ int f = tid+128*q; ar[q] = *(const float4*)&Sb[(size_t)(f>>2)*MB + (f&3)*4]; }
    #pragma unroll
    for (int q = 0; q < 2; q++){ int f = tid+128*q; br[q] = *(const float4*)&Vb[(size_t)(f>>4)*HD + (f&15)*4]; }
    #pragma unroll
    for (int q = 0; q < 2; q++){ int f = tid+128*q; int r=f>>2, c4=f&3;
        Ps[0][c4*4+0][r]=ar[q].x; Ps[0][c4*4+1][r]=ar[q].y; Ps[0][c4*4+2][r]=ar[q].z; Ps[0][c4*4+3][r]=ar[q].w; }
    #pragma unroll
    for (int q = 0; q < 2; q++){ int f = tid+128*q; *(float4*)&Vs[0][f>>4][(f&15)*4] = br[q]; }
    __syncthreads();
    for (int it = 1; it <= nk; it++){
        if (it < nk){
            int k0 = it*16;
            #pragma unroll
            for (int q = 0; q < 2; q++){ int f = tid+128*q; ar[q] = *(const float4*)&Sb[(size_t)(f>>2)*MB + k0 + (f&3)*4]; }
            #pragma unroll
            for (int q = 0; q < 2; q++){ int f = tid+128*q; br[q] = *(const float4*)&Vb[(size_t)(k0+(f>>4))*HD + (f&15)*4]; }
        }
        const float (*Pb)[68] = Ps[(it-1)&1];
        const float (*Vv)[68] = Vs[(it-1)&1];
        #pragma unroll
        for (int k = 0; k < 16; k++){
            float4 a0 = *(const float4*)&Pb[k][ty*4];
            float4 b0 = *(const float4*)&Vv[k][tx*4];
            float4 b1 = *(const float4*)&Vv[k][32+tx*4];
            float2 bb0 = {b0.x,b0.y}, bb1 = {b0.z,b0.w}, bb2 = {b1.x,b1.y}, bb3 = {b1.z,b1.w};
            float av[4] = {a0.x,a0.y,a0.z,a0.w};
            #pragma unroll
            for (int i = 0; i < 4; i++){
                float2 ap = {av[i], av[i]};
                ffma2(acc[i][0], ap, bb0);
                ffma2(acc[i][1], ap, bb1);
                ffma2(acc[i][2], ap, bb2);
                ffma2(acc[i][3], ap, bb3);
            }
        }
        if (it < nk){
            int nb = it & 1;
            #pragma unroll
            for (int q = 0; q < 2; q++){ int f = tid+128*q; int r=f>>2, c4=f&3;
                Ps[nb][c4*4+0][r]=ar[q].x; Ps[nb][c4*4+1][r]=ar[q].y; Ps[nb][c4*4+2][r]=ar[q].z; Ps[nb][c4*4+3][r]=ar[q].w; }
            #pragma unroll
            for (int q = 0; q < 2; q++){ int f = tid+128*q; *(float4*)&Vs[nb][f>>4][(f&15)*4] = br[q]; }
            __syncthreads();
        }
    }
    #pragma unroll
    for (int i = 0; i < 4; i++){
        int rw = nt + ty*4 + i;
        float il = g_invl[h*NTOK + rw];
        *(float4*)&g_outc[(size_t)rw*HD + h*DH + tx*4]      = make_float4(acc[i][0].x*il, acc[i][0].y*il, acc[i][1].x*il, acc[i][1].y*il);
        *(float4*)&g_outc[(size_t)rw*HD + h*DH + 32 + tx*4] = make_float4(acc[i][2].x*il, acc[i][2].y*il, acc[i][3].x*il, acc[i][3].y*il);
    }
}

// ---------------- sel_score + top-8 ----------------
__global__ void topk_k(){
    int n = blockIdx.x, tid = threadIdx.x;
    int lane = tid & 31, w = tid >> 5;
    __shared__ float ss[SBN];
    __shared__ float wv[16];
    __shared__ int   wi[16];
    float v = 0.f;
    int o0 = g_soff[tid], o1 = g_soff[tid+1];
    for (int i = o0; i < o1; i++) v += g_P8[(size_t)n*MB + g_slist[i]];
    ss[tid] = v;
    __syncthreads();
    for (int r = 0; r < 8; r++){
        float mv = ss[tid]; int mi = tid;
        #pragma unroll
        for (int o = 16; o; o >>= 1){
            float ov = __shfl_xor_sync(0xffffffffu, mv, o);
            int   oi = __shfl_xor_sync(0xffffffffu, mi, o);
            if (ov > mv || (ov == mv && oi < mi)){ mv = ov; mi = oi; }
        }
        if (lane == 0){ wv[w] = mv; wi[w] = mi; }
        __syncthreads();
        if (tid < 16){
            float m2 = wv[tid]; int i2 = wi[tid];
            #pragma unroll
            for (int o = 8; o; o >>= 1){
                float ov = __shfl_xor_sync(0x0000ffffu, m2, o);
                int   oi = __shfl_xor_sync(0x0000ffffu, i2, o);
                if (ov > m2 || (ov == m2 && oi < i2)){ m2 = ov; i2 = oi; }
            }
            if (tid == 0){ g_top8[n*8 + r] = i2; ss[i2] = -1e30f; }
        }
        __syncthreads();
    }
}

// ---------------- selection / window attention ----------------
__global__ void spattn_k(){
    int n = blockIdx.x, mode = blockIdx.y;
    int h = threadIdx.x >> 5, lane = threadIdx.x & 31;
    const float* qr = &g_q[n*HD + h*DH];
    float q0 = qr[lane], q1 = qr[lane + 32];
    float m = -1e30f, l = 0.f, a0 = 0.f, a1 = 0.f;
    int nb = (mode == 0) ? 8 : 1;
    for (int kk = 0; kk < nb; kk++){
        int b, o, e;
        if (mode == 0){ b = g_top8[n*8 + kk]; o = g_sboff[b]; e = g_sboff[b+1]; }
        else          { b = g_wid[n];         o = g_woff[b];  e = g_woff[b+1]; }
        for (int i = o; i < e; i++){
            int t = (mode == 0) ? g_sbperm[i] : g_wperm[i];
            const float* kr = &g_kf[t*HD + h*DH];
            float s = q0*kr[lane] + q1*kr[lane + 32];
            #pragma unroll
            for (int of = 16; of; of >>= 1) s += __shfl_xor_sync(0xffffffffu, s, of);
            s *= 0.125f;
            float mn = fmaxf(m, s);
            float c = fexp(m - mn), ww = fexp(s - mn);
            const float* vr = &g_vf[t*HD + h*DH];
            l  = l*c  + ww;
            a0 = a0*c + ww*vr[lane];
            a1 = a1*c + ww*vr[lane + 32];
            m = mn;
        }
    }
    float* outp = mode ? g_outw : g_outs;
    outp[n*HD + h*DH + lane]      = a0 / l;
    outp[n*HD + h*DH + lane + 32] = a1 / l;
}

// ---------------- gated fuse -> split bf16 (input to Wo GEMM) ----------------
__global__ void fuse_k(){
    int i = blockIdx.x*256 + threadIdx.x;
    int n = i >> 9;
    float g0 = g_gate[n*3+0], g1 = g_gate[n*3+1], g2 = g_gate[n*3+2];
    float v = g0*g_outc[i] + g1*g_outs[i] + g2*g_outw[i];
    __nv_bfloat16 hb = __float2bfloat16(v);
    g_fh[i] = hb;
    g_fl[i] = __float2bfloat16(v - __bfloat162float(hb));
}

// ---------------- launch ----------------
extern "C" void kernel_launch(void* const* d_in, const int* in_sizes, int n_in,
                              void* d_out, int out_size){
    const float* feats  = (const float*)d_in[0];
    const int*   coords = (const int*)  d_in[1];
    const float* Wq  = (const float*)d_in[2];
    const float* Wk  = (const float*)d_in[3];
    const float* Wv  = (const float*)d_in[4];
    const float* Wo  = (const float*)d_in[5];
    const float* Wck = (const float*)d_in[6];
    const float* Wcv = (const float*)d_in[7];
    const float* pe  = (const float*)d_in[8];
    const float* Wg  = (const float*)d_in[9];
    float* out = (float*)d_out;

    float *gq, *gkf, *gvf, *gck, *gcv;
    __nv_bfloat16 *fh, *fl, *qh, *ql, *kah, *kal, *vah, *val, *ckh, *ckl;
    cudaGetSymbolAddress((void**)&gq,  g_q);
    cudaGetSymbolAddress((void**)&gkf, g_kf);
    cudaGetSymbolAddress((void**)&gvf, g_vf);
    cudaGetSymbolAddress((void**)&gck, g_ck);
    cudaGetSymbolAddress((void**)&gcv, g_cv);
    cudaGetSymbolAddress((void**)&fh,  g_fh);
    cudaGetSymbolAddress((void**)&fl,  g_fl);
    cudaGetSymbolAddress((void**)&qh,  g_qh);
    cudaGetSymbolAddress((void**)&ql,  g_ql);
    cudaGetSymbolAddress((void**)&kah, g_kah);
    cudaGetSymbolAddress((void**)&kal, g_kal);
    cudaGetSymbolAddress((void**)&vah, g_vah);
    cudaGetSymbolAddress((void**)&val, g_val);
    cudaGetSymbolAddress((void**)&ckh, g_ckh);
    cudaGetSymbolAddress((void**)&ckl, g_ckl);

    cudaFuncSetAttribute(mm_k,   cudaFuncAttributeMaxDynamicSharedMemorySize, 2*STG);
    cudaFuncSetAttribute(qkmm_k, cudaFuncAttributeMaxDynamicSharedMemorySize, 2*STG);

    zero_k<<<64, 256>>>();
    prep_k<<<8, 256>>>(coords);
    gate_k<<<NTOK, 128>>>(feats, Wg);
    convW_k<<<dim3(16, 16, 6), 256>>>(Wq, Wk, Wv, Wck, Wcv, Wo);
    convA_k<<<NTOK*HD/256, 256>>>(feats, fh, fl);

    // Q/K/V projection (q also emitted as split-bf16 for qk)
    mm_k<<<dim3(4, NTOK/128, 3), 256, 2*STG>>>(fh, fl, fh, fl, 0, gq, gkf, gvf, qh, ql, 1, 0);

    scan1_k<<<1, 128>>>();
    permfill_k<<<8, 256>>>();
    avg_k<<<MB, 256>>>(pe);

    // Wck/Wcv (ck emitted as split-bf16 for qk)
    mm_k<<<dim3(4, MB/128, 2), 256, 2*STG>>>(kah, kal, vah, val, 3, gck, gcv, gcv, ckh, ckl, 1, 1);

    scan2_k<<<1, 32>>>();
    slist_k<<<16, 256>>>();

    qkmm_k<<<dim3(MB/128, NTOK/128, NH), 256, 2*STG>>>();
    smrow_k<<<NTOK, 256>>>();
    pv_k<<<dim3(NTOK/64, NH), 128>>>();
    topk_k<<<NTOK, 512>>>();
    spattn_k<<<dim3(NTOK, 2), 256>>>();
    fuse_k<<<NTOK*HD/256, 256>>>();

    // output projection
    mm_k<<<dim3(4, NTOK/128, 1), 256, 2*STG>>>(fh, fl, fh, fl, 5, out, out, out, qh, ql, 0, 0);
}

// round 10
// speedup vs baseline: 1.8138x; 1.1386x over previous
#include <cuda_runtime.h>
#include <cuda_bf16.h>

#define NTOK 2048
#define HD   512
#define NH   8
#define DH   64
#define MB   4096
#define SBN  512
#define NWID 729
#define PVPL 5120   // byte stride between pv smem planes (64*40*2)

// ---------------- scratch ----------------
__device__ float g_q[NTOK*HD], g_kf[NTOK*HD], g_vf[NTOK*HD];
__device__ float g_ck[MB*HD], g_cv[MB*HD];
__device__ float g_S[(size_t)NH*NTOK*MB];
__device__ float g_P8[(size_t)NTOK*MB];
__device__ float g_invl[NH*NTOK];
__device__ unsigned g_rowmaxk[NH*NTOK];
__device__ float g_outc[NTOK*HD], g_outs[NTOK*HD], g_outw[NTOK*HD];
__device__ float g_gate[NTOK*3];
__device__ int g_cnt[MB], g_boff[MB+1], g_bperm[NTOK], g_bid[NTOK];
__device__ int g_sbcnt[SBN], g_sboff[SBN+1], g_sbperm[NTOK], g_sbid[NTOK];
__device__ int g_wcnt[NWID], g_woff[NWID+1], g_wperm[NTOK], g_wid[NTOK];
__device__ int g_scount[SBN], g_soff[SBN+1], g_slist[MB], g_sidc[MB];
__device__ int g_vlist[MB], g_nvalid;
__device__ int g_pei[NTOK], g_packed[NTOK], g_top8[NTOK*8];
__device__ int g_r1[NTOK], g_r2[NTOK], g_r3[NTOK], g_rs[MB];
// split-bf16 operands
__device__ __nv_bfloat16 g_wth[6*HD*HD], g_wtl[6*HD*HD];
__device__ __nv_bfloat16 g_fh[NTOK*HD], g_fl[NTOK*HD];
__device__ __nv_bfloat16 g_qh[NTOK*HD], g_ql[NTOK*HD];
__device__ __nv_bfloat16 g_kah[MB*HD], g_kal[MB*HD], g_vah[MB*HD], g_val[MB*HD];
__device__ __nv_bfloat16 g_ckh[MB*HD], g_ckl[MB*HD];
// transposed cv planes [h][d][j] (for pv MMA)
__device__ __nv_bfloat16 g_cvth[NH*DH*MB], g_cvtl[NH*DH*MB];

// ---------------- helpers ----------------
__device__ __forceinline__ unsigned smem_u32(const void* p){
    unsigned a;
    asm("{ .reg .u64 t; cvta.to.shared.u64 t, %1; cvt.u32.u64 %0, t; }" : "=r"(a) : "l"(p));
    return a;
}
__device__ __forceinline__ void sts128(unsigned a, float4 v){
    asm volatile("st.shared.v4.b32 [%0], {%1,%2,%3,%4};" :: "r"(a),
        "r"(__float_as_uint(v.x)), "r"(__float_as_uint(v.y)),
        "r"(__float_as_uint(v.z)), "r"(__float_as_uint(v.w)) : "memory");
}
__device__ __forceinline__ void ldsm4(unsigned* r, unsigned addr){
    asm volatile("ldmatrix.sync.aligned.m8n8.x4.shared.b16 {%0,%1,%2,%3}, [%4];"
        : "=r"(r[0]), "=r"(r[1]), "=r"(r[2]), "=r"(r[3]) : "r"(addr));
}
__device__ __forceinline__ void mma16816(float* c, const unsigned* a, const unsigned* b){
    asm volatile("mma.sync.aligned.m16n8k16.row.col.f32.bf16.bf16.f32 "
        "{%0,%1,%2,%3}, {%4,%5,%6,%7}, {%8,%9}, {%0,%1,%2,%3};"
        : "+f"(c[0]), "+f"(c[1]), "+f"(c[2]), "+f"(c[3])
        : "r"(a[0]), "r"(a[1]), "r"(a[2]), "r"(a[3]), "r"(b[0]), "r"(b[1]));
}
__device__ __forceinline__ float fexp(float x){
    x = fminf(fmaxf(x, -87.0f), 88.0f);
    float y = x * 1.4426950408889634f;
    float z = y + 12582912.0f;
    int ki = __float_as_int(z) - 0x4B400000;
    float f = y - (z - 12582912.0f);
    float p = 1.5403530393381609e-4f;
    p = fmaf(p, f, 1.3333558146428443e-3f);
    p = fmaf(p, f, 9.6181291076284772e-3f);
    p = fmaf(p, f, 5.5504108664821580e-2f);
    p = fmaf(p, f, 2.4022650695910071e-1f);
    p = fmaf(p, f, 6.9314718055994531e-1f);
    p = fmaf(p, f, 1.0f);
    return __int_as_float((ki + 127) << 23) * p;
}
__device__ __forceinline__ unsigned fenc(float f){
    unsigned u = __float_as_uint(f);
    return (u & 0x80000000u) ? ~u : (u | 0x80000000u);
}
__device__ __forceinline__ float fdec(unsigned k){
    return (k & 0x80000000u) ? __uint_as_float(k ^ 0x80000000u) : __uint_as_float(~k);
}
// split fp32x4 -> 2 packed bf16x2 words per plane
__device__ __forceinline__ void split4(float4 v, unsigned& h01, unsigned& h23, unsigned& l01, unsigned& l23){
    __nv_bfloat16 h0 = __float2bfloat16(v.x), h1 = __float2bfloat16(v.y);
    __nv_bfloat16 h2 = __float2bfloat16(v.z), h3 = __float2bfloat16(v.w);
    __nv_bfloat16 l0 = __float2bfloat16(v.x - __bfloat162float(h0));
    __nv_bfloat16 l1 = __float2bfloat16(v.y - __bfloat162float(h1));
    __nv_bfloat16 l2 = __float2bfloat16(v.z - __bfloat162float(h2));
    __nv_bfloat16 l3 = __float2bfloat16(v.w - __bfloat162float(h3));
    h01 = ((unsigned)__bfloat16_as_ushort(h1) << 16) | __bfloat16_as_ushort(h0);
    h23 = ((unsigned)__bfloat16_as_ushort(h3) << 16) | __bfloat16_as_ushort(h2);
    l01 = ((unsigned)__bfloat16_as_ushort(l1) << 16) | __bfloat16_as_ushort(l0);
    l23 = ((unsigned)__bfloat16_as_ushort(l3) << 16) | __bfloat16_as_ushort(l2);
}
__device__ __forceinline__ void sts64(unsigned a, unsigned w0, unsigned w1){
    asm volatile("st.shared.v2.b32 [%0], {%1,%2};" :: "r"(a), "r"(w0), "r"(w1) : "memory");
}

// ---------------- setup ----------------
__global__ void zero_k(){
    int i = blockIdx.x*256 + threadIdx.x;
    if (i < MB){ g_cnt[i] = 0; g_rs[i] = 0; }
    if (i < SBN){ g_sbcnt[i] = 0; g_scount[i] = 0; }
    if (i < NWID) g_wcnt[i] = 0;
    if (i < NH*NTOK) g_rowmaxk[i] = 0u;
    if (i < NTOK){ g_r1[i] = 0; g_r2[i] = 0; g_r3[i] = 0; }
}
__global__ void prep_k(const int* __restrict__ coords){
    int t = blockIdx.x*256 + threadIdx.x;
    if (t >= NTOK) return;
    int cf = coords[t];
    int x = cf >> 12, y = (cf >> 6) & 63, z = cf & 63;
    int bid = ((x>>2)<<8) | ((y>>2)<<4) | (z>>2);
    g_bid[t] = bid; atomicAdd(&g_cnt[bid], 1);
    int sb = ((x>>3)<<6) | ((y>>3)<<3) | (z>>3);
    g_sbid[t] = sb; atomicAdd(&g_sbcnt[sb], 1);
    int wd = (((x+4)>>3)*9 + ((y+4)>>3))*9 + ((z+4)>>3);
    g_wid[t] = wd; atomicAdd(&g_wcnt[wd], 1);
    g_pei[t] = (((x&3)*4 + (y&3))*4 + (z&3)) * HD;
    g_packed[t] = bid | (sb << 12) | (wd << 21);
}
__global__ void gate_k(const float* __restrict__ feats, const float* __restrict__ Wg){
    int n = blockIdx.x;
    int w = threadIdx.x >> 5, lane = threadIdx.x & 31;
    if (w >= 3) return;
    float s = 0.f;
    for (int i = lane; i < HD; i += 32) s += feats[n*HD + i] * Wg[i*3 + w];
    #pragma unroll
    for (int o = 16; o; o >>= 1) s += __shfl_xor_sync(0xffffffffu, s, o);
    if (lane == 0) g_gate[n*3 + w] = 1.0f / (1.0f + fexp(-s));
}
__device__ __forceinline__ void warp_exscan(const int* cnt, int* off, int len){
    int lane = threadIdx.x & 31;
    int run = 0;
    for (int base = 0; base < len; base += 32){
        int raw = (base+lane < len) ? cnt[base+lane] : 0;
        int v = raw;
        #pragma unroll
        for (int o = 1; o < 32; o <<= 1){ int t = __shfl_up_sync(0xffffffffu, v, o); if (lane >= o) v += t; }
        if (base+lane < len) off[base+lane] = run + v - raw;
        run += __shfl_sync(0xffffffffu, v, 31);
    }
    if (lane == 0) off[len] = run;
}
__global__ void scan1_k(){
    int w = threadIdx.x >> 5;
    if (w == 0) warp_exscan(g_cnt, g_boff, MB);
    else if (w == 1) warp_exscan(g_sbcnt, g_sboff, SBN);
    else if (w == 2) warp_exscan(g_wcnt, g_woff, NWID);
    else {
        int lane = threadIdx.x & 31;
        int run = 0;
        for (int base = 0; base < MB; base += 32){
            int valid = g_cnt[base+lane] > 0 ? 1 : 0;
            int v = valid;
            #pragma unroll
            for (int o = 1; o < 32; o <<= 1){ int t = __shfl_up_sync(0xffffffffu, v, o); if (lane >= o) v += t; }
            if (valid) g_vlist[run + v - 1] = base + lane;
            run += __shfl_sync(0xffffffffu, v, 31);
        }
        if (lane == 0) g_nvalid = run;
    }
}
__global__ void scan2_k(){ warp_exscan(g_scount, g_soff, SBN); }

// parallel deterministic ranking (int atomics only)
__global__ void permcnt_k(){
    int bt = blockIdx.x, bu = blockIdx.y;
    if (bu > bt) return;
    __shared__ int sp[256];
    int tid = threadIdx.x;
    int t = bt*256 + tid;
    sp[tid] = g_packed[bu*256 + tid];
    __syncthreads();
    int my = g_packed[t];
    int lim = (bu < bt) ? 256 : tid;
    int r1 = 0, r2 = 0, r3 = 0;
    for (int u = 0; u < lim; u++){
        int p = sp[u] ^ my;
        r3 += ((p & 0x00000FFF) == 0);
        r1 += ((p & 0x001FF000) == 0);
        r2 += ((p & 0x7FE00000) == 0);
    }
    if (r1) atomicAdd(&g_r1[t], r1);
    if (r2) atomicAdd(&g_r2[t], r2);
    if (r3) atomicAdd(&g_r3[t], r3);
}
__global__ void permscat_k(){
    int t = blockIdx.x*256 + threadIdx.x;
    if (t >= NTOK) return;
    int my = g_packed[t];
    int bd = my & 0xFFF, sb = (my >> 12) & 0x1FF, wd = (my >> 21) & 0x3FF;
    g_sbperm[g_sboff[sb] + g_r1[t]] = t;
    g_wperm [g_woff[wd]  + g_r2[t]] = t;
    g_bperm [g_boff[bd]  + g_r3[t]] = t;
}
__global__ void scnt_k(){
    int bj = blockIdx.x, bu = blockIdx.y;
    if (bu > bj) return;
    __shared__ int sp[256];
    int tid = threadIdx.x;
    int nv = g_nvalid;
    int ju = bu*256 + tid;
    sp[tid] = (ju < nv) ? g_sidc[ju] : -1;
    __syncthreads();
    int j = bj*256 + tid;
    if (j >= nv) return;
    int my = g_sidc[j];
    int lim = (bu < bj) ? 256 : tid;
    int r = 0;
    for (int u = 0; u < lim; u++) r += (sp[u] == my);
    if (r) atomicAdd(&g_rs[j], r);
}
__global__ void sscat_k(){
    int j = blockIdx.x*256 + threadIdx.x;
    if (j >= g_nvalid) return;
    g_slist[g_soff[g_sidc[j]] + g_rs[j]] = j;
}

__global__ void avg_k(const float* __restrict__ pe){
    int j = blockIdx.x;
    int nv = g_nvalid;
    if (j >= nv){
        __nv_bfloat16 zb = __float2bfloat16(0.f);
        for (int c = threadIdx.x; c < HD; c += 256){
            g_kah[j*HD+c]=zb; g_kal[j*HD+c]=zb; g_vah[j*HD+c]=zb; g_val[j*HD+c]=zb;
        }
        return;
    }
    int m = g_vlist[j];
    int c0 = g_boff[m], c1 = g_boff[m+1];
    float dn = 1.0f / (float)max(c1 - c0, 1);
    for (int c = threadIdx.x; c < HD; c += 256){
        float sk = 0.f, sv = 0.f;
        for (int i = c0; i < c1; i++){
            int t = g_bperm[i];
            sk += g_kf[t*HD + c] + pe[g_pei[t] + c];
            sv += g_vf[t*HD + c];
        }
        sk *= dn; sv *= dn;
        __nv_bfloat16 kh = __float2bfloat16(sk);
        __nv_bfloat16 vh = __float2bfloat16(sv);
        g_kah[j*HD+c] = kh; g_kal[j*HD+c] = __float2bfloat16(sk - __bfloat162float(kh));
        g_vah[j*HD+c] = vh; g_val[j*HD+c] = __float2bfloat16(sv - __bfloat162float(vh));
    }
    if (threadIdx.x == 0){
        int mx = m >> 8, my = (m >> 4) & 15, mz = m & 15;
        g_sidc[j] = ((mx>>1)<<6) | ((my>>1)<<3) | (mz>>1);
        atomicAdd(&g_scount[g_sidc[j]], 1);
    }
}
__global__ void convA_k(const float* __restrict__ in, __nv_bfloat16* __restrict__ h, __nv_bfloat16* __restrict__ l){
    int i = blockIdx.x*256 + threadIdx.x;
    float x = in[i];
    __nv_bfloat16 hb = __float2bfloat16(x);
    h[i] = hb; l[i] = __float2bfloat16(x - __bfloat162float(hb));
}
__global__ void convW_k(const float* W0, const float* W1, const float* W2,
                        const float* W3, const float* W4, const float* W5){
    int z = blockIdx.z;
    const float* W = z==0?W0 : z==1?W1 : z==2?W2 : z==3?W3 : z==4?W4 : W5;
    __nv_bfloat16* h = g_wth + (size_t)z*HD*HD;
    __nv_bfloat16* l = g_wtl + (size_t)z*HD*HD;
    __shared__ float t[32][33];
    int bn = blockIdx.x*32, bk = blockIdx.y*32;
    int tx = threadIdx.x & 31, ty = threadIdx.x >> 5;
    for (int r = ty; r < 32; r += 8) t[r][tx] = W[(size_t)(bk+r)*HD + bn + tx];
    __syncthreads();
    for (int r = ty; r < 32; r += 8){
        float x = t[tx][r];
        __nv_bfloat16 hb = __float2bfloat16(x);
        h[(size_t)(bn+r)*HD + bk + tx] = hb;
        l[(size_t)(bn+r)*HD + bk + tx] = __float2bfloat16(x - __bfloat162float(hb));
    }
}
// cv [j][h*64+d] -> cvt planes [h][d][j] split bf16
__global__ void cvt_k(){
    __shared__ float t[32][33];
    int bj = blockIdx.x*32, bd = blockIdx.y*32;
    int tx = threadIdx.x & 31, ty = threadIdx.x >> 5;
    for (int r = ty; r < 32; r += 8) t[r][tx] = g_cv[(size_t)(bj+r)*HD + bd + tx];
    __syncthreads();
    for (int r = ty; r < 32; r += 8){
        int gd = bd + r, h = gd >> 6, dd = gd & 63;
        float x = t[tx][r];
        __nv_bfloat16 hb = __float2bfloat16(x);
        g_cvth[(size_t)(h*DH + dd)*MB + bj + tx] = hb;
        g_cvtl[(size_t)(h*DH + dd)*MB + bj + tx] = __float2bfloat16(x - __bfloat162float(hb));
    }
}

// ---------------- mma.sync stage compute: 8 warps, CTA tile 128x128 ----------------
#define KSTR 24
#define ARR  6144
#define STG  24576

__device__ __forceinline__ void mma_stage(unsigned base, int wm, int wn, int lane, float acc[4][4][4]){
    unsigned ah[4][4], al[4][4], bh[4][2], bl[4][2];
    int t7 = lane & 7, t8 = lane >> 3;
    #pragma unroll
    for (int mt = 0; mt < 4; mt++){
        int m = wm*64 + mt*16 + (t8&1)*8 + t7;
        unsigned off = base + (m*KSTR + (t8>>1)*8)*2;
        ldsm4(ah[mt], off);
        ldsm4(al[mt], off + ARR);
    }
    #pragma unroll
    for (int p = 0; p < 2; p++){
        int n = wn*32 + p*16 + (t8>>1)*8 + t7;
        unsigned off = base + 2*ARR + (n*KSTR + (t8&1)*8)*2;
        unsigned r[4];
        ldsm4(r, off);
        bh[2*p][0]=r[0]; bh[2*p][1]=r[1]; bh[2*p+1][0]=r[2]; bh[2*p+1][1]=r[3];
        ldsm4(r, off + ARR);
        bl[2*p][0]=r[0]; bl[2*p][1]=r[1]; bl[2*p+1][0]=r[2]; bl[2*p+1][1]=r[3];
    }
    #pragma unroll
    for (int mt = 0; mt < 4; mt++)
        #pragma unroll
        for (int nt = 0; nt < 4; nt++){
            mma16816(acc[mt][nt], ah[mt], bh[nt]);
            mma16816(acc[mt][nt], ah[mt], bl[nt]);
            mma16816(acc[mt][nt], al[mt], bh[nt]);
        }
}

// ---------------- GEMM A[·,512] x W^T -> C[128,128] tiles ----------------
__global__ void __launch_bounds__(256) mm_k(
    const __nv_bfloat16* __restrict__ Ah0, const __nv_bfloat16* __restrict__ Al0,
    const __nv_bfloat16* __restrict__ Ah1, const __nv_bfloat16* __restrict__ Al1,
    int wbase, float* C0, float* C1, float* C2,
    __nv_bfloat16* Hh, __nv_bfloat16* Hl, int hz0, int guard)
{
    extern __shared__ char smem[];
    int z = blockIdx.z;
    const __nv_bfloat16* Ah = (z==1) ? Ah1 : Ah0;
    const __nv_bfloat16* Al = (z==1) ? Al1 : Al0;
    const __nv_bfloat16* Bh = g_wth + (size_t)(wbase+z)*HD*HD;
    const __nv_bfloat16* Bl = g_wtl + (size_t)(wbase+z)*HD*HD;
    float* C = (z==0) ? C0 : ((z==1) ? C1 : C2);
    int tbm = blockIdx.y*128, tbn = blockIdx.x*128;
    if (guard && tbm >= g_nvalid) return;
    unsigned s0 = smem_u32(smem);
    int tid = threadIdx.x, lane = tid & 31, warp = tid >> 5;
    int wm = warp & 1, wn = warp >> 1;
    int row = tid >> 1, half = tid & 1;
    size_t aoff = (size_t)(tbm+row)*HD + half*8;
    size_t boff = (size_t)(tbn+row)*HD + half*8;
    unsigned sdst = (row*KSTR + half*8)*2;

    float acc[4][4][4];
    #pragma unroll
    for (int i = 0; i < 4; i++)
        #pragma unroll
        for (int j2 = 0; j2 < 4; j2++){ acc[i][j2][0]=0.f; acc[i][j2][1]=0.f; acc[i][j2][2]=0.f; acc[i][j2][3]=0.f; }

    float4 pa = *(const float4*)&Ah[aoff];
    float4 pl = *(const float4*)&Al[aoff];
    float4 pb = *(const float4*)&Bh[boff];
    float4 pq = *(const float4*)&Bl[boff];
    { unsigned b = s0 + sdst; sts128(b, pa); sts128(b+ARR, pl); sts128(b+2*ARR, pb); sts128(b+3*ARR, pq); }
    __syncthreads();
    for (int it = 1; it <= 32; it++){
        if (it < 32){
            pa = *(const float4*)&Ah[aoff + it*16];
            pl = *(const float4*)&Al[aoff + it*16];
            pb = *(const float4*)&Bh[boff + it*16];
            pq = *(const float4*)&Bl[boff + it*16];
        }
        mma_stage(s0 + ((it-1)&1)*STG, wm, wn, lane, acc);
        if (it < 32){
            unsigned b = s0 + (it&1)*STG + sdst;
            sts128(b, pa); sts128(b+ARR, pl); sts128(b+2*ARR, pb); sts128(b+3*ARR, pq);
            __syncthreads();
        }
    }
    #pragma unroll
    for (int mt = 0; mt < 4; mt++){
        int m0 = tbm + wm*64 + mt*16 + (lane>>2);
        #pragma unroll
        for (int nt = 0; nt < 4; nt++){
            int n = tbn + wn*32 + nt*8 + (lane&3)*2;
            float* c = acc[mt][nt];
            size_t i0 = (size_t)m0*HD + n, i1 = (size_t)(m0+8)*HD + n;
            *(float2*)&C[i0] = make_float2(c[0], c[1]);
            *(float2*)&C[i1] = make_float2(c[2], c[3]);
            if (hz0 && z == 0){
                __nv_bfloat16 h0 = __float2bfloat16(c[0]), h1 = __float2bfloat16(c[1]);
                __nv_bfloat16 h2 = __float2bfloat16(c[2]), h3 = __float2bfloat16(c[3]);
                *(__nv_bfloat162*)&Hh[i0] = __nv_bfloat162(h0, h1);
                *(__nv_bfloat162*)&Hh[i1] = __nv_bfloat162(h2, h3);
                *(__nv_bfloat162*)&Hl[i0] = __nv_bfloat162(
                    __float2bfloat16(c[0]-__bfloat162float(h0)), __float2bfloat16(c[1]-__bfloat162float(h1)));
                *(__nv_bfloat162*)&Hl[i1] = __nv_bfloat162(
                    __float2bfloat16(c[2]-__bfloat162float(h2)), __float2bfloat16(c[3]-__bfloat162float(h3)));
            }
        }
    }
}

// ---------------- QK^T: S[128q x 128j] per head, K=64 ----------------
__global__ void __launch_bounds__(256) qkmm_k(){
    extern __shared__ char smem[];
    int h = blockIdx.z, nt0 = blockIdx.y*128, jt = blockIdx.x*128;
    int nv = g_nvalid;
    if (jt >= nv) return;
    unsigned s0 = smem_u32(smem);
    int tid = threadIdx.x, lane = tid & 31, warp = tid >> 5;
    int wm = warp & 1, wn = warp >> 1;
    int row = tid >> 1, half = tid & 1;
    size_t aoff = (size_t)(nt0+row)*HD + h*DH + half*8;
    size_t boff = (size_t)(jt+row)*HD + h*DH + half*8;
    unsigned sdst = (row*KSTR + half*8)*2;

    float acc[4][4][4];
    #pragma unroll
    for (int i = 0; i < 4; i++)
        #pragma unroll
        for (int j2 = 0; j2 < 4; j2++){ acc[i][j2][0]=0.f; acc[i][j2][1]=0.f; acc[i][j2][2]=0.f; acc[i][j2][3]=0.f; }

    float4 pa = *(const float4*)&g_qh [aoff];
    float4 pl = *(const float4*)&g_ql [aoff];
    float4 pb = *(const float4*)&g_ckh[boff];
    float4 pq = *(const float4*)&g_ckl[boff];
    { unsigned b = s0 + sdst; sts128(b, pa); sts128(b+ARR, pl); sts128(b+2*ARR, pb); sts128(b+3*ARR, pq); }
    __syncthreads();
    #pragma unroll
    for (int it = 1; it <= 4; it++){
        if (it < 4){
            pa = *(const float4*)&g_qh [aoff + it*16];
            pl = *(const float4*)&g_ql [aoff + it*16];
            pb = *(const float4*)&g_ckh[boff + it*16];
            pq = *(const float4*)&g_ckl[boff + it*16];
        }
        mma_stage(s0 + ((it-1)&1)*STG, wm, wn, lane, acc);
        if (it < 4){
            unsigned b = s0 + (it&1)*STG + sdst;
            sts128(b, pa); sts128(b+ARR, pl); sts128(b+2*ARR, pb); sts128(b+3*ARR, pq);
            __syncthreads();
        }
    }
    #pragma unroll
    for (int mt = 0; mt < 4; mt++){
        int m = nt0 + wm*64 + mt*16 + (lane>>2);
        float mx0 = -3.0e38f, mx1 = -3.0e38f;
        #pragma unroll
        for (int nt = 0; nt < 4; nt++){
            int j = jt + wn*32 + nt*8 + (lane&3)*2;
            float* c = acc[mt][nt];
            float v0 = c[0]*0.125f, v1 = c[1]*0.125f, v2 = c[2]*0.125f, v3 = c[3]*0.125f;
            *(float2*)&g_S[(size_t)(h*NTOK + m  )*MB + j] = make_float2(v0, v1);
            *(float2*)&g_S[(size_t)(h*NTOK + m+8)*MB + j] = make_float2(v2, v3);
            if (j   < nv){ mx0 = fmaxf(mx0, v0); mx1 = fmaxf(mx1, v2); }
            if (j+1 < nv){ mx0 = fmaxf(mx0, v1); mx1 = fmaxf(mx1, v3); }
        }
        mx0 = fmaxf(mx0, __shfl_xor_sync(0xffffffffu, mx0, 1));
        mx0 = fmaxf(mx0, __shfl_xor_sync(0xffffffffu, mx0, 2));
        mx1 = fmaxf(mx1, __shfl_xor_sync(0xffffffffu, mx1, 1));
        mx1 = fmaxf(mx1, __shfl_xor_sync(0xffffffffu, mx1, 2));
        if ((lane & 3) == 0){
            atomicMax(&g_rowmaxk[h*NTOK + m],     fenc(mx0));
            atomicMax(&g_rowmaxk[h*NTOK + m + 8], fenc(mx1));
        }
    }
}

// ---------------- fused softmax (exp in place) + head-pooled probs ----------------
__global__ __launch_bounds__(256) void smrow_k(){
    int n = blockIdx.x, tid = threadIdx.x;
    int nv = g_nvalid;
    __shared__ float red[8];
    __shared__ float binv;
    float p8a[16];
    #pragma unroll
    for (int q = 0; q < 16; q++) p8a[q] = 0.f;
    for (int h = 0; h < NH; h++){
        float* row = g_S + ((size_t)(h*NTOK + n))*MB;
        float bm = fdec(g_rowmaxk[h*NTOK + n]);
        float ec[16];
        float l = 0.f;
        #pragma unroll
        for (int q = 0; q < 16; q++){
            int j = tid + q*256;
            float e = 0.f;
            if (j < nv){ e = fexp(row[j] - bm); row[j] = e; l += e; }
            ec[q] = e;
        }
        #pragma unroll
        for (int o = 16; o; o >>= 1) l += __shfl_xor_sync(0xffffffffu, l, o);
        if ((tid & 31) == 0) red[tid >> 5] = l;
        __syncthreads();
        if (tid == 0){
            float s = 0.f;
            #pragma unroll
            for (int w = 0; w < 8; w++) s += red[w];
            float iv = 1.0f / s;
            binv = iv;
            g_invl[h*NTOK + n] = iv;
        }
        __syncthreads();
        float il = binv;
        #pragma unroll
        for (int q = 0; q < 16; q++) p8a[q] += ec[q] * il;
        __syncthreads();
    }
    #pragma unroll
    for (int q = 0; q < 16; q++){
        int j = tid + q*256;
        if (j < nv) g_P8[(size_t)n*MB + j] = p8a[q];
    }
}

// ---------------- P @ V via tensor cores: 64 rows x 64 cols per head ----------------
// P loaded fp32 from g_S, split to bf16 hi/lo in registers during staging.
__global__ void __launch_bounds__(128) pv_k(){
    __shared__ __nv_bfloat16 sm[2][4][64*40];   // [stage][ph,pl,vh,vl]
    int nt = blockIdx.x*64, h = blockIdx.y;
    int nv = g_nvalid;
    int nvp = (nv + 31) & ~31, nk = nvp/32;
    int tid = threadIdx.x, lane = tid & 31, w = tid >> 5;
    const float* Sb = g_S + (size_t)(h*NTOK + nt)*MB;
    const __nv_bfloat16* Vha = g_cvth + (size_t)h*DH*MB;
    const __nv_bfloat16* Vla = g_cvtl + (size_t)h*DH*MB;
    float acc[8][4];
    #pragma unroll
    for (int i = 0; i < 8; i++){ acc[i][0]=0.f; acc[i][1]=0.f; acc[i][2]=0.f; acc[i][3]=0.f; }

    float4 pr[4]; float4 vr[4];
    #pragma unroll
    for (int q = 0; q < 4; q++){
        int jb = tid + 128*q;
        pr[q] = *(const float4*)&Sb[(size_t)(jb>>3)*MB + (jb&7)*4];
        int rem = jb & 255, vrow = rem >> 2, vf = rem & 3;
        const __nv_bfloat16* Vp = (jb >> 8) ? Vla : Vha;
        vr[q] = *(const float4*)&Vp[(size_t)vrow*MB + vf*8];
    }
    #pragma unroll
    for (int q = 0; q < 4; q++){
        int jb = tid + 128*q;
        int prow = jb >> 3, pf = jb & 7;
        unsigned h01, h23, l01, l23;
        split4(pr[q], h01, h23, l01, l23);
        unsigned pa = smem_u32(&sm[0][0][prow*40 + pf*4]);
        sts64(pa, h01, h23);
        sts64(pa + PVPL, l01, l23);
        int rem = jb & 255, vrow = rem >> 2, vf = rem & 3;
        int vp = (jb >> 8) ? 3 : 2;
        *(float4*)&sm[0][vp][vrow*40 + vf*8] = vr[q];
    }
    __syncthreads();
    int t7 = lane & 7, t8 = lane >> 3;
    for (int it = 1; it <= nk; it++){
        if (it < nk){
            int j0 = it*32;
            #pragma unroll
            for (int q = 0; q < 4; q++){
                int jb = tid + 128*q;
                pr[q] = *(const float4*)&Sb[(size_t)(jb>>3)*MB + j0 + (jb&7)*4];
                int rem = jb & 255, vrow = rem >> 2, vf = rem & 3;
                const __nv_bfloat16* Vp = (jb >> 8) ? Vla : Vha;
                vr[q] = *(const float4*)&Vp[(size_t)vrow*MB + j0 + vf*8];
            }
        }
        int s = (it-1) & 1;
        #pragma unroll
        for (int kk = 0; kk < 2; kk++){
            unsigned ah[4], al[4], bh[8][2], bl[8][2];
            int arow = w*16 + (t8&1)*8 + t7;
            int acol = kk*16 + (t8>>1)*8;
            ldsm4(ah, smem_u32(&sm[s][0][arow*40 + acol]));
            ldsm4(al, smem_u32(&sm[s][1][arow*40 + acol]));
            #pragma unroll
            for (int p = 0; p < 4; p++){
                int nrow = p*16 + (t8>>1)*8 + t7;
                int ncol = kk*16 + (t8&1)*8;
                unsigned rr[4];
                ldsm4(rr, smem_u32(&sm[s][2][nrow*40 + ncol]));
                bh[2*p][0]=rr[0]; bh[2*p][1]=rr[1]; bh[2*p+1][0]=rr[2]; bh[2*p+1][1]=rr[3];
                ldsm4(rr, smem_u32(&sm[s][3][nrow*40 + ncol]));
                bl[2*p][0]=rr[0]; bl[2*p][1]=rr[1]; bl[2*p+1][0]=rr[2]; bl[2*p+1][1]=rr[3];
            }
            #pragma unroll
            for (int d = 0; d < 8; d++){
                mma16816(acc[d], ah, bh[d]);
                mma16816(acc[d], ah, bl[d]);
                mma16816(acc[d], al, bh[d]);
            }
        }
        if (it < nk){
            int ns = it & 1;
            #pragma unroll
            for (int q = 0; q < 4; q++){
                int jb = tid + 128*q;
                int prow = jb >> 3, pf = jb & 7;
                unsigned h01, h23, l01, l23;
                split4(pr[q], h01, h23, l01, l23);
                unsigned pa = smem_u32(&sm[ns][0][prow*40 + pf*4]);
                sts64(pa, h01, h23);
                sts64(pa + PVPL, l01, l23);
                int rem = jb & 255, vrow = rem >> 2, vf = rem & 3;
                int vp = (jb >> 8) ? 3 : 2;
                *(float4*)&sm[ns][vp][vrow*40 + vf*8] = vr[q];
            }
            __syncthreads();
        }
    }
    int rowA = nt + w*16 + (lane>>2);
    float ilA = g_invl[h*NTOK + rowA];
    float ilB = g_invl[h*NTOK + rowA + 8];
    #pragma unroll
    for (int d = 0; d < 8; d++){
        int col = h*DH + d*8 + (lane&3)*2;
        *(float2*)&g_outc[(size_t)rowA*HD + col]     = make_float2(acc[d][0]*ilA, acc[d][1]*ilA);
        *(float2*)&g_outc[(size_t)(rowA+8)*HD + col] = make_float2(acc[d][2]*ilB, acc[d][3]*ilB);
    }
}

// ---------------- sel_score + top-8 ----------------
__global__ void topk_k(){
    int n = blockIdx.x, tid = threadIdx.x;
    int lane = tid & 31, w = tid >> 5;
    __shared__ float ss[SBN];
    __shared__ float wv[16];
    __shared__ int   wi[16];
    float v = 0.f;
    int o0 = g_soff[tid], o1 = g_soff[tid+1];
    for (int i = o0; i < o1; i++) v += g_P8[(size_t)n*MB + g_slist[i]];
    ss[tid] = v;
    __syncthreads();
    for (int r = 0; r < 8; r++){
        float mv = ss[tid]; int mi = tid;
        #pragma unroll
        for (int o = 16; o; o >>= 1){
            float ov = __shfl_xor_sync(0xffffffffu, mv, o);
            int   oi = __shfl_xor_sync(0xffffffffu, mi, o);
            if (ov > mv || (ov == mv && oi < mi)){ mv = ov; mi = oi; }
        }
        if (lane == 0){ wv[w] = mv; wi[w] = mi; }
        __syncthreads();
        if (tid < 16){
            float m2 = wv[tid]; int i2 = wi[tid];
            #pragma unroll
            for (int o = 8; o; o >>= 1){
                float ov = __shfl_xor_sync(0x0000ffffu, m2, o);
                int   oi = __shfl_xor_sync(0x0000ffffu, i2, o);
                if (ov > m2 || (ov == m2 && oi < i2)){ m2 = ov; i2 = oi; }
            }
            if (tid == 0){ g_top8[n*8 + r] = i2; ss[i2] = -1e30f; }
        }
        __syncthreads();
    }
}

// ---------------- selection / window attention ----------------
__global__ void spattn_k(){
    int n = blockIdx.x, mode = blockIdx.y;
    int h = threadIdx.x >> 5, lane = threadIdx.x & 31;
    const float* qr = &g_q[n*HD + h*DH];
    float q0 = qr[lane], q1 = qr[lane + 32];
    float m = -1e30f, l = 0.f, a0 = 0.f, a1 = 0.f;
    int nb = (mode == 0) ? 8 : 1;
    for (int kk = 0; kk < nb; kk++){
        int b, o, e;
        if (mode == 0){ b = g_top8[n*8 + kk]; o = g_sboff[b]; e = g_sboff[b+1]; }
        else          { b = g_wid[n];         o = g_woff[b];  e = g_woff[b+1]; }
        for (int i = o; i < e; i++){
            int t = (mode == 0) ? g_sbperm[i] : g_wperm[i];
            const float* kr = &g_kf[t*HD + h*DH];
            float s = q0*kr[lane] + q1*kr[lane + 32];
            #pragma unroll
            for (int of = 16; of; of >>= 1) s += __shfl_xor_sync(0xffffffffu, s, of);
            s *= 0.125f;
            float mn = fmaxf(m, s);
            float c = fexp(m - mn), ww = fexp(s - mn);
            const float* vr = &g_vf[t*HD + h*DH];
            l  = l*c  + ww;
            a0 = a0*c + ww*vr[lane];
            a1 = a1*c + ww*vr[lane + 32];
            m = mn;
        }
    }
    float* outp = mode ? g_outw : g_outs;
    outp[n*HD + h*DH + lane]      = a0 / l;
    outp[n*HD + h*DH + lane + 32] = a1 / l;
}

// ---------------- gated fuse -> split bf16 (input to Wo GEMM) ----------------
__global__ void fuse_k(){
    int i = blockIdx.x*256 + threadIdx.x;
    int n = i >> 9;
    float g0 = g_gate[n*3+0], g1 = g_gate[n*3+1], g2 = g_gate[n*3+2];
    float v = g0*g_outc[i] + g1*g_outs[i] + g2*g_outw[i];
    __nv_bfloat16 hb = __float2bfloat16(v);
    g_fh[i] = hb;
    g_fl[i] = __float2bfloat16(v - __bfloat162float(hb));
}

// ---------------- launch ----------------
extern "C" void kernel_launch(void* const* d_in, const int* in_sizes, int n_in,
                              void* d_out, int out_size){
    const float* feats  = (const float*)d_in[0];
    const int*   coords = (const int*)  d_in[1];
    const float* Wq  = (const float*)d_in[2];
    const float* Wk  = (const float*)d_in[3];
    const float* Wv  = (const float*)d_in[4];
    const float* Wo  = (const float*)d_in[5];
    const float* Wck = (const float*)d_in[6];
    const float* Wcv = (const float*)d_in[7];
    const float* pe  = (const float*)d_in[8];
    const float* Wg  = (const float*)d_in[9];
    float* out = (float*)d_out;

    float *gq, *gkf, *gvf, *gck, *gcv;
    __nv_bfloat16 *fh, *fl, *qh, *ql, *kah, *kal, *vah, *val, *ckh, *ckl;
    cudaGetSymbolAddress((void**)&gq,  g_q);
    cudaGetSymbolAddress((void**)&gkf, g_kf);
    cudaGetSymbolAddress((void**)&gvf, g_vf);
    cudaGetSymbolAddress((void**)&gck, g_ck);
    cudaGetSymbolAddress((void**)&gcv, g_cv);
    cudaGetSymbolAddress((void**)&fh,  g_fh);
    cudaGetSymbolAddress((void**)&fl,  g_fl);
    cudaGetSymbolAddress((void**)&qh,  g_qh);
    cudaGetSymbolAddress((void**)&ql,  g_ql);
    cudaGetSymbolAddress((void**)&kah, g_kah);
    cudaGetSymbolAddress((void**)&kal, g_kal);
    cudaGetSymbolAddress((void**)&vah, g_vah);
    cudaGetSymbolAddress((void**)&val, g_val);
    cudaGetSymbolAddress((void**)&ckh, g_ckh);
    cudaGetSymbolAddress((void**)&ckl, g_ckl);

    cudaFuncSetAttribute(mm_k,   cudaFuncAttributeMaxDynamicSharedMemorySize, 2*STG);
    cudaFuncSetAttribute(qkmm_k, cudaFuncAttributeMaxDynamicSharedMemorySize, 2*STG);

    zero_k<<<64, 256>>>();
    prep_k<<<8, 256>>>(coords);
    gate_k<<<NTOK, 128>>>(feats, Wg);
    convW_k<<<dim3(16, 16, 6), 256>>>(Wq, Wk, Wv, Wck, Wcv, Wo);
    convA_k<<<NTOK*HD/256, 256>>>(feats, fh, fl);

    mm_k<<<dim3(4, NTOK/128, 3), 256, 2*STG>>>(fh, fl, fh, fl, 0, gq, gkf, gvf, qh, ql, 1, 0);

    scan1_k<<<1, 128>>>();
    permcnt_k<<<dim3(8, 8), 256>>>();
    permscat_k<<<8, 256>>>();
    avg_k<<<MB, 256>>>(pe);

    mm_k<<<dim3(4, MB/128, 2), 256, 2*STG>>>(kah, kal, vah, val, 3, gck, gcv, gcv, ckh, ckl, 1, 1);
    cvt_k<<<dim3(MB/32, HD/32), 256>>>();

    scan2_k<<<1, 32>>>();
    scnt_k<<<dim3(8, 8), 256>>>();
    sscat_k<<<8, 256>>>();

    qkmm_k<<<dim3(MB/128, NTOK/128, NH), 256, 2*STG>>>();
    smrow_k<<<NTOK, 256>>>();
    pv_k<<<dim3(NTOK/64, NH), 128>>>();
    topk_k<<<NTOK, 512>>>();
    spattn_k<<<dim3(NTOK, 2), 256>>>();
    fuse_k<<<NTOK*HD/256, 256>>>();

    mm_k<<<dim3(4, NTOK/128, 1), 256, 2*STG>>>(fh, fl, fh, fl, 5, out, out, out, qh, ql, 0, 0);
}

// round 11
// speedup vs baseline: 1.9309x; 1.0646x over previous
#include <cuda_runtime.h>
#include <cuda_bf16.h>

#define NTOK 2048
#define HD   512
#define NH   8
#define DH   64
#define MB   4096
#define SBN  512
#define NWID 729

// ---------------- scratch ----------------
__device__ float g_q[NTOK*HD], g_kf[NTOK*HD], g_vf[NTOK*HD];
__device__ float g_ck[MB*HD], g_cv[MB*HD];
__device__ float g_P8[(size_t)NTOK*MB];
__device__ float g_invl[NH*NTOK];
__device__ float g_rowm[NH*NTOK];
__device__ float g_outc[NTOK*HD], g_outs[NTOK*HD], g_outw[NTOK*HD];
__device__ float g_gate[NTOK*3];
__device__ int g_cnt[MB], g_boff[MB+1], g_bperm[NTOK], g_bid[NTOK];
__device__ int g_sbcnt[SBN], g_sboff[SBN+1], g_sbperm[NTOK], g_sbid[NTOK];
__device__ int g_wcnt[NWID], g_woff[NWID+1], g_wperm[NTOK], g_wid[NTOK];
__device__ int g_scount[SBN], g_soff[SBN+1], g_slist[MB], g_sidc[MB];
__device__ int g_vlist[MB], g_nvalid;
__device__ int g_pei[NTOK], g_packed[NTOK], g_top8[NTOK*8];
__device__ int g_r1[NTOK], g_r2[NTOK], g_r3[NTOK], g_rs[MB];
// split-bf16 operands
__device__ __nv_bfloat16 g_wth[6*HD*HD], g_wtl[6*HD*HD];
__device__ __nv_bfloat16 g_fh[NTOK*HD], g_fl[NTOK*HD];
__device__ __nv_bfloat16 g_qh[NTOK*HD], g_ql[NTOK*HD];   // pre-scaled by 0.125
__device__ __nv_bfloat16 g_kah[MB*HD], g_kal[MB*HD], g_vah[MB*HD], g_val[MB*HD];
__device__ __nv_bfloat16 g_ckh[MB*HD], g_ckl[MB*HD];
__device__ __nv_bfloat16 g_cvth[NH*DH*MB], g_cvtl[NH*DH*MB];

// ---------------- helpers ----------------
__device__ __forceinline__ unsigned smem_u32(const void* p){
    unsigned a;
    asm("{ .reg .u64 t; cvta.to.shared.u64 t, %1; cvt.u32.u64 %0, t; }" : "=r"(a) : "l"(p));
    return a;
}
__device__ __forceinline__ void sts128(unsigned a, float4 v){
    asm volatile("st.shared.v4.b32 [%0], {%1,%2,%3,%4};" :: "r"(a),
        "r"(__float_as_uint(v.x)), "r"(__float_as_uint(v.y)),
        "r"(__float_as_uint(v.z)), "r"(__float_as_uint(v.w)) : "memory");
}
__device__ __forceinline__ void ldsm4(unsigned* r, unsigned addr){
    asm volatile("ldmatrix.sync.aligned.m8n8.x4.shared.b16 {%0,%1,%2,%3}, [%4];"
        : "=r"(r[0]), "=r"(r[1]), "=r"(r[2]), "=r"(r[3]) : "r"(addr));
}
__device__ __forceinline__ void mma16816(float* c, const unsigned* a, const unsigned* b){
    asm volatile("mma.sync.aligned.m16n8k16.row.col.f32.bf16.bf16.f32 "
        "{%0,%1,%2,%3}, {%4,%5,%6,%7}, {%8,%9}, {%0,%1,%2,%3};"
        : "+f"(c[0]), "+f"(c[1]), "+f"(c[2]), "+f"(c[3])
        : "r"(a[0]), "r"(a[1]), "r"(a[2]), "r"(a[3]), "r"(b[0]), "r"(b[1]));
}
__device__ __forceinline__ float fexp(float x){
    x = fminf(fmaxf(x, -87.0f), 88.0f);
    float y = x * 1.4426950408889634f;
    float z = y + 12582912.0f;
    int ki = __float_as_int(z) - 0x4B400000;
    float f = y - (z - 12582912.0f);
    float p = 1.5403530393381609e-4f;
    p = fmaf(p, f, 1.3333558146428443e-3f);
    p = fmaf(p, f, 9.6181291076284772e-3f);
    p = fmaf(p, f, 5.5504108664821580e-2f);
    p = fmaf(p, f, 2.4022650695910071e-1f);
    p = fmaf(p, f, 6.9314718055994531e-1f);
    p = fmaf(p, f, 1.0f);
    return __int_as_float((ki + 127) << 23) * p;
}
__device__ __forceinline__ unsigned pack2(__nv_bfloat16 a, __nv_bfloat16 b){
    return ((unsigned)__bfloat16_as_ushort(b) << 16) | __bfloat16_as_ushort(a);
}

// ---------------- setup ----------------
__global__ void zero_k(){
    int i = blockIdx.x*256 + threadIdx.x;
    if (i < MB){ g_cnt[i] = 0; g_rs[i] = 0; }
    if (i < SBN){ g_sbcnt[i] = 0; g_scount[i] = 0; }
    if (i < NWID) g_wcnt[i] = 0;
    if (i < NTOK){ g_r1[i] = 0; g_r2[i] = 0; g_r3[i] = 0; }
}
__global__ void prep_k(const int* __restrict__ coords){
    int t = blockIdx.x*256 + threadIdx.x;
    if (t >= NTOK) return;
    int cf = coords[t];
    int x = cf >> 12, y = (cf >> 6) & 63, z = cf & 63;
    int bid = ((x>>2)<<8) | ((y>>2)<<4) | (z>>2);
    g_bid[t] = bid; atomicAdd(&g_cnt[bid], 1);
    int sb = ((x>>3)<<6) | ((y>>3)<<3) | (z>>3);
    g_sbid[t] = sb; atomicAdd(&g_sbcnt[sb], 1);
    int wd = (((x+4)>>3)*9 + ((y+4)>>3))*9 + ((z+4)>>3);
    g_wid[t] = wd; atomicAdd(&g_wcnt[wd], 1);
    g_pei[t] = (((x&3)*4 + (y&3))*4 + (z&3)) * HD;
    g_packed[t] = bid | (sb << 12) | (wd << 21);
}
__global__ void gate_k(const float* __restrict__ feats, const float* __restrict__ Wg){
    int n = blockIdx.x;
    int w = threadIdx.x >> 5, lane = threadIdx.x & 31;
    if (w >= 3) return;
    float s = 0.f;
    for (int i = lane; i < HD; i += 32) s += feats[n*HD + i] * Wg[i*3 + w];
    #pragma unroll
    for (int o = 16; o; o >>= 1) s += __shfl_xor_sync(0xffffffffu, s, o);
    if (lane == 0) g_gate[n*3 + w] = 1.0f / (1.0f + fexp(-s));
}
__device__ __forceinline__ void warp_exscan(const int* cnt, int* off, int len){
    int lane = threadIdx.x & 31;
    int run = 0;
    for (int base = 0; base < len; base += 32){
        int raw = (base+lane < len) ? cnt[base+lane] : 0;
        int v = raw;
        #pragma unroll
        for (int o = 1; o < 32; o <<= 1){ int t = __shfl_up_sync(0xffffffffu, v, o); if (lane >= o) v += t; }
        if (base+lane < len) off[base+lane] = run + v - raw;
        run += __shfl_sync(0xffffffffu, v, 31);
    }
    if (lane == 0) off[len] = run;
}
__global__ void scan1_k(){
    int w = threadIdx.x >> 5;
    if (w == 0) warp_exscan(g_cnt, g_boff, MB);
    else if (w == 1) warp_exscan(g_sbcnt, g_sboff, SBN);
    else if (w == 2) warp_exscan(g_wcnt, g_woff, NWID);
    else {
        int lane = threadIdx.x & 31;
        int run = 0;
        for (int base = 0; base < MB; base += 32){
            int valid = g_cnt[base+lane] > 0 ? 1 : 0;
            int v = valid;
            #pragma unroll
            for (int o = 1; o < 32; o <<= 1){ int t = __shfl_up_sync(0xffffffffu, v, o); if (lane >= o) v += t; }
            if (valid) g_vlist[run + v - 1] = base + lane;
            run += __shfl_sync(0xffffffffu, v, 31);
        }
        if (lane == 0) g_nvalid = run;
    }
}
__global__ void scan2_k(){ warp_exscan(g_scount, g_soff, SBN); }

__global__ void permcnt_k(){
    int bt = blockIdx.x, bu = blockIdx.y;
    if (bu > bt) return;
    __shared__ int sp[256];
    int tid = threadIdx.x;
    int t = bt*256 + tid;
    sp[tid] = g_packed[bu*256 + tid];
    __syncthreads();
    int my = g_packed[t];
    int lim = (bu < bt) ? 256 : tid;
    int r1 = 0, r2 = 0, r3 = 0;
    for (int u = 0; u < lim; u++){
        int p = sp[u] ^ my;
        r3 += ((p & 0x00000FFF) == 0);
        r1 += ((p & 0x001FF000) == 0);
        r2 += ((p & 0x7FE00000) == 0);
    }
    if (r1) atomicAdd(&g_r1[t], r1);
    if (r2) atomicAdd(&g_r2[t], r2);
    if (r3) atomicAdd(&g_r3[t], r3);
}
__global__ void permscat_k(){
    int t = blockIdx.x*256 + threadIdx.x;
    if (t >= NTOK) return;
    int my = g_packed[t];
    int bd = my & 0xFFF, sb = (my >> 12) & 0x1FF, wd = (my >> 21) & 0x3FF;
    g_sbperm[g_sboff[sb] + g_r1[t]] = t;
    g_wperm [g_woff[wd]  + g_r2[t]] = t;
    g_bperm [g_boff[bd]  + g_r3[t]] = t;
}
__global__ void scnt_k(){
    int bj = blockIdx.x, bu = blockIdx.y;
    if (bu > bj) return;
    __shared__ int sp[256];
    int tid = threadIdx.x;
    int nv = g_nvalid;
    int ju = bu*256 + tid;
    sp[tid] = (ju < nv) ? g_sidc[ju] : -1;
    __syncthreads();
    int j = bj*256 + tid;
    if (j >= nv) return;
    int my = g_sidc[j];
    int lim = (bu < bj) ? 256 : tid;
    int r = 0;
    for (int u = 0; u < lim; u++) r += (sp[u] == my);
    if (r) atomicAdd(&g_rs[j], r);
}
__global__ void sscat_k(){
    int j = blockIdx.x*256 + threadIdx.x;
    if (j >= g_nvalid) return;
    g_slist[g_soff[g_sidc[j]] + g_rs[j]] = j;
}

__global__ void avg_k(const float* __restrict__ pe){
    int j = blockIdx.x;
    int nv = g_nvalid;
    if (j >= nv){
        __nv_bfloat16 zb = __float2bfloat16(0.f);
        for (int c = threadIdx.x; c < HD; c += 256){
            g_kah[j*HD+c]=zb; g_kal[j*HD+c]=zb; g_vah[j*HD+c]=zb; g_val[j*HD+c]=zb;
        }
        return;
    }
    int m = g_vlist[j];
    int c0 = g_boff[m], c1 = g_boff[m+1];
    float dn = 1.0f / (float)max(c1 - c0, 1);
    for (int c = threadIdx.x; c < HD; c += 256){
        float sk = 0.f, sv = 0.f;
        for (int i = c0; i < c1; i++){
            int t = g_bperm[i];
            sk += g_kf[t*HD + c] + pe[g_pei[t] + c];
            sv += g_vf[t*HD + c];
        }
        sk *= dn; sv *= dn;
        __nv_bfloat16 kh = __float2bfloat16(sk);
        __nv_bfloat16 vh = __float2bfloat16(sv);
        g_kah[j*HD+c] = kh; g_kal[j*HD+c] = __float2bfloat16(sk - __bfloat162float(kh));
        g_vah[j*HD+c] = vh; g_val[j*HD+c] = __float2bfloat16(sv - __bfloat162float(vh));
    }
    if (threadIdx.x == 0){
        int mx = m >> 8, my = (m >> 4) & 15, mz = m & 15;
        g_sidc[j] = ((mx>>1)<<6) | ((my>>1)<<3) | (mz>>1);
        atomicAdd(&g_scount[g_sidc[j]], 1);
    }
}
__global__ void convA_k(const float* __restrict__ in, __nv_bfloat16* __restrict__ h, __nv_bfloat16* __restrict__ l){
    int i = blockIdx.x*256 + threadIdx.x;
    float x = in[i];
    __nv_bfloat16 hb = __float2bfloat16(x);
    h[i] = hb; l[i] = __float2bfloat16(x - __bfloat162float(hb));
}
__global__ void convW_k(const float* W0, const float* W1, const float* W2,
                        const float* W3, const float* W4, const float* W5){
    int z = blockIdx.z;
    const float* W = z==0?W0 : z==1?W1 : z==2?W2 : z==3?W3 : z==4?W4 : W5;
    __nv_bfloat16* h = g_wth + (size_t)z*HD*HD;
    __nv_bfloat16* l = g_wtl + (size_t)z*HD*HD;
    __shared__ float t[32][33];
    int bn = blockIdx.x*32, bk = blockIdx.y*32;
    int tx = threadIdx.x & 31, ty = threadIdx.x >> 5;
    for (int r = ty; r < 32; r += 8) t[r][tx] = W[(size_t)(bk+r)*HD + bn + tx];
    __syncthreads();
    for (int r = ty; r < 32; r += 8){
        float x = t[tx][r];
        __nv_bfloat16 hb = __float2bfloat16(x);
        h[(size_t)(bn+r)*HD + bk + tx] = hb;
        l[(size_t)(bn+r)*HD + bk + tx] = __float2bfloat16(x - __bfloat162float(hb));
    }
}
__global__ void cvt_k(){
    __shared__ float t[32][33];
    int bj = blockIdx.x*32, bd = blockIdx.y*32;
    int tx = threadIdx.x & 31, ty = threadIdx.x >> 5;
    for (int r = ty; r < 32; r += 8) t[r][tx] = g_cv[(size_t)(bj+r)*HD + bd + tx];
    __syncthreads();
    for (int r = ty; r < 32; r += 8){
        int gd = bd + r, h = gd >> 6, dd = gd & 63;
        float x = t[tx][r];
        __nv_bfloat16 hb = __float2bfloat16(x);
        g_cvth[(size_t)(h*DH + dd)*MB + bj + tx] = hb;
        g_cvtl[(size_t)(h*DH + dd)*MB + bj + tx] = __float2bfloat16(x - __bfloat162float(hb));
    }
}

// ---------------- mma.sync stage compute: 8 warps, CTA tile 128x128 ----------------
#define KSTR 24
#define ARR  6144
#define STG  24576

__device__ __forceinline__ void mma_stage(unsigned base, int wm, int wn, int lane, float acc[4][4][4]){
    unsigned ah[4][4], al[4][4], bh[4][2], bl[4][2];
    int t7 = lane & 7, t8 = lane >> 3;
    #pragma unroll
    for (int mt = 0; mt < 4; mt++){
        int m = wm*64 + mt*16 + (t8&1)*8 + t7;
        unsigned off = base + (m*KSTR + (t8>>1)*8)*2;
        ldsm4(ah[mt], off);
        ldsm4(al[mt], off + ARR);
    }
    #pragma unroll
    for (int p = 0; p < 2; p++){
        int n = wn*32 + p*16 + (t8>>1)*8 + t7;
        unsigned off = base + 2*ARR + (n*KSTR + (t8&1)*8)*2;
        unsigned r[4];
        ldsm4(r, off);
        bh[2*p][0]=r[0]; bh[2*p][1]=r[1]; bh[2*p+1][0]=r[2]; bh[2*p+1][1]=r[3];
        ldsm4(r, off + ARR);
        bl[2*p][0]=r[0]; bl[2*p][1]=r[1]; bl[2*p+1][0]=r[2]; bl[2*p+1][1]=r[3];
    }
    #pragma unroll
    for (int mt = 0; mt < 4; mt++)
        #pragma unroll
        for (int nt = 0; nt < 4; nt++){
            mma16816(acc[mt][nt], ah[mt], bh[nt]);
            mma16816(acc[mt][nt], ah[mt], bl[nt]);
            mma16816(acc[mt][nt], al[mt], bh[nt]);
        }
}

// ---------------- GEMM A[·,512] x W^T -> C[128,128] tiles ----------------
__global__ void __launch_bounds__(256) mm_k(
    const __nv_bfloat16* __restrict__ Ah0, const __nv_bfloat16* __restrict__ Al0,
    const __nv_bfloat16* __restrict__ Ah1, const __nv_bfloat16* __restrict__ Al1,
    int wbase, float* C0, float* C1, float* C2,
    __nv_bfloat16* Hh, __nv_bfloat16* Hl, float hscale, int hz0, int guard)
{
    extern __shared__ char smem[];
    int z = blockIdx.z;
    const __nv_bfloat16* Ah = (z==1) ? Ah1 : Ah0;
    const __nv_bfloat16* Al = (z==1) ? Al1 : Al0;
    const __nv_bfloat16* Bh = g_wth + (size_t)(wbase+z)*HD*HD;
    const __nv_bfloat16* Bl = g_wtl + (size_t)(wbase+z)*HD*HD;
    float* C = (z==0) ? C0 : ((z==1) ? C1 : C2);
    int tbm = blockIdx.y*128, tbn = blockIdx.x*128;
    if (guard && tbm >= g_nvalid) return;
    unsigned s0 = smem_u32(smem);
    int tid = threadIdx.x, lane = tid & 31, warp = tid >> 5;
    int wm = warp & 1, wn = warp >> 1;
    int row = tid >> 1, half = tid & 1;
    size_t aoff = (size_t)(tbm+row)*HD + half*8;
    size_t boff = (size_t)(tbn+row)*HD + half*8;
    unsigned sdst = (row*KSTR + half*8)*2;

    float acc[4][4][4];
    #pragma unroll
    for (int i = 0; i < 4; i++)
        #pragma unroll
        for (int j2 = 0; j2 < 4; j2++){ acc[i][j2][0]=0.f; acc[i][j2][1]=0.f; acc[i][j2][2]=0.f; acc[i][j2][3]=0.f; }

    float4 pa = *(const float4*)&Ah[aoff];
    float4 pl = *(const float4*)&Al[aoff];
    float4 pb = *(const float4*)&Bh[boff];
    float4 pq = *(const float4*)&Bl[boff];
    { unsigned b = s0 + sdst; sts128(b, pa); sts128(b+ARR, pl); sts128(b+2*ARR, pb); sts128(b+3*ARR, pq); }
    __syncthreads();
    for (int it = 1; it <= 32; it++){
        if (it < 32){
            pa = *(const float4*)&Ah[aoff + it*16];
            pl = *(const float4*)&Al[aoff + it*16];
            pb = *(const float4*)&Bh[boff + it*16];
            pq = *(const float4*)&Bl[boff + it*16];
        }
        mma_stage(s0 + ((it-1)&1)*STG, wm, wn, lane, acc);
        if (it < 32){
            unsigned b = s0 + (it&1)*STG + sdst;
            sts128(b, pa); sts128(b+ARR, pl); sts128(b+2*ARR, pb); sts128(b+3*ARR, pq);
            __syncthreads();
        }
    }
    #pragma unroll
    for (int mt = 0; mt < 4; mt++){
        int m0 = tbm + wm*64 + mt*16 + (lane>>2);
        #pragma unroll
        for (int nt = 0; nt < 4; nt++){
            int n = tbn + wn*32 + nt*8 + (lane&3)*2;
            float* c = acc[mt][nt];
            size_t i0 = (size_t)m0*HD + n, i1 = (size_t)(m0+8)*HD + n;
            *(float2*)&C[i0] = make_float2(c[0], c[1]);
            *(float2*)&C[i1] = make_float2(c[2], c[3]);
            if (hz0 && z == 0){
                float s0v = c[0]*hscale, s1v = c[1]*hscale, s2v = c[2]*hscale, s3v = c[3]*hscale;
                __nv_bfloat16 h0 = __float2bfloat16(s0v), h1 = __float2bfloat16(s1v);
                __nv_bfloat16 h2 = __float2bfloat16(s2v), h3 = __float2bfloat16(s3v);
                *(__nv_bfloat162*)&Hh[i0] = __nv_bfloat162(h0, h1);
                *(__nv_bfloat162*)&Hh[i1] = __nv_bfloat162(h2, h3);
                *(__nv_bfloat162*)&Hl[i0] = __nv_bfloat162(
                    __float2bfloat16(s0v-__bfloat162float(h0)), __float2bfloat16(s1v-__bfloat162float(h1)));
                *(__nv_bfloat162*)&Hl[i1] = __nv_bfloat162(
                    __float2bfloat16(s2v-__bfloat162float(h2)), __float2bfloat16(s3v-__bfloat162float(h3)));
            }
        }
    }
}

// ---------------- fused flash compressed attention ----------------
// grid (NTOK/128, NH); Q pre-scaled by 0.125. Emits out_c (normalized), invl, rowmax.
#define QPL  18432          // Q plane bytes (128*72*2)
#define KVPL 9216           // K/V plane bytes (64*72*2)
#define KVST 18432          // K or V stage (2 planes)
#define FASM (36864 + 36864 + 36864)

__global__ void __launch_bounds__(256) fa_k(){
    extern __shared__ char smem[];
    unsigned s0 = smem_u32(smem);
    unsigned Kb = s0 + 36864, Vb = s0 + 73728;
    int h = blockIdx.y, nt = blockIdx.x*128;
    int nv = g_nvalid;
    int njt = (nv + 63) >> 6;
    int tid = threadIdx.x, lane = tid & 31, w = tid >> 5;
    int tg = lane & 3, gp = lane >> 2;
    int t7 = lane & 7, t8 = lane >> 3;

    // stage Q (both planes), then load per-warp A fragments once
    #pragma unroll
    for (int q = 0; q < 8; q++){
        int jb = tid + 256*q, pl = jb >> 10, rem = jb & 1023, row = rem >> 3, c8 = rem & 7;
        const __nv_bfloat16* src = pl ? g_ql : g_qh;
        float4 v = *(const float4*)&src[(size_t)(nt+row)*HD + h*DH + c8*8];
        sts128(s0 + pl*QPL + (row*72 + c8*8)*2, v);
    }
    __syncthreads();
    unsigned aqh[4][4], aql[4][4];
    #pragma unroll
    for (int kc = 0; kc < 4; kc++){
        unsigned off = ((w*16 + (t8&1)*8 + t7)*72 + kc*16 + (t8>>1)*8)*2;
        ldsm4(aqh[kc], s0 + off);
        ldsm4(aql[kc], s0 + QPL + off);
    }

    float m0 = -3.0e38f, m1 = -3.0e38f, l0 = 0.f, l1 = 0.f;
    float co[8][4];
    #pragma unroll
    for (int i = 0; i < 8; i++){ co[i][0]=0.f; co[i][1]=0.f; co[i][2]=0.f; co[i][3]=0.f; }

    float4 kr[4], vr[4];
    // prefetch + store tile 0
    #pragma unroll
    for (int q = 0; q < 4; q++){
        int jb = tid + 256*q, pl = jb >> 9, rem = jb & 511, row = rem >> 3, c8 = rem & 7;
        const __nv_bfloat16* ks = pl ? g_ckl : g_ckh;
        kr[q] = *(const float4*)&ks[(size_t)row*HD + h*DH + c8*8];
        const __nv_bfloat16* vs = pl ? g_cvtl : g_cvth;
        vr[q] = *(const float4*)&vs[(size_t)(h*DH+row)*MB + c8*8];
    }
    #pragma unroll
    for (int q = 0; q < 4; q++){
        int jb = tid + 256*q, pl = jb >> 9, rem = jb & 511, row = rem >> 3, c8 = rem & 7;
        unsigned off = pl*KVPL + (row*72 + c8*8)*2;
        sts128(Kb + off, kr[q]);
        sts128(Vb + off, vr[q]);
    }
    __syncthreads();

    for (int t = 0; t < njt; t++){
        if (t+1 < njt){
            int j0 = (t+1)*64;
            #pragma unroll
            for (int q = 0; q < 4; q++){
                int jb = tid + 256*q, pl = jb >> 9, rem = jb & 511, row = rem >> 3, c8 = rem & 7;
                const __nv_bfloat16* ks = pl ? g_ckl : g_ckh;
                kr[q] = *(const float4*)&ks[(size_t)(j0+row)*HD + h*DH + c8*8];
                const __nv_bfloat16* vs = pl ? g_cvtl : g_cvth;
                vr[q] = *(const float4*)&vs[(size_t)(h*DH+row)*MB + j0 + c8*8];
            }
        }
        int st = t & 1;
        // ---- S tile (128 rows x 64 j) ----
        float cs[8][4];
        #pragma unroll
        for (int i = 0; i < 8; i++){ cs[i][0]=0.f; cs[i][1]=0.f; cs[i][2]=0.f; cs[i][3]=0.f; }
        #pragma unroll
        for (int kc = 0; kc < 4; kc++){
            unsigned bh[8][2], bl[8][2];
            #pragma unroll
            for (int p = 0; p < 4; p++){
                unsigned off = Kb + st*KVST + ((p*16 + (t8>>1)*8 + t7)*72 + kc*16 + (t8&1)*8)*2;
                unsigned r[4];
                ldsm4(r, off);
                bh[2*p][0]=r[0]; bh[2*p][1]=r[1]; bh[2*p+1][0]=r[2]; bh[2*p+1][1]=r[3];
                ldsm4(r, off + KVPL);
                bl[2*p][0]=r[0]; bl[2*p][1]=r[1]; bl[2*p+1][0]=r[2]; bl[2*p+1][1]=r[3];
            }
            #pragma unroll
            for (int n8 = 0; n8 < 8; n8++){
                mma16816(cs[n8], aqh[kc], bh[n8]);
                mma16816(cs[n8], aqh[kc], bl[n8]);
                mma16816(cs[n8], aql[kc], bh[n8]);
            }
        }
        // ---- mask + online softmax ----
        int jb0 = t*64 + tg*2;
        float tm0 = -3.0e38f, tm1 = -3.0e38f;
        #pragma unroll
        for (int n8 = 0; n8 < 8; n8++){
            int j = jb0 + n8*8;
            if (j   >= nv){ cs[n8][0] = -3.0e38f; cs[n8][2] = -3.0e38f; }
            if (j+1 >= nv){ cs[n8][1] = -3.0e38f; cs[n8][3] = -3.0e38f; }
            tm0 = fmaxf(tm0, fmaxf(cs[n8][0], cs[n8][1]));
            tm1 = fmaxf(tm1, fmaxf(cs[n8][2], cs[n8][3]));
        }
        tm0 = fmaxf(tm0, __shfl_xor_sync(0xffffffffu, tm0, 1));
        tm0 = fmaxf(tm0, __shfl_xor_sync(0xffffffffu, tm0, 2));
        tm1 = fmaxf(tm1, __shfl_xor_sync(0xffffffffu, tm1, 1));
        tm1 = fmaxf(tm1, __shfl_xor_sync(0xffffffffu, tm1, 2));
        float nm0 = fmaxf(m0, tm0), nm1 = fmaxf(m1, tm1);
        float f0 = fexp(m0 - nm0), f1 = fexp(m1 - nm1);
        m0 = nm0; m1 = nm1;
        l0 *= f0; l1 *= f1;
        #pragma unroll
        for (int d8 = 0; d8 < 8; d8++){
            co[d8][0] *= f0; co[d8][1] *= f0; co[d8][2] *= f1; co[d8][3] *= f1;
        }
        // ---- e + pack P A-fragments (hi/lo) ----
        unsigned pah[4][4], pal[4][4];
        #pragma unroll
        for (int kc = 0; kc < 4; kc++){
            float e00 = fexp(cs[2*kc][0] - m0),   e01 = fexp(cs[2*kc][1] - m0);
            float e02 = fexp(cs[2*kc][2] - m1),   e03 = fexp(cs[2*kc][3] - m1);
            float e10 = fexp(cs[2*kc+1][0] - m0), e11 = fexp(cs[2*kc+1][1] - m0);
            float e12 = fexp(cs[2*kc+1][2] - m1), e13 = fexp(cs[2*kc+1][3] - m1);
            l0 += e00 + e01 + e10 + e11;
            l1 += e02 + e03 + e12 + e13;
            __nv_bfloat16 h00=__float2bfloat16(e00), h01=__float2bfloat16(e01);
            __nv_bfloat16 h02=__float2bfloat16(e02), h03=__float2bfloat16(e03);
            __nv_bfloat16 h10=__float2bfloat16(e10), h11=__float2bfloat16(e11);
            __nv_bfloat16 h12=__float2bfloat16(e12), h13=__float2bfloat16(e13);
            pah[kc][0] = pack2(h00, h01);
            pah[kc][1] = pack2(h02, h03);
            pah[kc][2] = pack2(h10, h11);
            pah[kc][3] = pack2(h12, h13);
            pal[kc][0] = pack2(__float2bfloat16(e00-__bfloat162float(h00)), __float2bfloat16(e01-__bfloat162float(h01)));
            pal[kc][1] = pack2(__float2bfloat16(e02-__bfloat162float(h02)), __float2bfloat16(e03-__bfloat162float(h03)));
            pal[kc][2] = pack2(__float2bfloat16(e10-__bfloat162float(h10)), __float2bfloat16(e11-__bfloat162float(h11)));
            pal[kc][3] = pack2(__float2bfloat16(e12-__bfloat162float(h12)), __float2bfloat16(e13-__bfloat162float(h13)));
        }
        // ---- P @ V ----
        #pragma unroll
        for (int kc = 0; kc < 4; kc++){
            unsigned bh[8][2], bl[8][2];
            #pragma unroll
            for (int p = 0; p < 4; p++){
                unsigned off = Vb + st*KVST + ((p*16 + (t8>>1)*8 + t7)*72 + kc*16 + (t8&1)*8)*2;
                unsigned r[4];
                ldsm4(r, off);
                bh[2*p][0]=r[0]; bh[2*p][1]=r[1]; bh[2*p+1][0]=r[2]; bh[2*p+1][1]=r[3];
                ldsm4(r, off + KVPL);
                bl[2*p][0]=r[0]; bl[2*p][1]=r[1]; bl[2*p+1][0]=r[2]; bl[2*p+1][1]=r[3];
            }
            #pragma unroll
            for (int d8 = 0; d8 < 8; d8++){
                mma16816(co[d8], pah[kc], bh[d8]);
                mma16816(co[d8], pah[kc], bl[d8]);
                mma16816(co[d8], pal[kc], bh[d8]);
            }
        }
        if (t+1 < njt){
            int nst = (t+1) & 1;
            #pragma unroll
            for (int q = 0; q < 4; q++){
                int jb = tid + 256*q, pl = jb >> 9, rem = jb & 511, row = rem >> 3, c8 = rem & 7;
                unsigned off = pl*KVPL + (row*72 + c8*8)*2;
                sts128(Kb + nst*KVST + off, kr[q]);
                sts128(Vb + nst*KVST + off, vr[q]);
            }
            __syncthreads();
        }
    }
    // ---- finalize ----
    l0 += __shfl_xor_sync(0xffffffffu, l0, 1);
    l0 += __shfl_xor_sync(0xffffffffu, l0, 2);
    l1 += __shfl_xor_sync(0xffffffffu, l1, 1);
    l1 += __shfl_xor_sync(0xffffffffu, l1, 2);
    float iv0 = 1.0f / l0, iv1 = 1.0f / l1;
    int row0 = nt + w*16 + gp;
    if (tg == 0){
        g_invl[h*NTOK + row0]     = iv0;
        g_invl[h*NTOK + row0 + 8] = iv1;
        g_rowm[h*NTOK + row0]     = m0;
        g_rowm[h*NTOK + row0 + 8] = m1;
    }
    #pragma unroll
    for (int d8 = 0; d8 < 8; d8++){
        int col = h*DH + d8*8 + tg*2;
        *(float2*)&g_outc[(size_t)row0*HD + col]     = make_float2(co[d8][0]*iv0, co[d8][1]*iv0);
        *(float2*)&g_outc[(size_t)(row0+8)*HD + col] = make_float2(co[d8][2]*iv1, co[d8][3]*iv1);
    }
}

// ---------------- P8: recompute S per head, sum exp(s-m)*invl over heads ----------------
#define P8SM (36864 + 36864)   // Q planes + K planes (128 rows x 72 stride)

__global__ void __launch_bounds__(256) p8_k(){
    extern __shared__ char smem[];
    unsigned s0 = smem_u32(smem);
    unsigned Kb = s0 + 36864;
    int ntb = blockIdx.x*128, jt = blockIdx.y*128;
    int nv = g_nvalid;
    if (jt >= nv) return;
    int tid = threadIdx.x, lane = tid & 31, w = tid >> 5;
    int tg = lane & 3, gp = lane >> 2;
    int t7 = lane & 7, t8 = lane >> 3;
    int row0 = ntb + w*16 + gp;

    float acc[16][4];
    #pragma unroll
    for (int i = 0; i < 16; i++){ acc[i][0]=0.f; acc[i][1]=0.f; acc[i][2]=0.f; acc[i][3]=0.f; }

    for (int h = 0; h < NH; h++){
        float4 qr[8], kr[8];
        #pragma unroll
        for (int q = 0; q < 8; q++){
            int jb = tid + 256*q, pl = jb >> 10, rem = jb & 1023, row = rem >> 3, c8 = rem & 7;
            const __nv_bfloat16* qs = pl ? g_ql  : g_qh;
            qr[q] = *(const float4*)&qs[(size_t)(ntb+row)*HD + h*DH + c8*8];
            const __nv_bfloat16* ks = pl ? g_ckl : g_ckh;
            kr[q] = *(const float4*)&ks[(size_t)(jt+row)*HD + h*DH + c8*8];
        }
        __syncthreads();
        #pragma unroll
        for (int q = 0; q < 8; q++){
            int jb = tid + 256*q, pl = jb >> 10, rem = jb & 1023, row = rem >> 3, c8 = rem & 7;
            unsigned off = (row*72 + c8*8)*2;
            sts128(s0 + pl*QPL + off, qr[q]);
            sts128(Kb + pl*QPL + off, kr[q]);
        }
        __syncthreads();
        unsigned aqh[4][4], aql[4][4];
        #pragma unroll
        for (int kc = 0; kc < 4; kc++){
            unsigned off = ((w*16 + (t8&1)*8 + t7)*72 + kc*16 + (t8>>1)*8)*2;
            ldsm4(aqh[kc], s0 + off);
            ldsm4(aql[kc], s0 + QPL + off);
        }
        float cs[16][4];
        #pragma unroll
        for (int i = 0; i < 16; i++){ cs[i][0]=0.f; cs[i][1]=0.f; cs[i][2]=0.f; cs[i][3]=0.f; }
        #pragma unroll
        for (int kc = 0; kc < 4; kc++){
            unsigned bh[16][2], bl[16][2];
            #pragma unroll
            for (int p = 0; p < 8; p++){
                unsigned off = Kb + ((p*16 + (t8>>1)*8 + t7)*72 + kc*16 + (t8&1)*8)*2;
                unsigned r[4];
                ldsm4(r, off);
                bh[2*p][0]=r[0]; bh[2*p][1]=r[1]; bh[2*p+1][0]=r[2]; bh[2*p+1][1]=r[3];
                ldsm4(r, off + QPL);
                bl[2*p][0]=r[0]; bl[2*p][1]=r[1]; bl[2*p+1][0]=r[2]; bl[2*p+1][1]=r[3];
            }
            #pragma unroll
            for (int n8 = 0; n8 < 16; n8++){
                mma16816(cs[n8], aqh[kc], bh[n8]);
                mma16816(cs[n8], aqh[kc], bl[n8]);
                mma16816(cs[n8], aql[kc], bh[n8]);
            }
        }
        float m0 = g_rowm[h*NTOK + row0],     iv0 = g_invl[h*NTOK + row0];
        float m1 = g_rowm[h*NTOK + row0 + 8], iv1 = g_invl[h*NTOK + row0 + 8];
        #pragma unroll
        for (int n8 = 0; n8 < 16; n8++){
            int j = jt + n8*8 + tg*2;
            if (j < nv){
                acc[n8][0] += fexp(cs[n8][0] - m0) * iv0;
                acc[n8][2] += fexp(cs[n8][2] - m1) * iv1;
            }
            if (j+1 < nv){
                acc[n8][1] += fexp(cs[n8][1] - m0) * iv0;
                acc[n8][3] += fexp(cs[n8][3] - m1) * iv1;
            }
        }
    }
    #pragma unroll
    for (int n8 = 0; n8 < 16; n8++){
        int j = jt + n8*8 + tg*2;
        *(float2*)&g_P8[(size_t)row0*MB + j]     = make_float2(acc[n8][0], acc[n8][1]);
        *(float2*)&g_P8[(size_t)(row0+8)*MB + j] = make_float2(acc[n8][2], acc[n8][3]);
    }
}

// ---------------- sel_score + top-8 ----------------
__global__ void topk_k(){
    int n = blockIdx.x, tid = threadIdx.x;
    int lane = tid & 31, w = tid >> 5;
    __shared__ float ss[SBN];
    __shared__ float wv[16];
    __shared__ int   wi[16];
    float v = 0.f;
    int o0 = g_soff[tid], o1 = g_soff[tid+1];
    for (int i = o0; i < o1; i++) v += g_P8[(size_t)n*MB + g_slist[i]];
    ss[tid] = v;
    __syncthreads();
    for (int r = 0; r < 8; r++){
        float mv = ss[tid]; int mi = tid;
        #pragma unroll
        for (int o = 16; o; o >>= 1){
            float ov = __shfl_xor_sync(0xffffffffu, mv, o);
            int   oi = __shfl_xor_sync(0xffffffffu, mi, o);
            if (ov > mv || (ov == mv && oi < mi)){ mv = ov; mi = oi; }
        }
        if (lane == 0){ wv[w] = mv; wi[w] = mi; }
        __syncthreads();
        if (tid < 16){
            float m2 = wv[tid]; int i2 = wi[tid];
            #pragma unroll
            for (int o = 8; o; o >>= 1){
                float ov = __shfl_xor_sync(0x0000ffffu, m2, o);
                int   oi = __shfl_xor_sync(0x0000ffffu, i2, o);
                if (ov > m2 || (ov == m2 && oi < i2)){ m2 = ov; i2 = oi; }
            }
            if (tid == 0){ g_top8[n*8 + r] = i2; ss[i2] = -1e30f; }
        }
        __syncthreads();
    }
}

// ---------------- selection / window attention ----------------
__global__ void spattn_k(){
    int n = blockIdx.x, mode = blockIdx.y;
    int h = threadIdx.x >> 5, lane = threadIdx.x & 31;
    const float* qr = &g_q[n*HD + h*DH];
    float q0 = qr[lane], q1 = qr[lane + 32];
    float m = -1e30f, l = 0.f, a0 = 0.f, a1 = 0.f;
    int nb = (mode == 0) ? 8 : 1;
    for (int kk = 0; kk < nb; kk++){
        int b, o, e;
        if (mode == 0){ b = g_top8[n*8 + kk]; o = g_sboff[b]; e = g_sboff[b+1]; }
        else          { b = g_wid[n];         o = g_woff[b];  e = g_woff[b+1]; }
        for (int i = o; i < e; i++){
            int t = (mode == 0) ? g_sbperm[i] : g_wperm[i];
            const float* kr = &g_kf[t*HD + h*DH];
            float s = q0*kr[lane] + q1*kr[lane + 32];
            #pragma unroll
            for (int of = 16; of; of >>= 1) s += __shfl_xor_sync(0xffffffffu, s, of);
            s *= 0.125f;
            float mn = fmaxf(m, s);
            float c = fexp(m - mn), ww = fexp(s - mn);
            const float* vr = &g_vf[t*HD + h*DH];
            l  = l*c  + ww;
            a0 = a0*c + ww*vr[lane];
            a1 = a1*c + ww*vr[lane + 32];
            m = mn;
        }
    }
    float* outp = mode ? g_outw : g_outs;
    outp[n*HD + h*DH + lane]      = a0 / l;
    outp[n*HD + h*DH + lane + 32] = a1 / l;
}

// ---------------- gated fuse -> split bf16 (input to Wo GEMM) ----------------
__global__ void fuse_k(){
    int i = blockIdx.x*256 + threadIdx.x;
    int n = i >> 9;
    float g0 = g_gate[n*3+0], g1 = g_gate[n*3+1], g2 = g_gate[n*3+2];
    float v = g0*g_outc[i] + g1*g_outs[i] + g2*g_outw[i];
    __nv_bfloat16 hb = __float2bfloat16(v);
    g_fh[i] = hb;
    g_fl[i] = __float2bfloat16(v - __bfloat162float(hb));
}

// ---------------- launch ----------------
extern "C" void kernel_launch(void* const* d_in, const int* in_sizes, int n_in,
                              void* d_out, int out_size){
    const float* feats  = (const float*)d_in[0];
    const int*   coords = (const int*)  d_in[1];
    const float* Wq  = (const float*)d_in[2];
    const float* Wk  = (const float*)d_in[3];
    const float* Wv  = (const float*)d_in[4];
    const float* Wo  = (const float*)d_in[5];
    const float* Wck = (const float*)d_in[6];
    const float* Wcv = (const float*)d_in[7];
    const float* pe  = (const float*)d_in[8];
    const float* Wg  = (const float*)d_in[9];
    float* out = (float*)d_out;

    float *gq, *gkf, *gvf, *gck, *gcv;
    __nv_bfloat16 *fh, *fl, *qh, *ql, *kah, *kal, *vah, *val, *ckh, *ckl;
    cudaGetSymbolAddress((void**)&gq,  g_q);
    cudaGetSymbolAddress((void**)&gkf, g_kf);
    cudaGetSymbolAddress((void**)&gvf, g_vf);
    cudaGetSymbolAddress((void**)&gck, g_ck);
    cudaGetSymbolAddress((void**)&gcv, g_cv);
    cudaGetSymbolAddress((void**)&fh,  g_fh);
    cudaGetSymbolAddress((void**)&fl,  g_fl);
    cudaGetSymbolAddress((void**)&qh,  g_qh);
    cudaGetSymbolAddress((void**)&ql,  g_ql);
    cudaGetSymbolAddress((void**)&kah, g_kah);
    cudaGetSymbolAddress((void**)&kal, g_kal);
    cudaGetSymbolAddress((void**)&vah, g_vah);
    cudaGetSymbolAddress((void**)&val, g_val);
    cudaGetSymbolAddress((void**)&ckh, g_ckh);
    cudaGetSymbolAddress((void**)&ckl, g_ckl);

    cudaFuncSetAttribute(mm_k, cudaFuncAttributeMaxDynamicSharedMemorySize, 2*STG);
    cudaFuncSetAttribute(fa_k, cudaFuncAttributeMaxDynamicSharedMemorySize, FASM);
    cudaFuncSetAttribute(p8_k, cudaFuncAttributeMaxDynamicSharedMemorySize, P8SM);

    zero_k<<<64, 256>>>();
    prep_k<<<8, 256>>>(coords);
    gate_k<<<NTOK, 128>>>(feats, Wg);
    convW_k<<<dim3(16, 16, 6), 256>>>(Wq, Wk, Wv, Wck, Wcv, Wo);
    convA_k<<<NTOK*HD/256, 256>>>(feats, fh, fl);

    // QKV projection: qh/ql emitted pre-scaled by 1/8
    mm_k<<<dim3(4, NTOK/128, 3), 256, 2*STG>>>(fh, fl, fh, fl, 0, gq, gkf, gvf, qh, ql, 0.125f, 1, 0);

    scan1_k<<<1, 128>>>();
    permcnt_k<<<dim3(8, 8), 256>>>();
    permscat_k<<<8, 256>>>();
    avg_k<<<MB, 256>>>(pe);

    mm_k<<<dim3(4, MB/128, 2), 256, 2*STG>>>(kah, kal, vah, val, 3, gck, gcv, gcv, ckh, ckl, 1.0f, 1, 1);
    cvt_k<<<dim3(MB/32, HD/32), 256>>>();

    scan2_k<<<1, 32>>>();
    scnt_k<<<dim3(8, 8), 256>>>();
    sscat_k<<<8, 256>>>();

    fa_k<<<dim3(NTOK/128, NH), 256, FASM>>>();
    p8_k<<<dim3(NTOK/128, 13), 256, P8SM>>>();
    topk_k<<<NTOK, 512>>>();
    spattn_k<<<dim3(NTOK, 2), 256>>>();
    fuse_k<<<NTOK*HD/256, 256>>>();

    mm_k<<<dim3(4, NTOK/128, 1), 256, 2*STG>>>(fh, fl, fh, fl, 5, out, out, out, qh, ql, 1.0f, 0, 0);
}